// round 2
// baseline (speedup 1.0000x reference)
#include <cuda_runtime.h>
#include <math.h>

#define B_  2048
#define L_  200
#define C_  100
#define V_  2000

// ---------------- scratch ----------------
__device__ float g_IG[B_*5*384];
__device__ float g_HG[B_*384];
__device__ float g_H [B_*128];
__device__ float g_CT[B_*128];
__device__ float g_CI[B_*128];
__device__ float g_AL[B_*3];
__device__ float g_WT[128*128];   // Wt1 mid slab, k-major [k][j]
__device__ float g_WI[64*128];    // Wi1 mid slab, k-major [k][j]
__device__ int   g_LI[B_];

__device__ __forceinline__ float sigf(float x){ return 1.0f/(1.0f+expf(-x)); }
__device__ __forceinline__ float wsum(float v){
#pragma unroll
  for (int o=16;o;o>>=1) v += __shfl_xor_sync(0xffffffffu, v, o);
  return v;
}
__device__ __forceinline__ float wmax(float v){
#pragma unroll
  for (int o=16;o;o>>=1) v = fmaxf(v, __shfl_xor_sync(0xffffffffu, v, o));
  return v;
}

__global__ void k_init(){
  int i = blockIdx.x*blockDim.x + threadIdx.x;
  if (i < B_*128) g_H[i] = 0.f;
}

// 64x64-tile SGEMM: C[m][n] = A[m][:]·Wrow[n][:] + bias[n]
// gather=1: A row gathered from embeddings (K=192, out->g_IG)
// gather=0: A = g_H (K=128, out->g_HG)
__global__ __launch_bounds__(256) void k_gemm(
    const float* __restrict__ Bw, const float* __restrict__ bias,
    int M, int K, int gather,
    const float* __restrict__ ide, const float* __restrict__ txe,
    const int* __restrict__ lens)
{
  __shared__ float As[16][64];
  __shared__ float Bs[16][64];
  const int tid = threadIdx.x;
  const int m0 = blockIdx.x*64, n0 = blockIdx.y*64;
  const int lm = tid & 63, lk4 = (tid >> 6) * 4;
  const int row0 = (tid & 15)*4, col0 = (tid >> 4)*4;
  const float *arow, *arow2 = 0;
  if (gather){
    int m = m0 + lm; int b = m/5, t = m - 5*b;
    int pos = lens[b] - 5 + t;
    arow  = ide + ((long)b*L_ + pos)*64;
    arow2 = txe + ((long)b*L_ + pos)*128;
  } else {
    arow = g_H + (long)(m0 + lm)*K;
  }
  const float* brow = Bw + (long)(n0 + lm)*K;
  float acc[4][4];
#pragma unroll
  for (int i=0;i<4;i++)
#pragma unroll
    for (int j=0;j<4;j++) acc[i][j]=0.f;

  for (int k0=0;k0<K;k0+=16){
    int kk = k0 + lk4;
    float4 a4;
    if (gather) a4 = (kk < 64) ? *(const float4*)(arow+kk) : *(const float4*)(arow2+kk-64);
    else        a4 = *(const float4*)(arow+kk);
    float4 b4 = *(const float4*)(brow+kk);
    As[lk4+0][lm]=a4.x; As[lk4+1][lm]=a4.y; As[lk4+2][lm]=a4.z; As[lk4+3][lm]=a4.w;
    Bs[lk4+0][lm]=b4.x; Bs[lk4+1][lm]=b4.y; Bs[lk4+2][lm]=b4.z; Bs[lk4+3][lm]=b4.w;
    __syncthreads();
#pragma unroll
    for (int k=0;k<16;k++){
      float4 av = *(const float4*)&As[k][row0];
      float4 bv = *(const float4*)&Bs[k][col0];
      acc[0][0]=fmaf(av.x,bv.x,acc[0][0]); acc[0][1]=fmaf(av.x,bv.y,acc[0][1]);
      acc[0][2]=fmaf(av.x,bv.z,acc[0][2]); acc[0][3]=fmaf(av.x,bv.w,acc[0][3]);
      acc[1][0]=fmaf(av.y,bv.x,acc[1][0]); acc[1][1]=fmaf(av.y,bv.y,acc[1][1]);
      acc[1][2]=fmaf(av.y,bv.z,acc[1][2]); acc[1][3]=fmaf(av.y,bv.w,acc[1][3]);
      acc[2][0]=fmaf(av.z,bv.x,acc[2][0]); acc[2][1]=fmaf(av.z,bv.y,acc[2][1]);
      acc[2][2]=fmaf(av.z,bv.z,acc[2][2]); acc[2][3]=fmaf(av.z,bv.w,acc[2][3]);
      acc[3][0]=fmaf(av.w,bv.x,acc[3][0]); acc[3][1]=fmaf(av.w,bv.y,acc[3][1]);
      acc[3][2]=fmaf(av.w,bv.z,acc[3][2]); acc[3][3]=fmaf(av.w,bv.w,acc[3][3]);
    }
    __syncthreads();
  }
  float* outp = gather ? g_IG : g_HG;
#pragma unroll
  for (int i=0;i<4;i++){
    float* crow = outp + (long)(m0+row0+i)*384 + n0 + col0;
#pragma unroll
    for (int j=0;j<4;j++) crow[j] = acc[i][j] + bias[n0+col0+j];
  }
}

__global__ void k_gru(int t){
  int idx = blockIdx.x*blockDim.x + threadIdx.x;
  if (idx >= B_*128) return;
  int b = idx >> 7, j = idx & 127;
  const float* ig = g_IG + ((long)b*5 + t)*384;
  const float* hg = g_HG + (long)b*384;
  float r = sigf(ig[j]     + hg[j]);
  float z = sigf(ig[128+j] + hg[128+j]);
  float n = tanhf(ig[256+j] + r*hg[256+j]);
  float h = g_H[idx];
  g_H[idx] = (1.f - z)*n + z*h;
}

__global__ void k_wprep(const float* __restrict__ Wt1, const float* __restrict__ Wi1){
  int idx = blockIdx.x*blockDim.x + threadIdx.x;
  if (idx < 16384){
    int k = idx >> 7, j = idx & 127;
    g_WT[idx] = Wt1[(long)j*384 + 128 + k];
  } else if (idx < 16384 + 8192){
    int i2 = idx - 16384;
    int k = i2 >> 7, j = i2 & 127;
    g_WI[i2] = Wi1[(long)j*256 + 64 + k];
  }
}

// per-batch constants: ct, ci, alpha, last item; 16 batches per block, 128 thr
__global__ __launch_bounds__(128) void k_prep(
    const float* __restrict__ ide, const float* __restrict__ txe,
    const int* __restrict__ lens, const int* __restrict__ sitems,
    const float* __restrict__ Wt1, const float* __restrict__ bt1,
    const float* __restrict__ Wi1, const float* __restrict__ bi1,
    const float* __restrict__ Wa1, const float* __restrict__ ba1,
    const float* __restrict__ Wa2, const float* __restrict__ ba2)
{
  __shared__ float lt[16][128], hh[16][128], lid[16][64], a1s[16][64], lg[16][3];
  __shared__ int Ls[16];
  const int tid = threadIdx.x;
  const int b0 = blockIdx.x * 16;
  if (tid < 16) Ls[tid] = lens[b0+tid];
  __syncthreads();
  for (int i=tid;i<2048;i+=128){
    int bb=i>>7, k=i&127; int pos = Ls[bb]-1;
    lt[bb][k] = txe[((long)(b0+bb)*L_ + pos)*128 + k];
    hh[bb][k] = g_H[(b0+bb)*128 + k];
  }
  for (int i=tid;i<1024;i+=128){
    int bb=i>>6, k=i&63;
    lid[bb][k] = ide[((long)(b0+bb)*L_ + Ls[bb]-1)*64 + k];
  }
  if (tid < 16) g_LI[b0+tid] = sitems[(long)(b0+tid)*L_ + Ls[tid]-1];
  __syncthreads();

  const int j = tid;
  { // ct
    float acc[16];
#pragma unroll
    for (int bb=0;bb<16;bb++) acc[bb] = bt1[j];
    const float* w1 = Wt1 + (long)j*384;
    const float* w3 = w1 + 256;
    for (int k=0;k<128;k++){
      float ws = w1[k], wh = w3[k];
#pragma unroll
      for (int bb=0;bb<16;bb++) acc[bb] += ws*lt[bb][k] + wh*hh[bb][k];
    }
#pragma unroll
    for (int bb=0;bb<16;bb++) g_CT[(b0+bb)*128 + j] = acc[bb];
  }
  { // ci
    float acc[16];
#pragma unroll
    for (int bb=0;bb<16;bb++) acc[bb] = bi1[j];
    const float* w1 = Wi1 + (long)j*256;
    const float* w3 = w1 + 128;
    for (int k=0;k<64;k++){
      float ws = w1[k];
#pragma unroll
      for (int bb=0;bb<16;bb++) acc[bb] += ws*lid[bb][k];
    }
    for (int k=0;k<128;k++){
      float wh = w3[k];
#pragma unroll
      for (int bb=0;bb<16;bb++) acc[bb] += wh*hh[bb][k];
    }
#pragma unroll
    for (int bb=0;bb<16;bb++) g_CI[(b0+bb)*128 + j] = acc[bb];
  }
  if (tid < 64){ // alpha hidden
    const int u = tid;
    float acc[16];
#pragma unroll
    for (int bb=0;bb<16;bb++) acc[bb] = ba1[u];
    const float* w = Wa1 + (long)u*128;
    for (int k=0;k<128;k++){
      float wv = w[k];
#pragma unroll
      for (int bb=0;bb<16;bb++) acc[bb] += wv*hh[bb][k];
    }
#pragma unroll
    for (int bb=0;bb<16;bb++) a1s[bb][u] = fmaxf(acc[bb], 0.f);
  }
  __syncthreads();
  if (tid < 48){
    int bb = tid/3, g = tid%3;
    float s = ba2[g];
    const float* w = Wa2 + g*64;
    for (int u=0;u<64;u++) s += w[u]*a1s[bb][u];
    lg[bb][g] = s;
  }
  __syncthreads();
  if (tid < 16){
    float l0=lg[tid][0], l1=lg[tid][1], l2=lg[tid][2];
    float m = fmaxf(l0, fmaxf(l1,l2));
    float e0=expf(l0-m), e1=expf(l1-m), e2=expf(l2-m);
    float inv = 1.f/(e0+e1+e2);
    g_AL[(b0+tid)*3+0]=e0*inv; g_AL[(b0+tid)*3+1]=e1*inv; g_AL[(b0+tid)*3+2]=e2*inv;
  }
}

// fused scorer+softmax+mix: one block per batch, 256 threads, 96KB dyn smem
__global__ __launch_bounds__(256) void k_score(
    const float* __restrict__ ctxe, const float* __restrict__ cide,
    const int* __restrict__ cids, const float* __restrict__ co,
    const float* __restrict__ Wt2, const float* __restrict__ bt2,
    const float* __restrict__ Wi2, const float* __restrict__ bi2,
    const float* __restrict__ betac, const float* __restrict__ lTc,
    const float* __restrict__ lTt, const float* __restrict__ lTi,
    float* __restrict__ out)
{
  extern __shared__ float dyn[];
  float* sW = dyn;            // 16384 floats
  float* sE = dyn + 16384;    // 8192 floats
  __shared__ float ctv[128], civ[128], w2t[128], w2i[128];
  __shared__ float sco[3][128];
  __shared__ float mx3[3], inv3[3], sS;
  __shared__ float mixv[128];
  const int b = blockIdx.x, tid = threadIdx.x;
  const int warp = tid>>5, lane = tid&31;
  if (tid < 128){
    ctv[tid]=g_CT[b*128+tid]; civ[tid]=g_CI[b*128+tid];
    w2t[tid]=Wt2[tid];        w2i[tid]=Wi2[tid];
  }
  for (int i=tid;i<16384;i+=256) sW[i] = g_WT[i];
  if (tid < 100){
    long li = g_LI[b];
    sco[0][tid] = co[li*V_ + cids[(long)b*C_+tid]] * betac[0] / expf(lTc[0]);
  }
  const float Tt = expf(lTt[0]), Ti = expf(lTi[0]);
  __syncthreads();

  // text pass: D=128, 2 chunks of 64 candidates
  for (int ch=0; ch<2; ch++){
    for (int i=tid;i<8192;i+=256){
      int ci=i>>7, k=i&127; int c=ch*64+ci;
      sE[i] = (c < C_) ? ctxe[((long)b*C_+c)*128 + k] : 0.f;
    }
    __syncthreads();
    float acc[4][8];
#pragma unroll
    for (int i=0;i<4;i++)
#pragma unroll
      for (int q=0;q<8;q++) acc[i][q]=0.f;
    for (int k=0;k<128;k++){
      float4 w4 = *(const float4*)&sW[k*128 + lane*4];
      const float* ep = &sE[(warp*8)*128 + k];
#pragma unroll
      for (int q=0;q<8;q++){
        float e = ep[q*128];
        acc[0][q]=fmaf(w4.x,e,acc[0][q]); acc[1][q]=fmaf(w4.y,e,acc[1][q]);
        acc[2][q]=fmaf(w4.z,e,acc[2][q]); acc[3][q]=fmaf(w4.w,e,acc[3][q]);
      }
    }
#pragma unroll
    for (int q=0;q<8;q++){
      int c = ch*64 + warp*8 + q;
      float v = w2t[lane*4+0]*fmaxf(ctv[lane*4+0]+acc[0][q],0.f)
              + w2t[lane*4+1]*fmaxf(ctv[lane*4+1]+acc[1][q],0.f)
              + w2t[lane*4+2]*fmaxf(ctv[lane*4+2]+acc[2][q],0.f)
              + w2t[lane*4+3]*fmaxf(ctv[lane*4+3]+acc[3][q],0.f);
      v = wsum(v);
      if (lane==0 && c < C_) sco[1][c] = (v + bt2[0]) / Tt;
    }
    __syncthreads();
  }

  // id pass: D=64
  for (int i=tid;i<8192;i+=256) sW[i] = g_WI[i];
  for (int ch=0; ch<2; ch++){
    for (int i=tid;i<4096;i+=256){
      int ci=i>>6, k=i&63; int c=ch*64+ci;
      sE[i] = (c < C_) ? cide[((long)b*C_+c)*64 + k] : 0.f;
    }
    __syncthreads();
    float acc[4][8];
#pragma unroll
    for (int i=0;i<4;i++)
#pragma unroll
      for (int q=0;q<8;q++) acc[i][q]=0.f;
    for (int k=0;k<64;k++){
      float4 w4 = *(const float4*)&sW[k*128 + lane*4];
      const float* ep = &sE[(warp*8)*64 + k];
#pragma unroll
      for (int q=0;q<8;q++){
        float e = ep[q*64];
        acc[0][q]=fmaf(w4.x,e,acc[0][q]); acc[1][q]=fmaf(w4.y,e,acc[1][q]);
        acc[2][q]=fmaf(w4.z,e,acc[2][q]); acc[3][q]=fmaf(w4.w,e,acc[3][q]);
      }
    }
#pragma unroll
    for (int q=0;q<8;q++){
      int c = ch*64 + warp*8 + q;
      float v = w2i[lane*4+0]*fmaxf(civ[lane*4+0]+acc[0][q],0.f)
              + w2i[lane*4+1]*fmaxf(civ[lane*4+1]+acc[1][q],0.f)
              + w2i[lane*4+2]*fmaxf(civ[lane*4+2]+acc[2][q],0.f)
              + w2i[lane*4+3]*fmaxf(civ[lane*4+3]+acc[3][q],0.f);
      v = wsum(v);
      if (lane==0 && c < C_) sco[2][c] = (v + bi2[0]) / Ti;
    }
    __syncthreads();
  }

  // softmaxes
  if (warp == 0){
#pragma unroll
    for (int chn=0;chn<3;chn++){
      float m = -1e30f;
      for (int q=lane;q<C_;q+=32) m = fmaxf(m, sco[chn][q]);
      m = wmax(m);
      float s = 0.f;
      for (int q=lane;q<C_;q+=32) s += expf(sco[chn][q]-m);
      s = wsum(s);
      if (lane==0){ mx3[chn]=m; inv3[chn]=1.f/s; }
    }
  }
  __syncthreads();
  const float a0=g_AL[b*3], a1=g_AL[b*3+1], a2=g_AL[b*3+2];
  if (tid < C_){
    float p = 0.01f
      + a0*expf(sco[0][tid]-mx3[0])*inv3[0]
      + a1*expf(sco[1][tid]-mx3[1])*inv3[1]
      + a2*expf(sco[2][tid]-mx3[2])*inv3[2];
    mixv[tid] = p;
  }
  __syncthreads();
  if (warp == 0){
    float s = 0.f;
    for (int q=lane;q<C_;q+=32) s += mixv[q];
    s = wsum(s);
    if (lane==0) sS = 1.f/s;
  }
  __syncthreads();
  if (tid < C_) out[(long)b*C_ + tid] = mixv[tid]*sS;
}

extern "C" void kernel_launch(void* const* d_in, const int* in_sizes, int n_in,
                              void* d_out, int out_size) {
  const int*   sitems = (const int*)  d_in[0];
  const float* ide    = (const float*)d_in[1];
  const float* txe    = (const float*)d_in[2];
  const int*   lens   = (const int*)  d_in[3];
  const int*   cids   = (const int*)  d_in[4];
  const float* cide   = (const float*)d_in[5];
  const float* ctxe   = (const float*)d_in[6];
  const float* co     = (const float*)d_in[7];
  const float* Wih    = (const float*)d_in[8];
  const float* Whh    = (const float*)d_in[9];
  const float* bih    = (const float*)d_in[10];
  const float* bhh    = (const float*)d_in[11];
  const float* Wt1    = (const float*)d_in[12];
  const float* bt1    = (const float*)d_in[13];
  const float* Wt2    = (const float*)d_in[14];
  const float* bt2    = (const float*)d_in[15];
  const float* Wi1    = (const float*)d_in[16];
  const float* bi1    = (const float*)d_in[17];
  const float* Wi2    = (const float*)d_in[18];
  const float* bi2    = (const float*)d_in[19];
  const float* Wa1    = (const float*)d_in[20];
  const float* ba1    = (const float*)d_in[21];
  const float* Wa2    = (const float*)d_in[22];
  const float* ba2    = (const float*)d_in[23];
  // d_in[24] = Wstab: unused (P_stable is uniform = 1/C exactly)
  const float* betac  = (const float*)d_in[25];
  const float* lTc    = (const float*)d_in[26];
  const float* lTt    = (const float*)d_in[27];
  const float* lTi    = (const float*)d_in[28];
  float* out = (float*)d_out;

  cudaFuncSetAttribute(k_score, cudaFuncAttributeMaxDynamicSharedMemorySize, 98304);

  k_init<<<(B_*128+255)/256, 256>>>();
  k_gemm<<<dim3(B_*5/64, 6), 256>>>(Wih, bih, B_*5, 192, 1, ide, txe, lens);
  for (int t=0;t<5;t++){
    k_gemm<<<dim3(B_/64, 6), 256>>>(Whh, bhh, B_, 128, 0, ide, txe, lens);
    k_gru<<<(B_*128+255)/256, 256>>>(t);
  }
  k_wprep<<<(16384+8192+255)/256, 256>>>(Wt1, Wi1);
  k_prep<<<B_/16, 128>>>(ide, txe, lens, sitems, Wt1, bt1, Wi1, bi1, Wa1, ba1, Wa2, ba2);
  k_score<<<B_, 256, 98304>>>(ctxe, cide, cids, co, Wt2, bt2, Wi2, bi2,
                              betac, lTc, lTt, lTi, out);
}

// round 3
// speedup vs baseline: 1.6811x; 1.6811x over previous
#include <cuda_runtime.h>
#include <math.h>

#define B_  2048
#define L_  200
#define C_  100
#define V_  2000

// ---------------- scratch ----------------
__device__ float g_IG[B_*5*384];
__device__ float g_HG[B_*384];
__device__ float g_H [B_*128];
__device__ float g_CT[B_*128];
__device__ float g_CI[B_*128];
__device__ float g_AL[B_*3];
__device__ float g_WT[16384];   // Wt1 mid slab, tf32 fragment-ordered
__device__ float g_WI[8192];    // Wi1 mid slab, tf32 fragment-ordered
__device__ int   g_LI[B_];

__device__ __forceinline__ float sigf(float x){ return 1.0f/(1.0f+expf(-x)); }
__device__ __forceinline__ float wsum(float v){
#pragma unroll
  for (int o=16;o;o>>=1) v += __shfl_xor_sync(0xffffffffu, v, o);
  return v;
}
__device__ __forceinline__ float wmax(float v){
#pragma unroll
  for (int o=16;o;o>>=1) v = fmaxf(v, __shfl_xor_sync(0xffffffffu, v, o));
  return v;
}
__device__ __forceinline__ unsigned f2tf(float x){
  unsigned r; asm("cvt.rna.tf32.f32 %0, %1;" : "=r"(r) : "f"(x)); return r;
}
__device__ __forceinline__ void mma8(float* d,
    unsigned a0, unsigned a1, unsigned a2, unsigned a3,
    unsigned b0, unsigned b1){
  asm volatile(
    "mma.sync.aligned.m16n8k8.row.col.f32.tf32.tf32.f32 "
    "{%0,%1,%2,%3},{%4,%5,%6,%7},{%8,%9},{%0,%1,%2,%3};\n"
    : "+f"(d[0]),"+f"(d[1]),"+f"(d[2]),"+f"(d[3])
    : "r"(a0),"r"(a1),"r"(a2),"r"(a3),"r"(b0),"r"(b1));
}

__global__ void k_init(){
  int i = blockIdx.x*blockDim.x + threadIdx.x;
  if (i < B_*128) g_H[i] = 0.f;
}

// 64x64-tile SGEMM: C[m][n] = A[m][:]·Wrow[n][:] + bias[n]
__global__ __launch_bounds__(256) void k_gemm(
    const float* __restrict__ Bw, const float* __restrict__ bias,
    int M, int K, int gather,
    const float* __restrict__ ide, const float* __restrict__ txe,
    const int* __restrict__ lens)
{
  __shared__ float As[16][64];
  __shared__ float Bs[16][64];
  const int tid = threadIdx.x;
  const int m0 = blockIdx.x*64, n0 = blockIdx.y*64;
  const int lm = tid & 63, lk4 = (tid >> 6) * 4;
  const int row0 = (tid & 15)*4, col0 = (tid >> 4)*4;
  const float *arow, *arow2 = 0;
  if (gather){
    int m = m0 + lm; int b = m/5, t = m - 5*b;
    int pos = lens[b] - 5 + t;
    arow  = ide + ((long)b*L_ + pos)*64;
    arow2 = txe + ((long)b*L_ + pos)*128;
  } else {
    arow = g_H + (long)(m0 + lm)*K;
  }
  const float* brow = Bw + (long)(n0 + lm)*K;
  float acc[4][4];
#pragma unroll
  for (int i=0;i<4;i++)
#pragma unroll
    for (int j=0;j<4;j++) acc[i][j]=0.f;

  for (int k0=0;k0<K;k0+=16){
    int kk = k0 + lk4;
    float4 a4;
    if (gather) a4 = (kk < 64) ? *(const float4*)(arow+kk) : *(const float4*)(arow2+kk-64);
    else        a4 = *(const float4*)(arow+kk);
    float4 b4 = *(const float4*)(brow+kk);
    As[lk4+0][lm]=a4.x; As[lk4+1][lm]=a4.y; As[lk4+2][lm]=a4.z; As[lk4+3][lm]=a4.w;
    Bs[lk4+0][lm]=b4.x; Bs[lk4+1][lm]=b4.y; Bs[lk4+2][lm]=b4.z; Bs[lk4+3][lm]=b4.w;
    __syncthreads();
#pragma unroll
    for (int k=0;k<16;k++){
      float4 av = *(const float4*)&As[k][row0];
      float4 bv = *(const float4*)&Bs[k][col0];
      acc[0][0]=fmaf(av.x,bv.x,acc[0][0]); acc[0][1]=fmaf(av.x,bv.y,acc[0][1]);
      acc[0][2]=fmaf(av.x,bv.z,acc[0][2]); acc[0][3]=fmaf(av.x,bv.w,acc[0][3]);
      acc[1][0]=fmaf(av.y,bv.x,acc[1][0]); acc[1][1]=fmaf(av.y,bv.y,acc[1][1]);
      acc[1][2]=fmaf(av.y,bv.z,acc[1][2]); acc[1][3]=fmaf(av.y,bv.w,acc[1][3]);
      acc[2][0]=fmaf(av.z,bv.x,acc[2][0]); acc[2][1]=fmaf(av.z,bv.y,acc[2][1]);
      acc[2][2]=fmaf(av.z,bv.z,acc[2][2]); acc[2][3]=fmaf(av.z,bv.w,acc[2][3]);
      acc[3][0]=fmaf(av.w,bv.x,acc[3][0]); acc[3][1]=fmaf(av.w,bv.y,acc[3][1]);
      acc[3][2]=fmaf(av.w,bv.z,acc[3][2]); acc[3][3]=fmaf(av.w,bv.w,acc[3][3]);
    }
    __syncthreads();
  }
  float* outp = gather ? g_IG : g_HG;
#pragma unroll
  for (int i=0;i<4;i++){
    float* crow = outp + (long)(m0+row0+i)*384 + n0 + col0;
#pragma unroll
    for (int j=0;j<4;j++) crow[j] = acc[i][j] + bias[n0+col0+j];
  }
}

__global__ void k_gru(int t){
  int idx = blockIdx.x*blockDim.x + threadIdx.x;
  if (idx >= B_*128) return;
  int b = idx >> 7, j = idx & 127;
  const float* ig = g_IG + ((long)b*5 + t)*384;
  const float* hg = g_HG + (long)b*384;
  float r = sigf(ig[j]     + hg[j]);
  float z = sigf(ig[128+j] + hg[128+j]);
  float n = tanhf(ig[256+j] + r*hg[256+j]);
  float h = g_H[idx];
  g_H[idx] = (1.f - z)*n + z*h;
}

// prepare scorer mid-slab weights in mma fragment order (tf32-rounded).
// layout: flat idx -> c=idx&3, lane=(idx>>2)&31, n2=(idx>>7)&7, kt=idx>>10
//   nt = 2*n2 + (c>>1), p = c&1, j = nt*8 + (lane>>2), k = kt*8 + (lane&3) + 4*p
__global__ void k_wprep(const float* __restrict__ Wt1, const float* __restrict__ Wi1){
  int idx = blockIdx.x*blockDim.x + threadIdx.x;
  if (idx < 16384){
    int c = idx&3, lane = (idx>>2)&31, n2 = (idx>>7)&7, kt = idx>>10;
    int nt = 2*n2 + (c>>1), p = c&1;
    int j = nt*8 + (lane>>2), k = kt*8 + (lane&3) + 4*p;
    unsigned v = f2tf(Wt1[(long)j*384 + 128 + k]);
    g_WT[idx] = __uint_as_float(v);
  } else if (idx < 16384 + 8192){
    int i2 = idx - 16384;
    int c = i2&3, lane = (i2>>2)&31, n2 = (i2>>7)&7, kt = i2>>10;
    int nt = 2*n2 + (c>>1), p = c&1;
    int j = nt*8 + (lane>>2), k = kt*8 + (lane&3) + 4*p;
    unsigned v = f2tf(Wi1[(long)j*256 + 64 + k]);
    g_WI[i2] = __uint_as_float(v);
  }
}

// per-batch constants: ct, ci, alpha, last item; 16 batches per block, 128 thr
__global__ __launch_bounds__(128) void k_prep(
    const float* __restrict__ ide, const float* __restrict__ txe,
    const int* __restrict__ lens, const int* __restrict__ sitems,
    const float* __restrict__ Wt1, const float* __restrict__ bt1,
    const float* __restrict__ Wi1, const float* __restrict__ bi1,
    const float* __restrict__ Wa1, const float* __restrict__ ba1,
    const float* __restrict__ Wa2, const float* __restrict__ ba2)
{
  __shared__ float lt[16][128], hh[16][128], lid[16][64], a1s[16][64], lg[16][3];
  __shared__ int Ls[16];
  const int tid = threadIdx.x;
  const int b0 = blockIdx.x * 16;
  if (tid < 16) Ls[tid] = lens[b0+tid];
  __syncthreads();
  for (int i=tid;i<2048;i+=128){
    int bb=i>>7, k=i&127; int pos = Ls[bb]-1;
    lt[bb][k] = txe[((long)(b0+bb)*L_ + pos)*128 + k];
    hh[bb][k] = g_H[(b0+bb)*128 + k];
  }
  for (int i=tid;i<1024;i+=128){
    int bb=i>>6, k=i&63;
    lid[bb][k] = ide[((long)(b0+bb)*L_ + Ls[bb]-1)*64 + k];
  }
  if (tid < 16) g_LI[b0+tid] = sitems[(long)(b0+tid)*L_ + Ls[tid]-1];
  __syncthreads();

  const int j = tid;
  { // ct
    float acc[16];
#pragma unroll
    for (int bb=0;bb<16;bb++) acc[bb] = bt1[j];
    const float* w1 = Wt1 + (long)j*384;
    const float* w3 = w1 + 256;
    for (int k=0;k<128;k++){
      float ws = w1[k], wh = w3[k];
#pragma unroll
      for (int bb=0;bb<16;bb++) acc[bb] += ws*lt[bb][k] + wh*hh[bb][k];
    }
#pragma unroll
    for (int bb=0;bb<16;bb++) g_CT[(b0+bb)*128 + j] = acc[bb];
  }
  { // ci
    float acc[16];
#pragma unroll
    for (int bb=0;bb<16;bb++) acc[bb] = bi1[j];
    const float* w1 = Wi1 + (long)j*256;
    const float* w3 = w1 + 128;
    for (int k=0;k<64;k++){
      float ws = w1[k];
#pragma unroll
      for (int bb=0;bb<16;bb++) acc[bb] += ws*lid[bb][k];
    }
    for (int k=0;k<128;k++){
      float wh = w3[k];
#pragma unroll
      for (int bb=0;bb<16;bb++) acc[bb] += wh*hh[bb][k];
    }
#pragma unroll
    for (int bb=0;bb<16;bb++) g_CI[(b0+bb)*128 + j] = acc[bb];
  }
  if (tid < 64){ // alpha hidden
    const int u = tid;
    float acc[16];
#pragma unroll
    for (int bb=0;bb<16;bb++) acc[bb] = ba1[u];
    const float* w = Wa1 + (long)u*128;
    for (int k=0;k<128;k++){
      float wv = w[k];
#pragma unroll
      for (int bb=0;bb<16;bb++) acc[bb] += wv*hh[bb][k];
    }
#pragma unroll
    for (int bb=0;bb<16;bb++) a1s[bb][u] = fmaxf(acc[bb], 0.f);
  }
  __syncthreads();
  if (tid < 48){
    int bb = tid/3, g = tid%3;
    float s = ba2[g];
    const float* w = Wa2 + g*64;
    for (int u=0;u<64;u++) s += w[u]*a1s[bb][u];
    lg[bb][g] = s;
  }
  __syncthreads();
  if (tid < 16){
    float l0=lg[tid][0], l1=lg[tid][1], l2=lg[tid][2];
    float m = fmaxf(l0, fmaxf(l1,l2));
    float e0=expf(l0-m), e1=expf(l1-m), e2=expf(l2-m);
    float inv = 1.f/(e0+e1+e2);
    g_AL[(b0+tid)*3+0]=e0*inv; g_AL[(b0+tid)*3+1]=e1*inv; g_AL[(b0+tid)*3+2]=e2*inv;
  }
}

// fused scorer (tf32 tensor cores) + softmaxes + mix: one block per batch
__global__ __launch_bounds__(256) void k_score(
    const float* __restrict__ ctxe, const float* __restrict__ cide,
    const int* __restrict__ cids, const float* __restrict__ co,
    const float* __restrict__ Wt2, const float* __restrict__ bt2,
    const float* __restrict__ Wi2, const float* __restrict__ bi2,
    const float* __restrict__ betac, const float* __restrict__ lTc,
    const float* __restrict__ lTt, const float* __restrict__ lTi,
    float* __restrict__ out)
{
  extern __shared__ float dyn[];
  float* sWT = dyn;            // 16384 floats
  float* sWI = dyn + 16384;    // 8192 floats
  __shared__ float ctv[128], civ[128], w2t[128], w2i[128];
  __shared__ float sco[3][128];
  __shared__ float mx3[3], inv3[3], sS;
  __shared__ float mixv[128];
  const int b = blockIdx.x, tid = threadIdx.x;
  const int warp = tid>>5, lane = tid&31;
  const int g = lane>>2, tig = lane&3;
  const int r0 = warp*16 + g, r1 = r0 + 8;

  if (tid < 128){
    ctv[tid]=g_CT[b*128+tid]; civ[tid]=g_CI[b*128+tid];
    w2t[tid]=Wt2[tid];        w2i[tid]=Wi2[tid];
  }
  for (int i=tid;i<16384;i+=256) sWT[i] = g_WT[i];
  for (int i=tid;i<8192;i+=256)  sWI[i] = g_WI[i];
  if (tid < 100){
    long li = g_LI[b];
    sco[0][tid] = co[li*V_ + cids[(long)b*C_+tid]] * betac[0] / expf(lTc[0]);
  }
  const float Tt = expf(lTt[0]), Ti = expf(lTi[0]);
  __syncthreads();

  // ---------- text pass: M=128(pad 100) x N=128 x K=128 ----------
  {
    float acc[16][4];
#pragma unroll
    for (int nt=0;nt<16;nt++){
      acc[nt][0]=0.f; acc[nt][1]=0.f; acc[nt][2]=0.f; acc[nt][3]=0.f;
    }
    const float* Eb = ctxe + (long)b*C_*128;
    const float4* bp = (const float4*)sWT;
#pragma unroll
    for (int kt=0;kt<16;kt++){
      const int k0 = kt*8 + tig;
      unsigned a0=0u,a1=0u,a2=0u,a3=0u;
      if (r0 < C_){ a0 = f2tf(Eb[(long)r0*128 + k0]); a2 = f2tf(Eb[(long)r0*128 + k0 + 4]); }
      if (r1 < C_){ a1 = f2tf(Eb[(long)r1*128 + k0]); a3 = f2tf(Eb[(long)r1*128 + k0 + 4]); }
#pragma unroll
      for (int n2=0;n2<8;n2++){
        float4 bv = bp[(kt*8 + n2)*32 + lane];
        mma8(acc[2*n2],   a0,a1,a2,a3, __float_as_uint(bv.x), __float_as_uint(bv.y));
        mma8(acc[2*n2+1], a0,a1,a2,a3, __float_as_uint(bv.z), __float_as_uint(bv.w));
      }
    }
    float p0=0.f, p1=0.f;
#pragma unroll
    for (int nt=0;nt<16;nt++){
      int j0 = nt*8 + 2*tig;
      float w0=w2t[j0], w1=w2t[j0+1], c0=ctv[j0], c1=ctv[j0+1];
      p0 += w0*fmaxf(c0+acc[nt][0],0.f) + w1*fmaxf(c1+acc[nt][1],0.f);
      p1 += w0*fmaxf(c0+acc[nt][2],0.f) + w1*fmaxf(c1+acc[nt][3],0.f);
    }
    p0 += __shfl_xor_sync(0xffffffffu,p0,1); p0 += __shfl_xor_sync(0xffffffffu,p0,2);
    p1 += __shfl_xor_sync(0xffffffffu,p1,1); p1 += __shfl_xor_sync(0xffffffffu,p1,2);
    if (tig==0){
      if (r0 < C_) sco[1][r0] = (p0 + bt2[0]) / Tt;
      if (r1 < C_) sco[1][r1] = (p1 + bt2[0]) / Tt;
    }
  }

  // ---------- id pass: M=128(pad 100) x N=128 x K=64 ----------
  {
    float acc[16][4];
#pragma unroll
    for (int nt=0;nt<16;nt++){
      acc[nt][0]=0.f; acc[nt][1]=0.f; acc[nt][2]=0.f; acc[nt][3]=0.f;
    }
    const float* Eb = cide + (long)b*C_*64;
    const float4* bp = (const float4*)sWI;
#pragma unroll
    for (int kt=0;kt<8;kt++){
      const int k0 = kt*8 + tig;
      unsigned a0=0u,a1=0u,a2=0u,a3=0u;
      if (r0 < C_){ a0 = f2tf(Eb[(long)r0*64 + k0]); a2 = f2tf(Eb[(long)r0*64 + k0 + 4]); }
      if (r1 < C_){ a1 = f2tf(Eb[(long)r1*64 + k0]); a3 = f2tf(Eb[(long)r1*64 + k0 + 4]); }
#pragma unroll
      for (int n2=0;n2<8;n2++){
        float4 bv = bp[(kt*8 + n2)*32 + lane];
        mma8(acc[2*n2],   a0,a1,a2,a3, __float_as_uint(bv.x), __float_as_uint(bv.y));
        mma8(acc[2*n2+1], a0,a1,a2,a3, __float_as_uint(bv.z), __float_as_uint(bv.w));
      }
    }
    float p0=0.f, p1=0.f;
#pragma unroll
    for (int nt=0;nt<16;nt++){
      int j0 = nt*8 + 2*tig;
      float w0=w2i[j0], w1=w2i[j0+1], c0=civ[j0], c1=civ[j0+1];
      p0 += w0*fmaxf(c0+acc[nt][0],0.f) + w1*fmaxf(c1+acc[nt][1],0.f);
      p1 += w0*fmaxf(c0+acc[nt][2],0.f) + w1*fmaxf(c1+acc[nt][3],0.f);
    }
    p0 += __shfl_xor_sync(0xffffffffu,p0,1); p0 += __shfl_xor_sync(0xffffffffu,p0,2);
    p1 += __shfl_xor_sync(0xffffffffu,p1,1); p1 += __shfl_xor_sync(0xffffffffu,p1,2);
    if (tig==0){
      if (r0 < C_) sco[2][r0] = (p0 + bi2[0]) / Ti;
      if (r1 < C_) sco[2][r1] = (p1 + bi2[0]) / Ti;
    }
  }
  __syncthreads();

  // softmaxes
  if (warp == 0){
#pragma unroll
    for (int chn=0;chn<3;chn++){
      float m = -1e30f;
      for (int q=lane;q<C_;q+=32) m = fmaxf(m, sco[chn][q]);
      m = wmax(m);
      float s = 0.f;
      for (int q=lane;q<C_;q+=32) s += expf(sco[chn][q]-m);
      s = wsum(s);
      if (lane==0){ mx3[chn]=m; inv3[chn]=1.f/s; }
    }
  }
  __syncthreads();
  const float a0=g_AL[b*3], a1=g_AL[b*3+1], a2=g_AL[b*3+2];
  if (tid < C_){
    float p = 0.01f
      + a0*expf(sco[0][tid]-mx3[0])*inv3[0]
      + a1*expf(sco[1][tid]-mx3[1])*inv3[1]
      + a2*expf(sco[2][tid]-mx3[2])*inv3[2];
    mixv[tid] = p;
  }
  __syncthreads();
  if (warp == 0){
    float s = 0.f;
    for (int q=lane;q<C_;q+=32) s += mixv[q];
    s = wsum(s);
    if (lane==0) sS = 1.f/s;
  }
  __syncthreads();
  if (tid < C_) out[(long)b*C_ + tid] = mixv[tid]*sS;
}

extern "C" void kernel_launch(void* const* d_in, const int* in_sizes, int n_in,
                              void* d_out, int out_size) {
  const int*   sitems = (const int*)  d_in[0];
  const float* ide    = (const float*)d_in[1];
  const float* txe    = (const float*)d_in[2];
  const int*   lens   = (const int*)  d_in[3];
  const int*   cids   = (const int*)  d_in[4];
  const float* cide   = (const float*)d_in[5];
  const float* ctxe   = (const float*)d_in[6];
  const float* co     = (const float*)d_in[7];
  const float* Wih    = (const float*)d_in[8];
  const float* Whh    = (const float*)d_in[9];
  const float* bih    = (const float*)d_in[10];
  const float* bhh    = (const float*)d_in[11];
  const float* Wt1    = (const float*)d_in[12];
  const float* bt1    = (const float*)d_in[13];
  const float* Wt2    = (const float*)d_in[14];
  const float* bt2    = (const float*)d_in[15];
  const float* Wi1    = (const float*)d_in[16];
  const float* bi1    = (const float*)d_in[17];
  const float* Wi2    = (const float*)d_in[18];
  const float* bi2    = (const float*)d_in[19];
  const float* Wa1    = (const float*)d_in[20];
  const float* ba1    = (const float*)d_in[21];
  const float* Wa2    = (const float*)d_in[22];
  const float* ba2    = (const float*)d_in[23];
  // d_in[24] = Wstab: unused (P_stable is uniform = 1/C exactly)
  const float* betac  = (const float*)d_in[25];
  const float* lTc    = (const float*)d_in[26];
  const float* lTt    = (const float*)d_in[27];
  const float* lTi    = (const float*)d_in[28];
  float* out = (float*)d_out;

  cudaFuncSetAttribute(k_score, cudaFuncAttributeMaxDynamicSharedMemorySize, 98304);

  k_init<<<(B_*128+255)/256, 256>>>();
  k_gemm<<<dim3(B_*5/64, 6), 256>>>(Wih, bih, B_*5, 192, 1, ide, txe, lens);
  for (int t=0;t<5;t++){
    k_gemm<<<dim3(B_/64, 6), 256>>>(Whh, bhh, B_, 128, 0, ide, txe, lens);
    k_gru<<<(B_*128+255)/256, 256>>>(t);
  }
  k_wprep<<<(16384+8192+255)/256, 256>>>(Wt1, Wi1);
  k_prep<<<B_/16, 128>>>(ide, txe, lens, sitems, Wt1, bt1, Wi1, bi1, Wa1, ba1, Wa2, ba2);
  k_score<<<B_, 256, 98304>>>(ctxe, cide, cids, co, Wt2, bt2, Wi2, bi2,
                              betac, lTc, lTt, lTi, out);
}

// round 5
// speedup vs baseline: 1.9538x; 1.1622x over previous
#include <cuda_runtime.h>
#include <math.h>

#define B_  2048
#define L_  200
#define C_  100
#define V_  2000

// ---------------- scratch ----------------
__device__ float g_IG [B_*5*384];
__device__ float g_HB [2][B_*128];     // double-buffered hidden
__device__ float g_CT [B_*128];
__device__ float g_CI [B_*128];
__device__ float g_AL [B_*3];
__device__ float g_WT [16384];         // Wt1 mid slab   (N=128,K=128) frag order
__device__ float g_WI [8192];          // Wi1 mid slab   (N=128,K=64)  frag order
__device__ float g_WIHf[73728];        // W_ih           (N=384,K=192) frag order
__device__ float g_WHHf[49152];        // W_hh           (N=384,K=128) frag order
__device__ int   g_LI [B_];

__device__ __forceinline__ float sigf(float x){ return 1.0f/(1.0f+__expf(-x)); }
__device__ __forceinline__ float tanhf_fast(float x){
  x = fminf(fmaxf(x,-15.f),15.f);
  float e = __expf(2.f*x);
  return (e-1.f)/(e+1.f);
}
__device__ __forceinline__ float wsum(float v){
#pragma unroll
  for (int o=16;o;o>>=1) v += __shfl_xor_sync(0xffffffffu, v, o);
  return v;
}
__device__ __forceinline__ float wmax(float v){
#pragma unroll
  for (int o=16;o;o>>=1) v = fmaxf(v, __shfl_xor_sync(0xffffffffu, v, o));
  return v;
}
__device__ __forceinline__ unsigned f2tf(float x){
  unsigned r; asm("cvt.rna.tf32.f32 %0, %1;" : "=r"(r) : "f"(x)); return r;
}
__device__ __forceinline__ void mma8(float* d,
    unsigned a0, unsigned a1, unsigned a2, unsigned a3,
    unsigned b0, unsigned b1){
  asm volatile(
    "mma.sync.aligned.m16n8k8.row.col.f32.tf32.tf32.f32 "
    "{%0,%1,%2,%3},{%4,%5,%6,%7},{%8,%9},{%0,%1,%2,%3};\n"
    : "+f"(d[0]),"+f"(d[1]),"+f"(d[2]),"+f"(d[3])
    : "r"(a0),"r"(a1),"r"(a2),"r"(a3),"r"(b0),"r"(b1));
}

// decode fragment-order flat index -> (j,k) for weight W[N][K], N rows of 8
__device__ __forceinline__ void frag_jk(int idx, int N, int* jj, int* kk){
  int c = idx & 3, lane = (idx>>2)&31;
  int P = N >> 4;
  int pr = (idx>>7) % P;
  int kt = idx / (128*P);
  int nt = 2*pr + (c>>1), p = c&1;
  *jj = nt*8 + (lane>>2);
  *kk = kt*8 + (lane&3) + 4*p;
}

// ---- prepare all fragment-ordered weights (tf32-rounded) ----
__global__ void k_wprep(const float* __restrict__ Wih, const float* __restrict__ Whh,
                        const float* __restrict__ Wt1, const float* __restrict__ Wi1){
  int idx = blockIdx.x*blockDim.x + threadIdx.x;
  int j, k;
  if (idx < 73728){                     // Wih: N=384, K=192
    frag_jk(idx, 384, &j, &k);
    g_WIHf[idx] = __uint_as_float(f2tf(Wih[(long)j*192 + k]));
  } else if (idx < 73728+49152){        // Whh: N=384, K=128
    int i2 = idx - 73728;
    frag_jk(i2, 384, &j, &k);
    g_WHHf[i2] = __uint_as_float(f2tf(Whh[(long)j*128 + k]));
  } else if (idx < 73728+49152+16384){  // Wt1 mid: N=128, K=128
    int i2 = idx - 73728 - 49152;
    frag_jk(i2, 128, &j, &k);
    g_WT[i2] = __uint_as_float(f2tf(Wt1[(long)j*384 + 128 + k]));
  } else if (idx < 73728+49152+16384+8192){ // Wi1 mid: N=128, K=64
    int i2 = idx - 73728 - 49152 - 16384;
    frag_jk(i2, 128, &j, &k);
    g_WI[i2] = __uint_as_float(f2tf(Wi1[(long)j*256 + 64 + k]));
  }
}

// ---- input-gate GEMM (tf32): IG[m][n] = x_m · Wih[n] + bih[n] ----
// m = b*5+t, x gathered from window; M=10240, N=384, K=192
__global__ __launch_bounds__(256) void k_ig(
    const float* __restrict__ ide, const float* __restrict__ txe,
    const int* __restrict__ lens, const float* __restrict__ bih)
{
  __shared__ float sB[384];
  const int tid = threadIdx.x, warp = tid>>5, lane = tid&31;
  const int g = lane>>2, tig = lane&3;
  for (int i=tid; i<384; i+=256) sB[i] = bih[i];
  const int r0 = blockIdx.x*128 + warp*16 + g;
  const int r1 = r0 + 8;
  int b0 = r0/5, t0 = r0 - 5*b0;  int p0 = lens[b0] - 5 + t0;
  int b1 = r1/5, t1 = r1 - 5*b1;  int p1 = lens[b1] - 5 + t1;
  const float* id0 = ide + ((long)b0*L_ + p0)*64;
  const float* tx0 = txe + ((long)b0*L_ + p0)*128;
  const float* id1 = ide + ((long)b1*L_ + p1)*64;
  const float* tx1 = txe + ((long)b1*L_ + p1)*128;
  __syncthreads();

  const float4* bp = (const float4*)g_WIHf;
  for (int ch=0; ch<3; ch++){
    float acc[16][4];
#pragma unroll
    for (int nt=0;nt<16;nt++){ acc[nt][0]=0.f;acc[nt][1]=0.f;acc[nt][2]=0.f;acc[nt][3]=0.f; }
#pragma unroll
    for (int kt=0;kt<24;kt++){
      int k0 = kt*8 + tig, k4 = k0+4;
      unsigned a0 = f2tf(k0<64 ? id0[k0] : tx0[k0-64]);
      unsigned a2 = f2tf(k4<64 ? id0[k4] : tx0[k4-64]);
      unsigned a1 = f2tf(k0<64 ? id1[k0] : tx1[k0-64]);
      unsigned a3 = f2tf(k4<64 ? id1[k4] : tx1[k4-64]);
#pragma unroll
      for (int n2=0;n2<8;n2++){
        float4 bv = bp[(kt*24 + ch*8 + n2)*32 + lane];
        mma8(acc[2*n2],   a0,a1,a2,a3, __float_as_uint(bv.x), __float_as_uint(bv.y));
        mma8(acc[2*n2+1], a0,a1,a2,a3, __float_as_uint(bv.z), __float_as_uint(bv.w));
      }
    }
#pragma unroll
    for (int nt=0;nt<16;nt++){
      int j = ch*128 + nt*8 + 2*tig;
      float* o0 = g_IG + (long)r0*384 + j;
      float* o1 = g_IG + (long)r1*384 + j;
      o0[0] = acc[nt][0]+sB[j]; o0[1] = acc[nt][1]+sB[j+1];
      o1[0] = acc[nt][2]+sB[j]; o1[1] = acc[nt][3]+sB[j+1];
    }
  }
}

// ---- GRU step 0: h = (1-z)*n, recurrent gates = bhh ----
__global__ void k_gru0(const float* __restrict__ bhh, float* __restrict__ hout){
  int idx = blockIdx.x*blockDim.x + threadIdx.x;
  if (idx >= B_*128) return;
  int b = idx >> 7, j = idx & 127;
  const float* ig = g_IG + ((long)b*5)*384;
  float r = sigf(ig[j]     + bhh[j]);
  float z = sigf(ig[128+j] + bhh[128+j]);
  float n = tanhf_fast(ig[256+j] + r*bhh[256+j]);
  hout[idx] = (1.f - z)*n;
}

// ---- fused GRU step t (t>=1): HG = h@Whh^T (tf32 MMA) + update, in registers
// block: 256 thr = 8 warps = 2 rowgroups(16) x 4 colgroups(32 j-cols); M-tile 32
__global__ __launch_bounds__(256) void k_step(
    int t, const float* __restrict__ hin, float* __restrict__ hout,
    const float* __restrict__ bhh)
{
  __shared__ float sB[384];
  const int tid = threadIdx.x, warp = tid>>5, lane = tid&31;
  const int g = lane>>2, tig = lane&3;
  const int rowg = warp>>2, colg = warp&3;
  const int r0 = blockIdx.x*32 + rowg*16 + g, r1 = r0+8;
  const int jb = colg*32;
  for (int i=tid; i<384; i+=256) sB[i] = bhh[i];
  __syncthreads();

  float acc[12][4];
#pragma unroll
  for (int i=0;i<12;i++){ acc[i][0]=0.f;acc[i][1]=0.f;acc[i][2]=0.f;acc[i][3]=0.f; }
  const float4* bp = (const float4*)g_WHHf;
  const float* h0p = hin + (long)r0*128;
  const float* h1p = hin + (long)r1*128;
#pragma unroll
  for (int kt=0;kt<16;kt++){
    int k0 = kt*8 + tig;
    unsigned a0 = f2tf(h0p[k0]), a2 = f2tf(h0p[k0+4]);
    unsigned a1 = f2tf(h1p[k0]), a3 = f2tf(h1p[k0+4]);
#pragma unroll
    for (int gate=0;gate<3;gate++){
#pragma unroll
      for (int op=0;op<2;op++){
        int pr = gate*8 + colg*2 + op;
        float4 bv = bp[(kt*24 + pr)*32 + lane];
        mma8(acc[gate*4+op*2],   a0,a1,a2,a3, __float_as_uint(bv.x), __float_as_uint(bv.y));
        mma8(acc[gate*4+op*2+1], a0,a1,a2,a3, __float_as_uint(bv.z), __float_as_uint(bv.w));
      }
    }
  }
  const float* ig0 = g_IG + ((long)r0*5 + t)*384;
  const float* ig1 = g_IG + ((long)r1*5 + t)*384;
#pragma unroll
  for (int o=0;o<4;o++){
#pragma unroll
    for (int c=0;c<2;c++){
      int j = jb + o*8 + 2*tig + c;
      {
        float hgr = acc[o][c]   + sB[j];
        float hgz = acc[4+o][c] + sB[128+j];
        float hgn = acc[8+o][c] + sB[256+j];
        float r = sigf(ig0[j] + hgr);
        float z = sigf(ig0[128+j] + hgz);
        float n = tanhf_fast(ig0[256+j] + r*hgn);
        hout[(long)r0*128+j] = (1.f-z)*n + z*h0p[j];
      }
      {
        float hgr = acc[o][c+2]   + sB[j];
        float hgz = acc[4+o][c+2] + sB[128+j];
        float hgn = acc[8+o][c+2] + sB[256+j];
        float r = sigf(ig1[j] + hgr);
        float z = sigf(ig1[128+j] + hgz);
        float n = tanhf_fast(ig1[256+j] + r*hgn);
        hout[(long)r1*128+j] = (1.f-z)*n + z*h1p[j];
      }
    }
  }
}

// ---- per-batch constants: ct, ci, alpha, last item; 16 batches, 256 thr ----
__global__ __launch_bounds__(256) void k_prep(
    const float* __restrict__ ide, const float* __restrict__ txe,
    const int* __restrict__ lens, const int* __restrict__ sitems,
    const float* __restrict__ hfin,
    const float* __restrict__ Wt1, const float* __restrict__ bt1,
    const float* __restrict__ Wi1, const float* __restrict__ bi1,
    const float* __restrict__ Wa1, const float* __restrict__ ba1,
    const float* __restrict__ Wa2, const float* __restrict__ ba2)
{
  __shared__ float lt[16][128], hh[16][128], lid[16][64], a1s[16][64], lg[16][3];
  __shared__ float sP[16][128];
  __shared__ int Ls[16];
  const int tid = threadIdx.x;
  const int b0 = blockIdx.x * 16;
  if (tid < 16) Ls[tid] = lens[b0+tid];
  __syncthreads();
  for (int i=tid;i<2048;i+=256){
    int bb=i>>7, k=i&127; int pos = Ls[bb]-1;
    lt[bb][k] = txe[((long)(b0+bb)*L_ + pos)*128 + k];
    hh[bb][k] = hfin[(b0+bb)*128 + k];
  }
  for (int i=tid;i<1024;i+=256){
    int bb=i>>6, k=i&63;
    lid[bb][k] = ide[((long)(b0+bb)*L_ + Ls[bb]-1)*64 + k];
  }
  if (tid < 16) g_LI[b0+tid] = sitems[(long)(b0+tid)*L_ + Ls[tid]-1];
  __syncthreads();

  const int j = tid & 127, half = tid >> 7;
  { // ct: split k-range between halves
    float acc[16];
#pragma unroll
    for (int bb=0;bb<16;bb++) acc[bb] = 0.f;
    const float* w1 = Wt1 + (long)j*384;
    const float* w3 = w1 + 256;
    int kb = half*64;
    for (int k=kb;k<kb+64;k++){
      float ws = w1[k], wh = w3[k];
#pragma unroll
      for (int bb=0;bb<16;bb++) acc[bb] += ws*lt[bb][k] + wh*hh[bb][k];
    }
    if (half==1){ for (int bb=0;bb<16;bb++) sP[bb][j] = acc[bb]; }
    __syncthreads();
    if (half==0){
      float bv = bt1[j];
      for (int bb=0;bb<16;bb++) g_CT[(b0+bb)*128 + j] = acc[bb] + sP[bb][j] + bv;
    }
    __syncthreads();
  }
  { // ci: half0 = lid(64) + hh[0:32]; half1 = hh[32:128]
    float acc[16];
#pragma unroll
    for (int bb=0;bb<16;bb++) acc[bb] = 0.f;
    const float* w1 = Wi1 + (long)j*256;
    const float* w3 = w1 + 128;
    if (half==0){
      for (int k=0;k<64;k++){
        float ws = w1[k];
#pragma unroll
        for (int bb=0;bb<16;bb++) acc[bb] += ws*lid[bb][k];
      }
      for (int k=0;k<32;k++){
        float wh = w3[k];
#pragma unroll
        for (int bb=0;bb<16;bb++) acc[bb] += wh*hh[bb][k];
      }
    } else {
      for (int k=32;k<128;k++){
        float wh = w3[k];
#pragma unroll
        for (int bb=0;bb<16;bb++) acc[bb] += wh*hh[bb][k];
      }
      for (int bb=0;bb<16;bb++) sP[bb][j] = acc[bb];
    }
    __syncthreads();
    if (half==0){
      float bv = bi1[j];
      for (int bb=0;bb<16;bb++) g_CI[(b0+bb)*128 + j] = acc[bb] + sP[bb][j] + bv;
    }
    __syncthreads();
  }
  { // alpha hidden: u = tid&63, k split between (tid>>6)==0/1; uniform barriers
    const int u = tid & 63, h2 = tid >> 6;   // h2 in 0..3; only 0,1 compute
    float acc[16];
#pragma unroll
    for (int bb=0;bb<16;bb++) acc[bb] = 0.f;
    if (h2 < 2){
      const float* w = Wa1 + (long)u*128;
      int kb = h2*64;
      for (int k=kb;k<kb+64;k++){
        float wv = w[k];
#pragma unroll
        for (int bb=0;bb<16;bb++) acc[bb] += wv*hh[bb][k];
      }
      if (h2==1){ for (int bb=0;bb<16;bb++) sP[bb][u] = acc[bb]; }
    }
    __syncthreads();
    if (h2==0){
      float bv = ba1[u];
      for (int bb=0;bb<16;bb++) a1s[bb][u] = fmaxf(acc[bb] + sP[bb][u] + bv, 0.f);
    }
    __syncthreads();
  }
  if (tid < 48){
    int bb = tid/3, gg = tid%3;
    float s = ba2[gg];
    const float* w = Wa2 + gg*64;
    for (int u=0;u<64;u++) s += w[u]*a1s[bb][u];
    lg[bb][gg] = s;
  }
  __syncthreads();
  if (tid < 16){
    float l0=lg[tid][0], l1=lg[tid][1], l2=lg[tid][2];
    float m = fmaxf(l0, fmaxf(l1,l2));
    float e0=__expf(l0-m), e1=__expf(l1-m), e2=__expf(l2-m);
    float inv = 1.f/(e0+e1+e2);
    g_AL[(b0+tid)*3+0]=e0*inv; g_AL[(b0+tid)*3+1]=e1*inv; g_AL[(b0+tid)*3+2]=e2*inv;
  }
}

// ---- fused scorer (tf32) + softmaxes + mix: one block per batch ----
__global__ __launch_bounds__(256) void k_score(
    const float* __restrict__ ctxe, const float* __restrict__ cide,
    const int* __restrict__ cids, const float* __restrict__ co,
    const float* __restrict__ Wt2, const float* __restrict__ bt2,
    const float* __restrict__ Wi2, const float* __restrict__ bi2,
    const float* __restrict__ betac, const float* __restrict__ lTc,
    const float* __restrict__ lTt, const float* __restrict__ lTi,
    float* __restrict__ out)
{
  extern __shared__ float dyn[];
  float* sWT = dyn;            // 16384 floats
  float* sWI = dyn + 16384;    // 8192 floats
  __shared__ float ctv[128], civ[128], w2t[128], w2i[128];
  __shared__ float sco[3][128];
  __shared__ float mx3[3], inv3[3], sS;
  __shared__ float mixv[128];
  const int b = blockIdx.x, tid = threadIdx.x;
  const int warp = tid>>5, lane = tid&31;
  const int g = lane>>2, tig = lane&3;
  const int r0 = warp*16 + g, r1 = r0 + 8;

  if (tid < 128){
    ctv[tid]=g_CT[b*128+tid]; civ[tid]=g_CI[b*128+tid];
    w2t[tid]=Wt2[tid];        w2i[tid]=Wi2[tid];
  }
  for (int i=tid;i<16384;i+=256) sWT[i] = g_WT[i];
  for (int i=tid;i<8192;i+=256)  sWI[i] = g_WI[i];
  if (tid < 100){
    long li = g_LI[b];
    sco[0][tid] = co[li*V_ + cids[(long)b*C_+tid]] * betac[0] / expf(lTc[0]);
  }
  const float Tt = expf(lTt[0]), Ti = expf(lTi[0]);
  __syncthreads();

  // text pass: M=128(pad 100) x N=128 x K=128
  {
    float acc[16][4];
#pragma unroll
    for (int nt=0;nt<16;nt++){ acc[nt][0]=0.f;acc[nt][1]=0.f;acc[nt][2]=0.f;acc[nt][3]=0.f; }
    const float* Eb = ctxe + (long)b*C_*128;
    const float4* bp = (const float4*)sWT;
#pragma unroll
    for (int kt=0;kt<16;kt++){
      const int k0 = kt*8 + tig;
      unsigned a0=0u,a1=0u,a2=0u,a3=0u;
      if (r0 < C_){ a0 = f2tf(Eb[(long)r0*128 + k0]); a2 = f2tf(Eb[(long)r0*128 + k0 + 4]); }
      if (r1 < C_){ a1 = f2tf(Eb[(long)r1*128 + k0]); a3 = f2tf(Eb[(long)r1*128 + k0 + 4]); }
#pragma unroll
      for (int n2=0;n2<8;n2++){
        float4 bv = bp[(kt*8 + n2)*32 + lane];
        mma8(acc[2*n2],   a0,a1,a2,a3, __float_as_uint(bv.x), __float_as_uint(bv.y));
        mma8(acc[2*n2+1], a0,a1,a2,a3, __float_as_uint(bv.z), __float_as_uint(bv.w));
      }
    }
    float p0=0.f, p1=0.f;
#pragma unroll
    for (int nt=0;nt<16;nt++){
      int j0 = nt*8 + 2*tig;
      float w0=w2t[j0], w1=w2t[j0+1], c0=ctv[j0], c1=ctv[j0+1];
      p0 += w0*fmaxf(c0+acc[nt][0],0.f) + w1*fmaxf(c1+acc[nt][1],0.f);
      p1 += w0*fmaxf(c0+acc[nt][2],0.f) + w1*fmaxf(c1+acc[nt][3],0.f);
    }
    p0 += __shfl_xor_sync(0xffffffffu,p0,1); p0 += __shfl_xor_sync(0xffffffffu,p0,2);
    p1 += __shfl_xor_sync(0xffffffffu,p1,1); p1 += __shfl_xor_sync(0xffffffffu,p1,2);
    if (tig==0){
      if (r0 < C_) sco[1][r0] = (p0 + bt2[0]) / Tt;
      if (r1 < C_) sco[1][r1] = (p1 + bt2[0]) / Tt;
    }
  }
  // id pass: K=64
  {
    float acc[16][4];
#pragma unroll
    for (int nt=0;nt<16;nt++){ acc[nt][0]=0.f;acc[nt][1]=0.f;acc[nt][2]=0.f;acc[nt][3]=0.f; }
    const float* Eb = cide + (long)b*C_*64;
    const float4* bp = (const float4*)sWI;
#pragma unroll
    for (int kt=0;kt<8;kt++){
      const int k0 = kt*8 + tig;
      unsigned a0=0u,a1=0u,a2=0u,a3=0u;
      if (r0 < C_){ a0 = f2tf(Eb[(long)r0*64 + k0]); a2 = f2tf(Eb[(long)r0*64 + k0 + 4]); }
      if (r1 < C_){ a1 = f2tf(Eb[(long)r1*64 + k0]); a3 = f2tf(Eb[(long)r1*64 + k0 + 4]); }
#pragma unroll
      for (int n2=0;n2<8;n2++){
        float4 bv = bp[(kt*8 + n2)*32 + lane];
        mma8(acc[2*n2],   a0,a1,a2,a3, __float_as_uint(bv.x), __float_as_uint(bv.y));
        mma8(acc[2*n2+1], a0,a1,a2,a3, __float_as_uint(bv.z), __float_as_uint(bv.w));
      }
    }
    float p0=0.f, p1=0.f;
#pragma unroll
    for (int nt=0;nt<16;nt++){
      int j0 = nt*8 + 2*tig;
      float w0=w2i[j0], w1=w2i[j0+1], c0=civ[j0], c1=civ[j0+1];
      p0 += w0*fmaxf(c0+acc[nt][0],0.f) + w1*fmaxf(c1+acc[nt][1],0.f);
      p1 += w0*fmaxf(c0+acc[nt][2],0.f) + w1*fmaxf(c1+acc[nt][3],0.f);
    }
    p0 += __shfl_xor_sync(0xffffffffu,p0,1); p0 += __shfl_xor_sync(0xffffffffu,p0,2);
    p1 += __shfl_xor_sync(0xffffffffu,p1,1); p1 += __shfl_xor_sync(0xffffffffu,p1,2);
    if (tig==0){
      if (r0 < C_) sco[2][r0] = (p0 + bi2[0]) / Ti;
      if (r1 < C_) sco[2][r1] = (p1 + bi2[0]) / Ti;
    }
  }
  __syncthreads();

  if (warp == 0){
#pragma unroll
    for (int chn=0;chn<3;chn++){
      float m = -1e30f;
      for (int q=lane;q<C_;q+=32) m = fmaxf(m, sco[chn][q]);
      m = wmax(m);
      float s = 0.f;
      for (int q=lane;q<C_;q+=32) s += __expf(sco[chn][q]-m);
      s = wsum(s);
      if (lane==0){ mx3[chn]=m; inv3[chn]=1.f/s; }
    }
  }
  __syncthreads();
  const float a0=g_AL[b*3], a1=g_AL[b*3+1], a2=g_AL[b*3+2];
  if (tid < C_){
    float p = 0.01f
      + a0*__expf(sco[0][tid]-mx3[0])*inv3[0]
      + a1*__expf(sco[1][tid]-mx3[1])*inv3[1]
      + a2*__expf(sco[2][tid]-mx3[2])*inv3[2];
    mixv[tid] = p;
  }
  __syncthreads();
  if (warp == 0){
    float s = 0.f;
    for (int q=lane;q<C_;q+=32) s += mixv[q];
    s = wsum(s);
    if (lane==0) sS = 1.f/s;
  }
  __syncthreads();
  if (tid < C_) out[(long)b*C_ + tid] = mixv[tid]*sS;
}

extern "C" void kernel_launch(void* const* d_in, const int* in_sizes, int n_in,
                              void* d_out, int out_size) {
  const int*   sitems = (const int*)  d_in[0];
  const float* ide    = (const float*)d_in[1];
  const float* txe    = (const float*)d_in[2];
  const int*   lens   = (const int*)  d_in[3];
  const int*   cids   = (const int*)  d_in[4];
  const float* cide   = (const float*)d_in[5];
  const float* ctxe   = (const float*)d_in[6];
  const float* co     = (const float*)d_in[7];
  const float* Wih    = (const float*)d_in[8];
  const float* Whh    = (const float*)d_in[9];
  const float* bih    = (const float*)d_in[10];
  const float* bhh    = (const float*)d_in[11];
  const float* Wt1    = (const float*)d_in[12];
  const float* bt1    = (const float*)d_in[13];
  const float* Wt2    = (const float*)d_in[14];
  const float* bt2    = (const float*)d_in[15];
  const float* Wi1    = (const float*)d_in[16];
  const float* bi1    = (const float*)d_in[17];
  const float* Wi2    = (const float*)d_in[18];
  const float* bi2    = (const float*)d_in[19];
  const float* Wa1    = (const float*)d_in[20];
  const float* ba1    = (const float*)d_in[21];
  const float* Wa2    = (const float*)d_in[22];
  const float* ba2    = (const float*)d_in[23];
  // d_in[24] = Wstab: unused (P_stable is uniform = 1/C exactly)
  const float* betac  = (const float*)d_in[25];
  const float* lTc    = (const float*)d_in[26];
  const float* lTt    = (const float*)d_in[27];
  const float* lTi    = (const float*)d_in[28];
  float* out = (float*)d_out;

  cudaFuncSetAttribute(k_score, cudaFuncAttributeMaxDynamicSharedMemorySize, 98304);

  float* hb0; float* hb1;
  cudaGetSymbolAddress((void**)&hb0, g_HB);
  hb1 = hb0 + B_*128;

  k_wprep<<<(73728+49152+16384+8192+255)/256, 256>>>(Wih, Whh, Wt1, Wi1);
  k_ig<<<80, 256>>>(ide, txe, lens, bih);
  k_gru0<<<(B_*128+255)/256, 256>>>(bhh, hb0);
  k_step<<<64, 256>>>(1, hb0, hb1, bhh);
  k_step<<<64, 256>>>(2, hb1, hb0, bhh);
  k_step<<<64, 256>>>(3, hb0, hb1, bhh);
  k_step<<<64, 256>>>(4, hb1, hb0, bhh);
  k_prep<<<B_/16, 256>>>(ide, txe, lens, sitems, hb0,
                         Wt1, bt1, Wi1, bi1, Wa1, ba1, Wa2, ba2);
  k_score<<<B_, 256, 98304>>>(ctxe, cide, cids, co, Wt2, bt2, Wi2, bi2,
                              betac, lTc, lTt, lTi, out);
}

// round 6
// speedup vs baseline: 2.5371x; 1.2986x over previous
#include <cuda_runtime.h>
#include <math.h>

#define B_  2048
#define L_  200
#define C_  100
#define V_  2000

// ---------------- scratch ----------------
__device__ float g_IG  [B_*5*384];
__device__ float g_Hfin[B_*128];
__device__ float g_CT  [B_*128];
__device__ float g_CI  [B_*128];
__device__ float g_AL  [B_*3];
__device__ float g_WT  [16384];        // Wt1 mid slab (N=128,K=128) frag order
__device__ float g_WI  [8192];         // Wi1 mid slab (N=128,K=64)  frag order
__device__ float g_WIHf[73728];        // W_ih (N=384,K=192) frag order
__device__ float g_WHHf[49152];        // W_hh (N=384,K=128) frag order
__device__ int   g_LI  [B_];

__device__ __forceinline__ float sigf(float x){ return 1.0f/(1.0f+__expf(-x)); }
__device__ __forceinline__ float tanhf_fast(float x){
  x = fminf(fmaxf(x,-15.f),15.f);
  float e = __expf(2.f*x);
  return (e-1.f)/(e+1.f);
}
__device__ __forceinline__ float wsum(float v){
#pragma unroll
  for (int o=16;o;o>>=1) v += __shfl_xor_sync(0xffffffffu, v, o);
  return v;
}
__device__ __forceinline__ float wmax(float v){
#pragma unroll
  for (int o=16;o;o>>=1) v = fmaxf(v, __shfl_xor_sync(0xffffffffu, v, o));
  return v;
}
__device__ __forceinline__ unsigned f2tf(float x){
  unsigned r; asm("cvt.rna.tf32.f32 %0, %1;" : "=r"(r) : "f"(x)); return r;
}
__device__ __forceinline__ void mma8(float* d,
    unsigned a0, unsigned a1, unsigned a2, unsigned a3,
    unsigned b0, unsigned b1){
  asm volatile(
    "mma.sync.aligned.m16n8k8.row.col.f32.tf32.tf32.f32 "
    "{%0,%1,%2,%3},{%4,%5,%6,%7},{%8,%9},{%0,%1,%2,%3};\n"
    : "+f"(d[0]),"+f"(d[1]),"+f"(d[2]),"+f"(d[3])
    : "r"(a0),"r"(a1),"r"(a2),"r"(a3),"r"(b0),"r"(b1));
}

// decode fragment-order flat index -> (j,k) for weight W[N][K]
__device__ __forceinline__ void frag_jk(int idx, int N, int* jj, int* kk){
  int c = idx & 3, lane = (idx>>2)&31;
  int P = N >> 4;
  int pr = (idx>>7) % P;
  int kt = idx / (128*P);
  int nt = 2*pr + (c>>1), p = c&1;
  *jj = nt*8 + (lane>>2);
  *kk = kt*8 + (lane&3) + 4*p;
}

// ---- prepare all fragment-ordered weights (tf32-rounded) ----
__global__ void k_wprep(const float* __restrict__ Wih, const float* __restrict__ Whh,
                        const float* __restrict__ Wt1, const float* __restrict__ Wi1){
  int idx = blockIdx.x*blockDim.x + threadIdx.x;
  int j, k;
  if (idx < 73728){                     // Wih: N=384, K=192
    frag_jk(idx, 384, &j, &k);
    g_WIHf[idx] = __uint_as_float(f2tf(Wih[(long)j*192 + k]));
  } else if (idx < 73728+49152){        // Whh: N=384, K=128
    int i2 = idx - 73728;
    frag_jk(i2, 384, &j, &k);
    g_WHHf[i2] = __uint_as_float(f2tf(Whh[(long)j*128 + k]));
  } else if (idx < 73728+49152+16384){  // Wt1 mid: N=128, K=128
    int i2 = idx - 73728 - 49152;
    frag_jk(i2, 128, &j, &k);
    g_WT[i2] = __uint_as_float(f2tf(Wt1[(long)j*384 + 128 + k]));
  } else if (idx < 73728+49152+16384+8192){ // Wi1 mid: N=128, K=64
    int i2 = idx - 73728 - 49152 - 16384;
    frag_jk(i2, 128, &j, &k);
    g_WI[i2] = __uint_as_float(f2tf(Wi1[(long)j*256 + 64 + k]));
  }
}

// ---- input-gate GEMM (tf32): IG[m][n] = x_m · Wih[n] + bih[n] ----
__global__ __launch_bounds__(256) void k_ig(
    const float* __restrict__ ide, const float* __restrict__ txe,
    const int* __restrict__ lens, const float* __restrict__ bih)
{
  __shared__ float sB[384];
  const int tid = threadIdx.x, warp = tid>>5, lane = tid&31;
  const int g = lane>>2, tig = lane&3;
  for (int i=tid; i<384; i+=256) sB[i] = bih[i];
  const int r0 = blockIdx.x*128 + warp*16 + g;
  const int r1 = r0 + 8;
  int b0 = r0/5, t0 = r0 - 5*b0;  int p0 = lens[b0] - 5 + t0;
  int b1 = r1/5, t1 = r1 - 5*b1;  int p1 = lens[b1] - 5 + t1;
  const float* id0 = ide + ((long)b0*L_ + p0)*64;
  const float* tx0 = txe + ((long)b0*L_ + p0)*128;
  const float* id1 = ide + ((long)b1*L_ + p1)*64;
  const float* tx1 = txe + ((long)b1*L_ + p1)*128;
  __syncthreads();

  const float4* bp = (const float4*)g_WIHf;
  for (int ch=0; ch<3; ch++){
    float acc[16][4];
#pragma unroll
    for (int nt=0;nt<16;nt++){ acc[nt][0]=0.f;acc[nt][1]=0.f;acc[nt][2]=0.f;acc[nt][3]=0.f; }
#pragma unroll
    for (int kt=0;kt<24;kt++){
      int k0 = kt*8 + tig, k4 = k0+4;
      unsigned a0 = f2tf(k0<64 ? id0[k0] : tx0[k0-64]);
      unsigned a2 = f2tf(k4<64 ? id0[k4] : tx0[k4-64]);
      unsigned a1 = f2tf(k0<64 ? id1[k0] : tx1[k0-64]);
      unsigned a3 = f2tf(k4<64 ? id1[k4] : tx1[k4-64]);
#pragma unroll
      for (int n2=0;n2<8;n2++){
        float4 bv = bp[(kt*24 + ch*8 + n2)*32 + lane];
        mma8(acc[2*n2],   a0,a1,a2,a3, __float_as_uint(bv.x), __float_as_uint(bv.y));
        mma8(acc[2*n2+1], a0,a1,a2,a3, __float_as_uint(bv.z), __float_as_uint(bv.w));
      }
    }
#pragma unroll
    for (int nt=0;nt<16;nt++){
      int j = ch*128 + nt*8 + 2*tig;
      float* o0 = g_IG + (long)r0*384 + j;
      float* o1 = g_IG + (long)r1*384 + j;
      o0[0] = acc[nt][0]+sB[j]; o0[1] = acc[nt][1]+sB[j+1];
      o1[0] = acc[nt][2]+sB[j]; o1[1] = acc[nt][3]+sB[j+1];
    }
  }
}

// ---- persistent fused GRU: all 5 steps in one kernel ----
// grid=128, block=256 (8 warps). 16 batches per block.
// smem: W_hh frag (49152 f) + h (2048 f) + bias (384 f) = 206336 B.
// warp w owns j-columns [16w,16w+16) for all 3 gates (pr = gate*8 + w).
__global__ __launch_bounds__(256) void k_gruall(const float* __restrict__ bhh){
  extern __shared__ float sm[];
  float* sW = sm;               // 49152
  float* sH = sm + 49152;       // 2048: sH[row*128+k], row=batch-in-block
  float* sB = sm + 49152+2048;  // 384
  const int tid = threadIdx.x, warp = tid>>5, lane = tid&31;
  const int g = lane>>2, tig = lane&3;
  const int b0 = blockIdx.x*16;

  {
    const float4* gw = (const float4*)g_WHHf;
    float4* swv = (float4*)sW;
    for (int i=tid;i<12288;i+=256) swv[i] = gw[i];
  }
  for (int i=tid;i<384;i+=256) sB[i] = bhh[i];
  __syncthreads();

  // step 0: h = (1-z)*n with recurrent gates = bhh
  for (int i=tid;i<2048;i+=256){
    int bb = i>>7, j = i&127;
    const float* ig = g_IG + ((long)(b0+bb)*5)*384;
    float r = sigf(ig[j]       + sB[j]);
    float z = sigf(ig[128+j]   + sB[128+j]);
    float n = tanhf_fast(ig[256+j] + r*sB[256+j]);
    sH[i] = (1.f - z)*n;
  }
  __syncthreads();

  const float4* swv4 = (const float4*)sW;
  for (int t=1;t<5;t++){
    float acc[3][2][4];
#pragma unroll
    for (int gate=0;gate<3;gate++)
#pragma unroll
      for (int s=0;s<2;s++){ acc[gate][s][0]=0.f;acc[gate][s][1]=0.f;acc[gate][s][2]=0.f;acc[gate][s][3]=0.f; }
#pragma unroll
    for (int kt=0;kt<16;kt++){
      int k0 = kt*8 + tig;
      unsigned a0 = f2tf(sH[g*128     + k0]);
      unsigned a1 = f2tf(sH[(g+8)*128 + k0]);
      unsigned a2 = f2tf(sH[g*128     + k0+4]);
      unsigned a3 = f2tf(sH[(g+8)*128 + k0+4]);
#pragma unroll
      for (int gate=0;gate<3;gate++){
        int pr = gate*8 + warp;
        float4 bv = swv4[(kt*24 + pr)*32 + lane];
        mma8(acc[gate][0], a0,a1,a2,a3, __float_as_uint(bv.x), __float_as_uint(bv.y));
        mma8(acc[gate][1], a0,a1,a2,a3, __float_as_uint(bv.z), __float_as_uint(bv.w));
      }
    }
    __syncthreads();   // all A-fragment reads of sH complete before updates
    const float* ig0 = g_IG + (((long)(b0+g))*5   + t)*384;
    const float* ig1 = g_IG + (((long)(b0+g+8))*5 + t)*384;
#pragma unroll
    for (int s=0;s<2;s++){
#pragma unroll
      for (int cc=0;cc<2;cc++){
        int j = warp*16 + s*8 + tig*2 + cc;
        { // row g
          float r = sigf(ig0[j]       + acc[0][s][cc] + sB[j]);
          float z = sigf(ig0[128+j]   + acc[1][s][cc] + sB[128+j]);
          float n = tanhf_fast(ig0[256+j] + r*(acc[2][s][cc] + sB[256+j]));
          float hp = sH[g*128 + j];
          sH[g*128 + j] = (1.f-z)*n + z*hp;
        }
        { // row g+8
          float r = sigf(ig1[j]       + acc[0][s][cc+2] + sB[j]);
          float z = sigf(ig1[128+j]   + acc[1][s][cc+2] + sB[128+j]);
          float n = tanhf_fast(ig1[256+j] + r*(acc[2][s][cc+2] + sB[256+j]));
          float hp = sH[(g+8)*128 + j];
          sH[(g+8)*128 + j] = (1.f-z)*n + z*hp;
        }
      }
    }
    __syncthreads();
  }
  for (int i=tid;i<2048;i+=256)
    g_Hfin[(long)(b0 + (i>>7))*128 + (i&127)] = sH[i];
}

// ---- per-batch constants: ct, ci, alpha, last item; 16 batches, 256 thr ----
__global__ __launch_bounds__(256) void k_prep(
    const float* __restrict__ ide, const float* __restrict__ txe,
    const int* __restrict__ lens, const int* __restrict__ sitems,
    const float* __restrict__ Wt1, const float* __restrict__ bt1,
    const float* __restrict__ Wi1, const float* __restrict__ bi1,
    const float* __restrict__ Wa1, const float* __restrict__ ba1,
    const float* __restrict__ Wa2, const float* __restrict__ ba2)
{
  __shared__ float lt[16][128], hh[16][128], lid[16][64], a1s[16][64], lg[16][3];
  __shared__ float sP[16][128];
  __shared__ int Ls[16];
  const int tid = threadIdx.x;
  const int b0 = blockIdx.x * 16;
  if (tid < 16) Ls[tid] = lens[b0+tid];
  __syncthreads();
  for (int i=tid;i<2048;i+=256){
    int bb=i>>7, k=i&127; int pos = Ls[bb]-1;
    lt[bb][k] = txe[((long)(b0+bb)*L_ + pos)*128 + k];
    hh[bb][k] = g_Hfin[(long)(b0+bb)*128 + k];
  }
  for (int i=tid;i<1024;i+=256){
    int bb=i>>6, k=i&63;
    lid[bb][k] = ide[((long)(b0+bb)*L_ + Ls[bb]-1)*64 + k];
  }
  if (tid < 16) g_LI[b0+tid] = sitems[(long)(b0+tid)*L_ + Ls[tid]-1];
  __syncthreads();

  const int j = tid & 127, half = tid >> 7;
  { // ct: split k-range between halves
    float acc[16];
#pragma unroll
    for (int bb=0;bb<16;bb++) acc[bb] = 0.f;
    const float* w1 = Wt1 + (long)j*384;
    const float* w3 = w1 + 256;
    int kb = half*64;
    for (int k=kb;k<kb+64;k++){
      float ws = w1[k], wh = w3[k];
#pragma unroll
      for (int bb=0;bb<16;bb++) acc[bb] += ws*lt[bb][k] + wh*hh[bb][k];
    }
    if (half==1){ for (int bb=0;bb<16;bb++) sP[bb][j] = acc[bb]; }
    __syncthreads();
    if (half==0){
      float bv = bt1[j];
      for (int bb=0;bb<16;bb++) g_CT[(b0+bb)*128 + j] = acc[bb] + sP[bb][j] + bv;
    }
    __syncthreads();
  }
  { // ci
    float acc[16];
#pragma unroll
    for (int bb=0;bb<16;bb++) acc[bb] = 0.f;
    const float* w1 = Wi1 + (long)j*256;
    const float* w3 = w1 + 128;
    if (half==0){
      for (int k=0;k<64;k++){
        float ws = w1[k];
#pragma unroll
        for (int bb=0;bb<16;bb++) acc[bb] += ws*lid[bb][k];
      }
      for (int k=0;k<32;k++){
        float wh = w3[k];
#pragma unroll
        for (int bb=0;bb<16;bb++) acc[bb] += wh*hh[bb][k];
      }
    } else {
      for (int k=32;k<128;k++){
        float wh = w3[k];
#pragma unroll
        for (int bb=0;bb<16;bb++) acc[bb] += wh*hh[bb][k];
      }
      for (int bb=0;bb<16;bb++) sP[bb][j] = acc[bb];
    }
    __syncthreads();
    if (half==0){
      float bv = bi1[j];
      for (int bb=0;bb<16;bb++) g_CI[(b0+bb)*128 + j] = acc[bb] + sP[bb][j] + bv;
    }
    __syncthreads();
  }
  { // alpha hidden
    const int u = tid & 63, h2 = tid >> 6;
    float acc[16];
#pragma unroll
    for (int bb=0;bb<16;bb++) acc[bb] = 0.f;
    if (h2 < 2){
      const float* w = Wa1 + (long)u*128;
      int kb = h2*64;
      for (int k=kb;k<kb+64;k++){
        float wv = w[k];
#pragma unroll
        for (int bb=0;bb<16;bb++) acc[bb] += wv*hh[bb][k];
      }
      if (h2==1){ for (int bb=0;bb<16;bb++) sP[bb][u] = acc[bb]; }
    }
    __syncthreads();
    if (h2==0){
      float bv = ba1[u];
      for (int bb=0;bb<16;bb++) a1s[bb][u] = fmaxf(acc[bb] + sP[bb][u] + bv, 0.f);
    }
    __syncthreads();
  }
  if (tid < 48){
    int bb = tid/3, gg = tid%3;
    float s = ba2[gg];
    const float* w = Wa2 + gg*64;
    for (int u=0;u<64;u++) s += w[u]*a1s[bb][u];
    lg[bb][gg] = s;
  }
  __syncthreads();
  if (tid < 16){
    float l0=lg[tid][0], l1=lg[tid][1], l2=lg[tid][2];
    float m = fmaxf(l0, fmaxf(l1,l2));
    float e0=__expf(l0-m), e1=__expf(l1-m), e2=__expf(l2-m);
    float inv = 1.f/(e0+e1+e2);
    g_AL[(b0+tid)*3+0]=e0*inv; g_AL[(b0+tid)*3+1]=e1*inv; g_AL[(b0+tid)*3+2]=e2*inv;
  }
}

// ---- fused scorer (tf32) + softmaxes + mix: one block per batch ----
// weights read straight from L2-resident fragment buffers (no smem staging)
__global__ __launch_bounds__(256) void k_score(
    const float* __restrict__ ctxe, const float* __restrict__ cide,
    const int* __restrict__ cids, const float* __restrict__ co,
    const float* __restrict__ Wt2, const float* __restrict__ bt2,
    const float* __restrict__ Wi2, const float* __restrict__ bi2,
    const float* __restrict__ betac, const float* __restrict__ lTc,
    const float* __restrict__ lTt, const float* __restrict__ lTi,
    float* __restrict__ out)
{
  __shared__ float ctv[128], civ[128], w2t[128], w2i[128];
  __shared__ float sco[3][128];
  __shared__ float mx3[3], inv3[3], sS;
  __shared__ float mixv[128];
  const int b = blockIdx.x, tid = threadIdx.x;
  const int warp = tid>>5, lane = tid&31;
  const int g = lane>>2, tig = lane&3;
  const int r0 = warp*16 + g, r1 = r0 + 8;

  if (tid < 128){
    ctv[tid]=g_CT[b*128+tid]; civ[tid]=g_CI[b*128+tid];
    w2t[tid]=Wt2[tid];        w2i[tid]=Wi2[tid];
  }
  if (tid < 100){
    long li = g_LI[b];
    sco[0][tid] = co[li*V_ + cids[(long)b*C_+tid]] * betac[0] / expf(lTc[0]);
  }
  const float Tt = expf(lTt[0]), Ti = expf(lTi[0]);
  __syncthreads();

  // text pass: M=128(pad 100) x N=128 x K=128
  {
    float acc[16][4];
#pragma unroll
    for (int nt=0;nt<16;nt++){ acc[nt][0]=0.f;acc[nt][1]=0.f;acc[nt][2]=0.f;acc[nt][3]=0.f; }
    const float* Eb = ctxe + (long)b*C_*128;
    const float4* bp = (const float4*)g_WT;
#pragma unroll
    for (int kt=0;kt<16;kt++){
      const int k0 = kt*8 + tig;
      unsigned a0=0u,a1=0u,a2=0u,a3=0u;
      if (r0 < C_){ a0 = f2tf(Eb[(long)r0*128 + k0]); a2 = f2tf(Eb[(long)r0*128 + k0 + 4]); }
      if (r1 < C_){ a1 = f2tf(Eb[(long)r1*128 + k0]); a3 = f2tf(Eb[(long)r1*128 + k0 + 4]); }
#pragma unroll
      for (int n2=0;n2<8;n2++){
        float4 bv = bp[(kt*8 + n2)*32 + lane];
        mma8(acc[2*n2],   a0,a1,a2,a3, __float_as_uint(bv.x), __float_as_uint(bv.y));
        mma8(acc[2*n2+1], a0,a1,a2,a3, __float_as_uint(bv.z), __float_as_uint(bv.w));
      }
    }
    float p0=0.f, p1=0.f;
#pragma unroll
    for (int nt=0;nt<16;nt++){
      int j0 = nt*8 + 2*tig;
      float w0=w2t[j0], w1=w2t[j0+1], c0=ctv[j0], c1=ctv[j0+1];
      p0 += w0*fmaxf(c0+acc[nt][0],0.f) + w1*fmaxf(c1+acc[nt][1],0.f);
      p1 += w0*fmaxf(c0+acc[nt][2],0.f) + w1*fmaxf(c1+acc[nt][3],0.f);
    }
    p0 += __shfl_xor_sync(0xffffffffu,p0,1); p0 += __shfl_xor_sync(0xffffffffu,p0,2);
    p1 += __shfl_xor_sync(0xffffffffu,p1,1); p1 += __shfl_xor_sync(0xffffffffu,p1,2);
    if (tig==0){
      if (r0 < C_) sco[1][r0] = (p0 + bt2[0]) / Tt;
      if (r1 < C_) sco[1][r1] = (p1 + bt2[0]) / Tt;
    }
  }
  // id pass: K=64
  {
    float acc[16][4];
#pragma unroll
    for (int nt=0;nt<16;nt++){ acc[nt][0]=0.f;acc[nt][1]=0.f;acc[nt][2]=0.f;acc[nt][3]=0.f; }
    const float* Eb = cide + (long)b*C_*64;
    const float4* bp = (const float4*)g_WI;
#pragma unroll
    for (int kt=0;kt<8;kt++){
      const int k0 = kt*8 + tig;
      unsigned a0=0u,a1=0u,a2=0u,a3=0u;
      if (r0 < C_){ a0 = f2tf(Eb[(long)r0*64 + k0]); a2 = f2tf(Eb[(long)r0*64 + k0 + 4]); }
      if (r1 < C_){ a1 = f2tf(Eb[(long)r1*64 + k0]); a3 = f2tf(Eb[(long)r1*64 + k0 + 4]); }
#pragma unroll
      for (int n2=0;n2<8;n2++){
        float4 bv = bp[(kt*8 + n2)*32 + lane];
        mma8(acc[2*n2],   a0,a1,a2,a3, __float_as_uint(bv.x), __float_as_uint(bv.y));
        mma8(acc[2*n2+1], a0,a1,a2,a3, __float_as_uint(bv.z), __float_as_uint(bv.w));
      }
    }
    float p0=0.f, p1=0.f;
#pragma unroll
    for (int nt=0;nt<16;nt++){
      int j0 = nt*8 + 2*tig;
      float w0=w2i[j0], w1=w2i[j0+1], c0=civ[j0], c1=civ[j0+1];
      p0 += w0*fmaxf(c0+acc[nt][0],0.f) + w1*fmaxf(c1+acc[nt][1],0.f);
      p1 += w0*fmaxf(c0+acc[nt][2],0.f) + w1*fmaxf(c1+acc[nt][3],0.f);
    }
    p0 += __shfl_xor_sync(0xffffffffu,p0,1); p0 += __shfl_xor_sync(0xffffffffu,p0,2);
    p1 += __shfl_xor_sync(0xffffffffu,p1,1); p1 += __shfl_xor_sync(0xffffffffu,p1,2);
    if (tig==0){
      if (r0 < C_) sco[2][r0] = (p0 + bi2[0]) / Ti;
      if (r1 < C_) sco[2][r1] = (p1 + bi2[0]) / Ti;
    }
  }
  __syncthreads();

  if (warp == 0){
#pragma unroll
    for (int chn=0;chn<3;chn++){
      float m = -1e30f;
      for (int q=lane;q<C_;q+=32) m = fmaxf(m, sco[chn][q]);
      m = wmax(m);
      float s = 0.f;
      for (int q=lane;q<C_;q+=32) s += __expf(sco[chn][q]-m);
      s = wsum(s);
      if (lane==0){ mx3[chn]=m; inv3[chn]=1.f/s; }
    }
  }
  __syncthreads();
  const float a0=g_AL[b*3], a1=g_AL[b*3+1], a2=g_AL[b*3+2];
  if (tid < C_){
    float p = 0.01f
      + a0*__expf(sco[0][tid]-mx3[0])*inv3[0]
      + a1*__expf(sco[1][tid]-mx3[1])*inv3[1]
      + a2*__expf(sco[2][tid]-mx3[2])*inv3[2];
    mixv[tid] = p;
  }
  __syncthreads();
  if (warp == 0){
    float s = 0.f;
    for (int q=lane;q<C_;q+=32) s += mixv[q];
    s = wsum(s);
    if (lane==0) sS = 1.f/s;
  }
  __syncthreads();
  if (tid < C_) out[(long)b*C_ + tid] = mixv[tid]*sS;
}

extern "C" void kernel_launch(void* const* d_in, const int* in_sizes, int n_in,
                              void* d_out, int out_size) {
  const int*   sitems = (const int*)  d_in[0];
  const float* ide    = (const float*)d_in[1];
  const float* txe    = (const float*)d_in[2];
  const int*   lens   = (const int*)  d_in[3];
  const int*   cids   = (const int*)  d_in[4];
  const float* cide   = (const float*)d_in[5];
  const float* ctxe   = (const float*)d_in[6];
  const float* co     = (const float*)d_in[7];
  const float* Wih    = (const float*)d_in[8];
  const float* Whh    = (const float*)d_in[9];
  const float* bih    = (const float*)d_in[10];
  const float* bhh    = (const float*)d_in[11];
  const float* Wt1    = (const float*)d_in[12];
  const float* bt1    = (const float*)d_in[13];
  const float* Wt2    = (const float*)d_in[14];
  const float* bt2    = (const float*)d_in[15];
  const float* Wi1    = (const float*)d_in[16];
  const float* bi1    = (const float*)d_in[17];
  const float* Wi2    = (const float*)d_in[18];
  const float* bi2    = (const float*)d_in[19];
  const float* Wa1    = (const float*)d_in[20];
  const float* ba1    = (const float*)d_in[21];
  const float* Wa2    = (const float*)d_in[22];
  const float* ba2    = (const float*)d_in[23];
  // d_in[24] = Wstab: unused (P_stable is uniform = 1/C exactly)
  const float* betac  = (const float*)d_in[25];
  const float* lTc    = (const float*)d_in[26];
  const float* lTt    = (const float*)d_in[27];
  const float* lTi    = (const float*)d_in[28];
  float* out = (float*)d_out;

  const int GRU_SMEM = (49152 + 2048 + 384) * 4;   // 206336 B
  cudaFuncSetAttribute(k_gruall, cudaFuncAttributeMaxDynamicSharedMemorySize, GRU_SMEM);

  k_wprep<<<(73728+49152+16384+8192+255)/256, 256>>>(Wih, Whh, Wt1, Wi1);
  k_ig<<<80, 256>>>(ide, txe, lens, bih);
  k_gruall<<<128, 256, GRU_SMEM>>>(bhh);
  k_prep<<<B_/16, 256>>>(ide, txe, lens, sitems,
                         Wt1, bt1, Wi1, bi1, Wa1, ba1, Wa2, ba2);
  k_score<<<B_, 256>>>(ctxe, cide, cids, co, Wt2, bt2, Wi2, bi2,
                       betac, lTc, lTt, lTi, out);
}

// round 7
// speedup vs baseline: 2.8395x; 1.1192x over previous
#include <cuda_runtime.h>
#include <math.h>

#define B_  2048
#define L_  200
#define C_  100
#define V_  2000

// ---------------- scratch ----------------
__device__ float g_IG  [B_*5*384];
__device__ float g_Hfin[B_*128];
__device__ float g_CT  [B_*128];
__device__ float g_CI  [B_*128];
__device__ float g_AL  [B_*3];
__device__ float g_WT  [16384];        // Wt1 mid slab (N=128,K=128) frag order
__device__ float g_WI  [8192];         // Wi1 mid slab (N=128,K=64)  frag order
__device__ float g_WIHf[73728];        // W_ih (N=384,K=192) frag order
__device__ float g_WHHf[49152];        // W_hh (N=384,K=128) frag order
__device__ float g_WCT [32768];        // [Wt1 src | Wt1 h]  (N=128,K=256) frag
__device__ float g_WCI [24576];        // [Wi1 src | Wi1 h]  (N=128,K=192) frag
__device__ float g_WA  [8192];         // Wa1 (N=64,K=128) frag
__device__ int   g_LI  [B_];

__device__ __forceinline__ float sigf(float x){ return 1.0f/(1.0f+__expf(-x)); }
__device__ __forceinline__ float tanhf_fast(float x){
  x = fminf(fmaxf(x,-15.f),15.f);
  float e = __expf(2.f*x);
  return (e-1.f)/(e+1.f);
}
__device__ __forceinline__ float wsum(float v){
#pragma unroll
  for (int o=16;o;o>>=1) v += __shfl_xor_sync(0xffffffffu, v, o);
  return v;
}
__device__ __forceinline__ float wmax(float v){
#pragma unroll
  for (int o=16;o;o>>=1) v = fmaxf(v, __shfl_xor_sync(0xffffffffu, v, o));
  return v;
}
__device__ __forceinline__ unsigned f2tf(float x){
  unsigned r; asm("cvt.rna.tf32.f32 %0, %1;" : "=r"(r) : "f"(x)); return r;
}
__device__ __forceinline__ void mma8(float* d,
    unsigned a0, unsigned a1, unsigned a2, unsigned a3,
    unsigned b0, unsigned b1){
  asm volatile(
    "mma.sync.aligned.m16n8k8.row.col.f32.tf32.tf32.f32 "
    "{%0,%1,%2,%3},{%4,%5,%6,%7},{%8,%9},{%0,%1,%2,%3};\n"
    : "+f"(d[0]),"+f"(d[1]),"+f"(d[2]),"+f"(d[3])
    : "r"(a0),"r"(a1),"r"(a2),"r"(a3),"r"(b0),"r"(b1));
}

// decode fragment-order flat index -> (j,k) for weight W[N][K]
__device__ __forceinline__ void frag_jk(int idx, int N, int* jj, int* kk){
  int c = idx & 3, lane = (idx>>2)&31;
  int P = N >> 4;
  int pr = (idx>>7) % P;
  int kt = idx / (128*P);
  int nt = 2*pr + (c>>1), p = c&1;
  *jj = nt*8 + (lane>>2);
  *kk = kt*8 + (lane&3) + 4*p;
}

// ---- prepare all fragment-ordered weights (tf32-rounded) ----
__global__ void k_wprep(const float* __restrict__ Wih, const float* __restrict__ Whh,
                        const float* __restrict__ Wt1, const float* __restrict__ Wi1,
                        const float* __restrict__ Wa1){
  int idx = blockIdx.x*blockDim.x + threadIdx.x;
  int j, k;
  int off = 0;
  if (idx < (off += 73728)){                       // Wih: N=384,K=192
    frag_jk(idx, 384, &j, &k);
    g_WIHf[idx] = __uint_as_float(f2tf(Wih[(long)j*192 + k]));
    return;
  }
  if (idx < (off + 49152)){                        // Whh: N=384,K=128
    int i2 = idx - off;
    frag_jk(i2, 384, &j, &k);
    g_WHHf[i2] = __uint_as_float(f2tf(Whh[(long)j*128 + k]));
    return;
  }
  off += 49152;
  if (idx < (off + 16384)){                        // Wt1 mid: N=128,K=128
    int i2 = idx - off;
    frag_jk(i2, 128, &j, &k);
    g_WT[i2] = __uint_as_float(f2tf(Wt1[(long)j*384 + 128 + k]));
    return;
  }
  off += 16384;
  if (idx < (off + 8192)){                         // Wi1 mid: N=128,K=64
    int i2 = idx - off;
    frag_jk(i2, 128, &j, &k);
    g_WI[i2] = __uint_as_float(f2tf(Wi1[(long)j*256 + 64 + k]));
    return;
  }
  off += 8192;
  if (idx < (off + 32768)){                        // WCT: N=128,K=256
    int i2 = idx - off;
    frag_jk(i2, 128, &j, &k);
    float v = (k < 128) ? Wt1[(long)j*384 + k] : Wt1[(long)j*384 + 256 + (k-128)];
    g_WCT[i2] = __uint_as_float(f2tf(v));
    return;
  }
  off += 32768;
  if (idx < (off + 24576)){                        // WCI: N=128,K=192
    int i2 = idx - off;
    frag_jk(i2, 128, &j, &k);
    float v = (k < 64) ? Wi1[(long)j*256 + k] : Wi1[(long)j*256 + 128 + (k-64)];
    g_WCI[i2] = __uint_as_float(f2tf(v));
    return;
  }
  off += 24576;
  if (idx < (off + 8192)){                         // WA: N=64,K=128
    int i2 = idx - off;
    frag_jk(i2, 64, &j, &k);
    g_WA[i2] = __uint_as_float(f2tf(Wa1[(long)j*128 + k]));
    return;
  }
}

// ---- input-gate GEMM (tf32): IG[m][n] = x_m · Wih[n] + bih[n] ----
__global__ __launch_bounds__(256) void k_ig(
    const float* __restrict__ ide, const float* __restrict__ txe,
    const int* __restrict__ lens, const float* __restrict__ bih)
{
  __shared__ float sB[384];
  const int tid = threadIdx.x, warp = tid>>5, lane = tid&31;
  const int g = lane>>2, tig = lane&3;
  for (int i=tid; i<384; i+=256) sB[i] = bih[i];
  const int r0 = blockIdx.x*128 + warp*16 + g;
  const int r1 = r0 + 8;
  int b0 = r0/5, t0 = r0 - 5*b0;  int p0 = lens[b0] - 5 + t0;
  int b1 = r1/5, t1 = r1 - 5*b1;  int p1 = lens[b1] - 5 + t1;
  const float* id0 = ide + ((long)b0*L_ + p0)*64;
  const float* tx0 = txe + ((long)b0*L_ + p0)*128;
  const float* id1 = ide + ((long)b1*L_ + p1)*64;
  const float* tx1 = txe + ((long)b1*L_ + p1)*128;
  __syncthreads();

  const float4* bp = (const float4*)g_WIHf;
  for (int ch=0; ch<3; ch++){
    float acc[16][4];
#pragma unroll
    for (int nt=0;nt<16;nt++){ acc[nt][0]=0.f;acc[nt][1]=0.f;acc[nt][2]=0.f;acc[nt][3]=0.f; }
#pragma unroll
    for (int kt=0;kt<24;kt++){
      int k0 = kt*8 + tig, k4 = k0+4;
      unsigned a0 = f2tf(k0<64 ? id0[k0] : tx0[k0-64]);
      unsigned a2 = f2tf(k4<64 ? id0[k4] : tx0[k4-64]);
      unsigned a1 = f2tf(k0<64 ? id1[k0] : tx1[k0-64]);
      unsigned a3 = f2tf(k4<64 ? id1[k4] : tx1[k4-64]);
#pragma unroll
      for (int n2=0;n2<8;n2++){
        float4 bv = bp[(kt*24 + ch*8 + n2)*32 + lane];
        mma8(acc[2*n2],   a0,a1,a2,a3, __float_as_uint(bv.x), __float_as_uint(bv.y));
        mma8(acc[2*n2+1], a0,a1,a2,a3, __float_as_uint(bv.z), __float_as_uint(bv.w));
      }
    }
#pragma unroll
    for (int nt=0;nt<16;nt++){
      int j = ch*128 + nt*8 + 2*tig;
      float* o0 = g_IG + (long)r0*384 + j;
      float* o1 = g_IG + (long)r1*384 + j;
      o0[0] = acc[nt][0]+sB[j]; o0[1] = acc[nt][1]+sB[j+1];
      o1[0] = acc[nt][2]+sB[j]; o1[1] = acc[nt][3]+sB[j+1];
    }
  }
}

// ---- persistent fused GRU: all 5 steps in one kernel ----
__global__ __launch_bounds__(256) void k_gruall(const float* __restrict__ bhh){
  extern __shared__ float sm[];
  float* sW = sm;               // 49152
  float* sH = sm + 49152;       // 2048
  float* sB = sm + 49152+2048;  // 384
  const int tid = threadIdx.x, warp = tid>>5, lane = tid&31;
  const int g = lane>>2, tig = lane&3;
  const int b0 = blockIdx.x*16;

  {
    const float4* gw = (const float4*)g_WHHf;
    float4* swv = (float4*)sW;
    for (int i=tid;i<12288;i+=256) swv[i] = gw[i];
  }
  for (int i=tid;i<384;i+=256) sB[i] = bhh[i];
  __syncthreads();

  for (int i=tid;i<2048;i+=256){
    int bb = i>>7, j = i&127;
    const float* ig = g_IG + ((long)(b0+bb)*5)*384;
    float r = sigf(ig[j]       + sB[j]);
    float z = sigf(ig[128+j]   + sB[128+j]);
    float n = tanhf_fast(ig[256+j] + r*sB[256+j]);
    sH[i] = (1.f - z)*n;
  }
  __syncthreads();

  const float4* swv4 = (const float4*)sW;
  for (int t=1;t<5;t++){
    float acc[3][2][4];
#pragma unroll
    for (int gate=0;gate<3;gate++)
#pragma unroll
      for (int s=0;s<2;s++){ acc[gate][s][0]=0.f;acc[gate][s][1]=0.f;acc[gate][s][2]=0.f;acc[gate][s][3]=0.f; }
#pragma unroll
    for (int kt=0;kt<16;kt++){
      int k0 = kt*8 + tig;
      unsigned a0 = f2tf(sH[g*128     + k0]);
      unsigned a1 = f2tf(sH[(g+8)*128 + k0]);
      unsigned a2 = f2tf(sH[g*128     + k0+4]);
      unsigned a3 = f2tf(sH[(g+8)*128 + k0+4]);
#pragma unroll
      for (int gate=0;gate<3;gate++){
        int pr = gate*8 + warp;
        float4 bv = swv4[(kt*24 + pr)*32 + lane];
        mma8(acc[gate][0], a0,a1,a2,a3, __float_as_uint(bv.x), __float_as_uint(bv.y));
        mma8(acc[gate][1], a0,a1,a2,a3, __float_as_uint(bv.z), __float_as_uint(bv.w));
      }
    }
    __syncthreads();
    const float* ig0 = g_IG + (((long)(b0+g))*5   + t)*384;
    const float* ig1 = g_IG + (((long)(b0+g+8))*5 + t)*384;
#pragma unroll
    for (int s=0;s<2;s++){
#pragma unroll
      for (int cc=0;cc<2;cc++){
        int j = warp*16 + s*8 + tig*2 + cc;
        {
          float r = sigf(ig0[j]       + acc[0][s][cc] + sB[j]);
          float z = sigf(ig0[128+j]   + acc[1][s][cc] + sB[128+j]);
          float n = tanhf_fast(ig0[256+j] + r*(acc[2][s][cc] + sB[256+j]));
          float hp = sH[g*128 + j];
          sH[g*128 + j] = (1.f-z)*n + z*hp;
        }
        {
          float r = sigf(ig1[j]       + acc[0][s][cc+2] + sB[j]);
          float z = sigf(ig1[128+j]   + acc[1][s][cc+2] + sB[128+j]);
          float n = tanhf_fast(ig1[256+j] + r*(acc[2][s][cc+2] + sB[256+j]));
          float hp = sH[(g+8)*128 + j];
          sH[(g+8)*128 + j] = (1.f-z)*n + z*hp;
        }
      }
    }
    __syncthreads();
  }
  for (int i=tid;i<2048;i+=256)
    g_Hfin[(long)(b0 + (i>>7))*128 + (i&127)] = sH[i];
}

// ---- per-batch constants via tf32 MMA: ct, ci, alpha, last item ----
// grid=32, block=128 (4 warps x 16 rows = 64 batches per block)
__global__ __launch_bounds__(128) void k_prep2(
    const float* __restrict__ ide, const float* __restrict__ txe,
    const int* __restrict__ lens, const int* __restrict__ sitems,
    const float* __restrict__ bt1, const float* __restrict__ bi1,
    const float* __restrict__ ba1, const float* __restrict__ Wa2,
    const float* __restrict__ ba2)
{
  __shared__ float sbt[128], sbi[128], sba[64], swa2[192], sba2[3];
  const int tid = threadIdx.x, warp = tid>>5, lane = tid&31;
  const int g = lane>>2, tig = lane&3;
  const int base = blockIdx.x*64;
  const int r0 = base + warp*16 + g, r1 = r0 + 8;

  if (tid < 128){ sbt[tid] = bt1[tid]; sbi[tid] = bi1[tid]; }
  if (tid < 64)  sba[tid] = ba1[tid];
  for (int i=tid;i<192;i+=128) swa2[i] = Wa2[i];
  if (tid < 3) sba2[tid] = ba2[tid];

  const int L0 = lens[r0], L1 = lens[r1];
  const float* lt0 = txe + ((long)r0*L_ + L0-1)*128;
  const float* lt1 = txe + ((long)r1*L_ + L1-1)*128;
  const float* li0 = ide + ((long)r0*L_ + L0-1)*64;
  const float* li1 = ide + ((long)r1*L_ + L1-1)*64;
  const float* hh0 = g_Hfin + (long)r0*128;
  const float* hh1 = g_Hfin + (long)r1*128;

  if (tid < 64){
    int b = base + tid;
    g_LI[b] = sitems[(long)b*L_ + lens[b]-1];
  }
  __syncthreads();

  // ---- CT: K=256 ([lt | hh]), N=128 ----
  {
    float acc[16][4];
#pragma unroll
    for (int nt=0;nt<16;nt++){ acc[nt][0]=0.f;acc[nt][1]=0.f;acc[nt][2]=0.f;acc[nt][3]=0.f; }
    const float4* bp = (const float4*)g_WCT;
#pragma unroll
    for (int kt=0;kt<32;kt++){
      int k0 = kt*8 + tig, k4 = k0+4;
      unsigned a0 = f2tf(k0<128 ? lt0[k0] : hh0[k0-128]);
      unsigned a2 = f2tf(k4<128 ? lt0[k4] : hh0[k4-128]);
      unsigned a1 = f2tf(k0<128 ? lt1[k0] : hh1[k0-128]);
      unsigned a3 = f2tf(k4<128 ? lt1[k4] : hh1[k4-128]);
#pragma unroll
      for (int n2=0;n2<8;n2++){
        float4 bv = bp[(kt*8 + n2)*32 + lane];
        mma8(acc[2*n2],   a0,a1,a2,a3, __float_as_uint(bv.x), __float_as_uint(bv.y));
        mma8(acc[2*n2+1], a0,a1,a2,a3, __float_as_uint(bv.z), __float_as_uint(bv.w));
      }
    }
#pragma unroll
    for (int nt=0;nt<16;nt++){
      int j = nt*8 + 2*tig;
      float* o0 = g_CT + (long)r0*128 + j;
      float* o1 = g_CT + (long)r1*128 + j;
      o0[0] = acc[nt][0]+sbt[j]; o0[1] = acc[nt][1]+sbt[j+1];
      o1[0] = acc[nt][2]+sbt[j]; o1[1] = acc[nt][3]+sbt[j+1];
    }
  }
  // ---- CI: K=192 ([lid | hh]), N=128 ----
  {
    float acc[16][4];
#pragma unroll
    for (int nt=0;nt<16;nt++){ acc[nt][0]=0.f;acc[nt][1]=0.f;acc[nt][2]=0.f;acc[nt][3]=0.f; }
    const float4* bp = (const float4*)g_WCI;
#pragma unroll
    for (int kt=0;kt<24;kt++){
      int k0 = kt*8 + tig, k4 = k0+4;
      unsigned a0 = f2tf(k0<64 ? li0[k0] : hh0[k0-64]);
      unsigned a2 = f2tf(k4<64 ? li0[k4] : hh0[k4-64]);
      unsigned a1 = f2tf(k0<64 ? li1[k0] : hh1[k0-64]);
      unsigned a3 = f2tf(k4<64 ? li1[k4] : hh1[k4-64]);
#pragma unroll
      for (int n2=0;n2<8;n2++){
        float4 bv = bp[(kt*8 + n2)*32 + lane];
        mma8(acc[2*n2],   a0,a1,a2,a3, __float_as_uint(bv.x), __float_as_uint(bv.y));
        mma8(acc[2*n2+1], a0,a1,a2,a3, __float_as_uint(bv.z), __float_as_uint(bv.w));
      }
    }
#pragma unroll
    for (int nt=0;nt<16;nt++){
      int j = nt*8 + 2*tig;
      float* o0 = g_CI + (long)r0*128 + j;
      float* o1 = g_CI + (long)r1*128 + j;
      o0[0] = acc[nt][0]+sbi[j]; o0[1] = acc[nt][1]+sbi[j+1];
      o1[0] = acc[nt][2]+sbi[j]; o1[1] = acc[nt][3]+sbi[j+1];
    }
  }
  // ---- alpha: hh @ Wa1^T (N=64,K=128), relu, 64->3, softmax ----
  {
    float acc[8][4];
#pragma unroll
    for (int nt=0;nt<8;nt++){ acc[nt][0]=0.f;acc[nt][1]=0.f;acc[nt][2]=0.f;acc[nt][3]=0.f; }
    const float4* bp = (const float4*)g_WA;
#pragma unroll
    for (int kt=0;kt<16;kt++){
      int k0 = kt*8 + tig;
      unsigned a0 = f2tf(hh0[k0]), a2 = f2tf(hh0[k0+4]);
      unsigned a1 = f2tf(hh1[k0]), a3 = f2tf(hh1[k0+4]);
#pragma unroll
      for (int n2=0;n2<4;n2++){
        float4 bv = bp[(kt*4 + n2)*32 + lane];
        mma8(acc[2*n2],   a0,a1,a2,a3, __float_as_uint(bv.x), __float_as_uint(bv.y));
        mma8(acc[2*n2+1], a0,a1,a2,a3, __float_as_uint(bv.z), __float_as_uint(bv.w));
      }
    }
    float p0[3] = {0.f,0.f,0.f}, p1[3] = {0.f,0.f,0.f};
#pragma unroll
    for (int nt=0;nt<8;nt++){
      int u0 = nt*8 + 2*tig, u1 = u0+1;
      float v00 = fmaxf(acc[nt][0]+sba[u0],0.f), v01 = fmaxf(acc[nt][1]+sba[u1],0.f);
      float v10 = fmaxf(acc[nt][2]+sba[u0],0.f), v11 = fmaxf(acc[nt][3]+sba[u1],0.f);
#pragma unroll
      for (int gg=0;gg<3;gg++){
        float w0 = swa2[gg*64+u0], w1 = swa2[gg*64+u1];
        p0[gg] += w0*v00 + w1*v01;
        p1[gg] += w0*v10 + w1*v11;
      }
    }
#pragma unroll
    for (int gg=0;gg<3;gg++){
      p0[gg] += __shfl_xor_sync(0xffffffffu,p0[gg],1);
      p0[gg] += __shfl_xor_sync(0xffffffffu,p0[gg],2);
      p1[gg] += __shfl_xor_sync(0xffffffffu,p1[gg],1);
      p1[gg] += __shfl_xor_sync(0xffffffffu,p1[gg],2);
    }
    if (tig==0){
      {
        float l0=p0[0]+sba2[0], l1=p0[1]+sba2[1], l2=p0[2]+sba2[2];
        float m = fmaxf(l0, fmaxf(l1,l2));
        float e0=__expf(l0-m), e1=__expf(l1-m), e2=__expf(l2-m);
        float inv = 1.f/(e0+e1+e2);
        g_AL[(long)r0*3+0]=e0*inv; g_AL[(long)r0*3+1]=e1*inv; g_AL[(long)r0*3+2]=e2*inv;
      }
      {
        float l0=p1[0]+sba2[0], l1=p1[1]+sba2[1], l2=p1[2]+sba2[2];
        float m = fmaxf(l0, fmaxf(l1,l2));
        float e0=__expf(l0-m), e1=__expf(l1-m), e2=__expf(l2-m);
        float inv = 1.f/(e0+e1+e2);
        g_AL[(long)r1*3+0]=e0*inv; g_AL[(long)r1*3+1]=e1*inv; g_AL[(long)r1*3+2]=e2*inv;
      }
    }
  }
}

// ---- fused scorer (tf32) + softmaxes + mix: one block per batch ----
__global__ __launch_bounds__(256) void k_score(
    const float* __restrict__ ctxe, const float* __restrict__ cide,
    const int* __restrict__ cids, const float* __restrict__ co,
    const float* __restrict__ Wt2, const float* __restrict__ bt2,
    const float* __restrict__ Wi2, const float* __restrict__ bi2,
    const float* __restrict__ betac, const float* __restrict__ lTc,
    const float* __restrict__ lTt, const float* __restrict__ lTi,
    float* __restrict__ out)
{
  __shared__ float ctv[128], civ[128], w2t[128], w2i[128];
  __shared__ float sco[3][128];
  __shared__ float mx3[3], inv3[3], sS;
  __shared__ float mixv[128];
  const int b = blockIdx.x, tid = threadIdx.x;
  const int warp = tid>>5, lane = tid&31;
  const int g = lane>>2, tig = lane&3;
  const int r0 = warp*16 + g, r1 = r0 + 8;

  if (tid < 128){
    ctv[tid]=g_CT[b*128+tid]; civ[tid]=g_CI[b*128+tid];
    w2t[tid]=Wt2[tid];        w2i[tid]=Wi2[tid];
  }
  if (tid < 100){
    long li = g_LI[b];
    sco[0][tid] = co[li*V_ + cids[(long)b*C_+tid]] * betac[0] / expf(lTc[0]);
  }
  const float Tt = expf(lTt[0]), Ti = expf(lTi[0]);
  __syncthreads();

  // text pass: M=128(pad 100) x N=128 x K=128
  {
    float acc[16][4];
#pragma unroll
    for (int nt=0;nt<16;nt++){ acc[nt][0]=0.f;acc[nt][1]=0.f;acc[nt][2]=0.f;acc[nt][3]=0.f; }
    const float* Eb = ctxe + (long)b*C_*128;
    const float4* bp = (const float4*)g_WT;
#pragma unroll
    for (int kt=0;kt<16;kt++){
      const int k0 = kt*8 + tig;
      unsigned a0=0u,a1=0u,a2=0u,a3=0u;
      if (r0 < C_){ a0 = f2tf(Eb[(long)r0*128 + k0]); a2 = f2tf(Eb[(long)r0*128 + k0 + 4]); }
      if (r1 < C_){ a1 = f2tf(Eb[(long)r1*128 + k0]); a3 = f2tf(Eb[(long)r1*128 + k0 + 4]); }
#pragma unroll
      for (int n2=0;n2<8;n2++){
        float4 bv = bp[(kt*8 + n2)*32 + lane];
        mma8(acc[2*n2],   a0,a1,a2,a3, __float_as_uint(bv.x), __float_as_uint(bv.y));
        mma8(acc[2*n2+1], a0,a1,a2,a3, __float_as_uint(bv.z), __float_as_uint(bv.w));
      }
    }
    float p0=0.f, p1=0.f;
#pragma unroll
    for (int nt=0;nt<16;nt++){
      int j0 = nt*8 + 2*tig;
      float w0=w2t[j0], w1=w2t[j0+1], c0=ctv[j0], c1=ctv[j0+1];
      p0 += w0*fmaxf(c0+acc[nt][0],0.f) + w1*fmaxf(c1+acc[nt][1],0.f);
      p1 += w0*fmaxf(c0+acc[nt][2],0.f) + w1*fmaxf(c1+acc[nt][3],0.f);
    }
    p0 += __shfl_xor_sync(0xffffffffu,p0,1); p0 += __shfl_xor_sync(0xffffffffu,p0,2);
    p1 += __shfl_xor_sync(0xffffffffu,p1,1); p1 += __shfl_xor_sync(0xffffffffu,p1,2);
    if (tig==0){
      if (r0 < C_) sco[1][r0] = (p0 + bt2[0]) / Tt;
      if (r1 < C_) sco[1][r1] = (p1 + bt2[0]) / Tt;
    }
  }
  // id pass: K=64
  {
    float acc[16][4];
#pragma unroll
    for (int nt=0;nt<16;nt++){ acc[nt][0]=0.f;acc[nt][1]=0.f;acc[nt][2]=0.f;acc[nt][3]=0.f; }
    const float* Eb = cide + (long)b*C_*64;
    const float4* bp = (const float4*)g_WI;
#pragma unroll
    for (int kt=0;kt<8;kt++){
      const int k0 = kt*8 + tig;
      unsigned a0=0u,a1=0u,a2=0u,a3=0u;
      if (r0 < C_){ a0 = f2tf(Eb[(long)r0*64 + k0]); a2 = f2tf(Eb[(long)r0*64 + k0 + 4]); }
      if (r1 < C_){ a1 = f2tf(Eb[(long)r1*64 + k0]); a3 = f2tf(Eb[(long)r1*64 + k0 + 4]); }
#pragma unroll
      for (int n2=0;n2<8;n2++){
        float4 bv = bp[(kt*8 + n2)*32 + lane];
        mma8(acc[2*n2],   a0,a1,a2,a3, __float_as_uint(bv.x), __float_as_uint(bv.y));
        mma8(acc[2*n2+1], a0,a1,a2,a3, __float_as_uint(bv.z), __float_as_uint(bv.w));
      }
    }
    float p0=0.f, p1=0.f;
#pragma unroll
    for (int nt=0;nt<16;nt++){
      int j0 = nt*8 + 2*tig;
      float w0=w2i[j0], w1=w2i[j0+1], c0=civ[j0], c1=civ[j0+1];
      p0 += w0*fmaxf(c0+acc[nt][0],0.f) + w1*fmaxf(c1+acc[nt][1],0.f);
      p1 += w0*fmaxf(c0+acc[nt][2],0.f) + w1*fmaxf(c1+acc[nt][3],0.f);
    }
    p0 += __shfl_xor_sync(0xffffffffu,p0,1); p0 += __shfl_xor_sync(0xffffffffu,p0,2);
    p1 += __shfl_xor_sync(0xffffffffu,p1,1); p1 += __shfl_xor_sync(0xffffffffu,p1,2);
    if (tig==0){
      if (r0 < C_) sco[2][r0] = (p0 + bi2[0]) / Ti;
      if (r1 < C_) sco[2][r1] = (p1 + bi2[0]) / Ti;
    }
  }
  __syncthreads();

  if (warp == 0){
#pragma unroll
    for (int chn=0;chn<3;chn++){
      float m = -1e30f;
      for (int q=lane;q<C_;q+=32) m = fmaxf(m, sco[chn][q]);
      m = wmax(m);
      float s = 0.f;
      for (int q=lane;q<C_;q+=32) s += __expf(sco[chn][q]-m);
      s = wsum(s);
      if (lane==0){ mx3[chn]=m; inv3[chn]=1.f/s; }
    }
  }
  __syncthreads();
  const float a0=g_AL[b*3], a1=g_AL[b*3+1], a2=g_AL[b*3+2];
  if (tid < C_){
    float p = 0.01f
      + a0*__expf(sco[0][tid]-mx3[0])*inv3[0]
      + a1*__expf(sco[1][tid]-mx3[1])*inv3[1]
      + a2*__expf(sco[2][tid]-mx3[2])*inv3[2];
    mixv[tid] = p;
  }
  __syncthreads();
  if (warp == 0){
    float s = 0.f;
    for (int q=lane;q<C_;q+=32) s += mixv[q];
    s = wsum(s);
    if (lane==0) sS = 1.f/s;
  }
  __syncthreads();
  if (tid < C_) out[(long)b*C_ + tid] = mixv[tid]*sS;
}

extern "C" void kernel_launch(void* const* d_in, const int* in_sizes, int n_in,
                              void* d_out, int out_size) {
  const int*   sitems = (const int*)  d_in[0];
  const float* ide    = (const float*)d_in[1];
  const float* txe    = (const float*)d_in[2];
  const int*   lens   = (const int*)  d_in[3];
  const int*   cids   = (const int*)  d_in[4];
  const float* cide   = (const float*)d_in[5];
  const float* ctxe   = (const float*)d_in[6];
  const float* co     = (const float*)d_in[7];
  const float* Wih    = (const float*)d_in[8];
  const float* Whh    = (const float*)d_in[9];
  const float* bih    = (const float*)d_in[10];
  const float* bhh    = (const float*)d_in[11];
  const float* Wt1    = (const float*)d_in[12];
  const float* bt1    = (const float*)d_in[13];
  const float* Wt2    = (const float*)d_in[14];
  const float* bt2    = (const float*)d_in[15];
  const float* Wi1    = (const float*)d_in[16];
  const float* bi1    = (const float*)d_in[17];
  const float* Wi2    = (const float*)d_in[18];
  const float* bi2    = (const float*)d_in[19];
  const float* Wa1    = (const float*)d_in[20];
  const float* ba1    = (const float*)d_in[21];
  const float* Wa2    = (const float*)d_in[22];
  const float* ba2    = (const float*)d_in[23];
  // d_in[24] = Wstab: unused (P_stable is uniform = 1/C exactly)
  const float* betac  = (const float*)d_in[25];
  const float* lTc    = (const float*)d_in[26];
  const float* lTt    = (const float*)d_in[27];
  const float* lTi    = (const float*)d_in[28];
  float* out = (float*)d_out;

  const int GRU_SMEM = (49152 + 2048 + 384) * 4;   // 206336 B
  cudaFuncSetAttribute(k_gruall, cudaFuncAttributeMaxDynamicSharedMemorySize, GRU_SMEM);

  const int WPREP_N = 73728+49152+16384+8192+32768+24576+8192;
  k_wprep<<<(WPREP_N+255)/256, 256>>>(Wih, Whh, Wt1, Wi1, Wa1);
  k_ig<<<80, 256>>>(ide, txe, lens, bih);
  k_gruall<<<128, 256, GRU_SMEM>>>(bhh);
  k_prep2<<<32, 128>>>(ide, txe, lens, sitems, bt1, bi1, ba1, Wa2, ba2);
  k_score<<<B_, 256>>>(ctxe, cide, cids, co, Wt2, bt2, Wi2, bi2,
                       betac, lTc, lTt, lTi, out);
}

// round 8
// speedup vs baseline: 3.0194x; 1.0634x over previous
#include <cuda_runtime.h>
#include <math.h>

#define B_  2048
#define L_  200
#define C_  100
#define V_  2000

// ---------------- scratch ----------------
__device__ float g_IG  [B_*5*384];
__device__ float g_CT  [B_*128];
__device__ float g_CI  [B_*128];
__device__ float g_AL  [B_*3];
__device__ float g_WT  [16384];        // Wt1 mid slab (N=128,K=128) frag order
__device__ float g_WI  [8192];         // Wi1 mid slab (N=128,K=64)  frag order
__device__ float g_WIHf[73728];        // W_ih (N=384,K=192) frag order
__device__ float g_WHHf[49152];        // W_hh (N=384,K=128) frag order
__device__ float g_WCT [32768];        // [Wt1 src | Wt1 h]  (N=128,K=256) frag
__device__ float g_WCI [24576];        // [Wi1 src | Wi1 h]  (N=128,K=192) frag
__device__ float g_WA  [8192];         // Wa1 (N=64,K=128) frag
__device__ int   g_LI  [B_];

__device__ __forceinline__ float sigf(float x){ return 1.0f/(1.0f+__expf(-x)); }
__device__ __forceinline__ float tanhf_fast(float x){
  x = fminf(fmaxf(x,-15.f),15.f);
  float e = __expf(2.f*x);
  return (e-1.f)/(e+1.f);
}
__device__ __forceinline__ float wsum(float v){
#pragma unroll
  for (int o=16;o;o>>=1) v += __shfl_xor_sync(0xffffffffu, v, o);
  return v;
}
__device__ __forceinline__ float wmax(float v){
#pragma unroll
  for (int o=16;o;o>>=1) v = fmaxf(v, __shfl_xor_sync(0xffffffffu, v, o));
  return v;
}
__device__ __forceinline__ unsigned f2tf(float x){
  unsigned r; asm("cvt.rna.tf32.f32 %0, %1;" : "=r"(r) : "f"(x)); return r;
}
__device__ __forceinline__ void mma8(float* d,
    unsigned a0, unsigned a1, unsigned a2, unsigned a3,
    unsigned b0, unsigned b1){
  asm volatile(
    "mma.sync.aligned.m16n8k8.row.col.f32.tf32.tf32.f32 "
    "{%0,%1,%2,%3},{%4,%5,%6,%7},{%8,%9},{%0,%1,%2,%3};\n"
    : "+f"(d[0]),"+f"(d[1]),"+f"(d[2]),"+f"(d[3])
    : "r"(a0),"r"(a1),"r"(a2),"r"(a3),"r"(b0),"r"(b1));
}

// decode fragment-order flat index -> (j,k) for weight W[N][K]
__device__ __forceinline__ void frag_jk(int idx, int N, int* jj, int* kk){
  int c = idx & 3, lane = (idx>>2)&31;
  int P = N >> 4;
  int pr = (idx>>7) % P;
  int kt = idx / (128*P);
  int nt = 2*pr + (c>>1), p = c&1;
  *jj = nt*8 + (lane>>2);
  *kk = kt*8 + (lane&3) + 4*p;
}

// ---- prepare all fragment-ordered weights (tf32-rounded) ----
__global__ void k_wprep(const float* __restrict__ Wih, const float* __restrict__ Whh,
                        const float* __restrict__ Wt1, const float* __restrict__ Wi1,
                        const float* __restrict__ Wa1){
  int idx = blockIdx.x*blockDim.x + threadIdx.x;
  int j, k;
  int off = 0;
  if (idx < (off += 73728)){                       // Wih: N=384,K=192
    frag_jk(idx, 384, &j, &k);
    g_WIHf[idx] = __uint_as_float(f2tf(Wih[(long)j*192 + k]));
    return;
  }
  if (idx < (off + 49152)){                        // Whh: N=384,K=128
    int i2 = idx - off;
    frag_jk(i2, 384, &j, &k);
    g_WHHf[i2] = __uint_as_float(f2tf(Whh[(long)j*128 + k]));
    return;
  }
  off += 49152;
  if (idx < (off + 16384)){                        // Wt1 mid: N=128,K=128
    int i2 = idx - off;
    frag_jk(i2, 128, &j, &k);
    g_WT[i2] = __uint_as_float(f2tf(Wt1[(long)j*384 + 128 + k]));
    return;
  }
  off += 16384;
  if (idx < (off + 8192)){                         // Wi1 mid: N=128,K=64
    int i2 = idx - off;
    frag_jk(i2, 128, &j, &k);
    g_WI[i2] = __uint_as_float(f2tf(Wi1[(long)j*256 + 64 + k]));
    return;
  }
  off += 8192;
  if (idx < (off + 32768)){                        // WCT: N=128,K=256
    int i2 = idx - off;
    frag_jk(i2, 128, &j, &k);
    float v = (k < 128) ? Wt1[(long)j*384 + k] : Wt1[(long)j*384 + 256 + (k-128)];
    g_WCT[i2] = __uint_as_float(f2tf(v));
    return;
  }
  off += 32768;
  if (idx < (off + 24576)){                        // WCI: N=128,K=192
    int i2 = idx - off;
    frag_jk(i2, 128, &j, &k);
    float v = (k < 64) ? Wi1[(long)j*256 + k] : Wi1[(long)j*256 + 128 + (k-64)];
    g_WCI[i2] = __uint_as_float(f2tf(v));
    return;
  }
  off += 24576;
  if (idx < (off + 8192)){                         // WA: N=64,K=128
    int i2 = idx - off;
    frag_jk(i2, 64, &j, &k);
    g_WA[i2] = __uint_as_float(f2tf(Wa1[(long)j*128 + k]));
    return;
  }
}

// ---- input-gate GEMM (tf32): IG[m][n] = x_m · Wih[n] + bih[n] ----
__global__ __launch_bounds__(256) void k_ig(
    const float* __restrict__ ide, const float* __restrict__ txe,
    const int* __restrict__ lens, const float* __restrict__ bih)
{
  __shared__ float sB[384];
  const int tid = threadIdx.x, warp = tid>>5, lane = tid&31;
  const int g = lane>>2, tig = lane&3;
  for (int i=tid; i<384; i+=256) sB[i] = bih[i];
  const int r0 = blockIdx.x*128 + warp*16 + g;
  const int r1 = r0 + 8;
  int b0 = r0/5, t0 = r0 - 5*b0;  int p0 = lens[b0] - 5 + t0;
  int b1 = r1/5, t1 = r1 - 5*b1;  int p1 = lens[b1] - 5 + t1;
  const float* id0 = ide + ((long)b0*L_ + p0)*64;
  const float* tx0 = txe + ((long)b0*L_ + p0)*128;
  const float* id1 = ide + ((long)b1*L_ + p1)*64;
  const float* tx1 = txe + ((long)b1*L_ + p1)*128;
  __syncthreads();

  const float4* bp = (const float4*)g_WIHf;
  for (int ch=0; ch<3; ch++){
    float acc[16][4];
#pragma unroll
    for (int nt=0;nt<16;nt++){ acc[nt][0]=0.f;acc[nt][1]=0.f;acc[nt][2]=0.f;acc[nt][3]=0.f; }
#pragma unroll
    for (int kt=0;kt<24;kt++){
      int k0 = kt*8 + tig, k4 = k0+4;
      unsigned a0 = f2tf(k0<64 ? id0[k0] : tx0[k0-64]);
      unsigned a2 = f2tf(k4<64 ? id0[k4] : tx0[k4-64]);
      unsigned a1 = f2tf(k0<64 ? id1[k0] : tx1[k0-64]);
      unsigned a3 = f2tf(k4<64 ? id1[k4] : tx1[k4-64]);
#pragma unroll
      for (int n2=0;n2<8;n2++){
        float4 bv = bp[(kt*24 + ch*8 + n2)*32 + lane];
        mma8(acc[2*n2],   a0,a1,a2,a3, __float_as_uint(bv.x), __float_as_uint(bv.y));
        mma8(acc[2*n2+1], a0,a1,a2,a3, __float_as_uint(bv.z), __float_as_uint(bv.w));
      }
    }
#pragma unroll
    for (int nt=0;nt<16;nt++){
      int j = ch*128 + nt*8 + 2*tig;
      float* o0 = g_IG + (long)r0*384 + j;
      float* o1 = g_IG + (long)r1*384 + j;
      o0[0] = acc[nt][0]+sB[j]; o0[1] = acc[nt][1]+sB[j+1];
      o1[0] = acc[nt][2]+sB[j]; o1[1] = acc[nt][3]+sB[j+1];
    }
  }
}

// ---- persistent fused GRU (5 steps) + per-batch prep (ct/ci/alpha) ----
// grid=128, block=256 (8 warps), 16 batches per block.
// smem: W_hh frag (49152 f, reused as a1s/lg after GRU) + h (2048) + biases.
__global__ __launch_bounds__(256) void k_gruall(
    const float* __restrict__ bhh,
    const float* __restrict__ ide, const float* __restrict__ txe,
    const int* __restrict__ lens, const int* __restrict__ sitems,
    const float* __restrict__ bt1, const float* __restrict__ bi1,
    const float* __restrict__ ba1, const float* __restrict__ Wa2,
    const float* __restrict__ ba2)
{
  extern __shared__ float sm[];
  float* sW  = sm;                  // 49152 (W_hh frags; reused after GRU)
  float* sH  = sm + 49152;          // 2048
  float* sB  = sm + 49152+2048;     // 384
  float* sbt = sB + 384;            // 128
  float* sbi = sbt + 128;           // 128
  float* sba = sbi + 128;           // 64
  float* swa2= sba + 64;            // 192
  float* sba2= swa2 + 192;          // 4 (3 used)
  const int tid = threadIdx.x, warp = tid>>5, lane = tid&31;
  const int g = lane>>2, tig = lane&3;
  const int b0 = blockIdx.x*16;

  {
    const float4* gw = (const float4*)g_WHHf;
    float4* swv = (float4*)sW;
    for (int i=tid;i<12288;i+=256) swv[i] = gw[i];
  }
  for (int i=tid;i<384;i+=256) sB[i] = bhh[i];
  if (tid < 128){ sbt[tid] = bt1[tid]; sbi[tid] = bi1[tid]; }
  else if (tid < 192) sba[tid-128] = ba1[tid-128];
  else if (tid < 195) sba2[tid-192] = ba2[tid-192];
  for (int i=tid;i<192;i+=256) swa2[i] = Wa2[i];
  if (tid < 16) g_LI[b0+tid] = sitems[(long)(b0+tid)*L_ + lens[b0+tid]-1];
  __syncthreads();

  // step 0
  for (int i=tid;i<2048;i+=256){
    int bb = i>>7, j = i&127;
    const float* ig = g_IG + ((long)(b0+bb)*5)*384;
    float r = sigf(ig[j]       + sB[j]);
    float z = sigf(ig[128+j]   + sB[128+j]);
    float n = tanhf_fast(ig[256+j] + r*sB[256+j]);
    sH[i] = (1.f - z)*n;
  }
  __syncthreads();

  const float4* swv4 = (const float4*)sW;
  for (int t=1;t<5;t++){
    float acc[3][2][4];
#pragma unroll
    for (int gate=0;gate<3;gate++)
#pragma unroll
      for (int s=0;s<2;s++){ acc[gate][s][0]=0.f;acc[gate][s][1]=0.f;acc[gate][s][2]=0.f;acc[gate][s][3]=0.f; }
#pragma unroll
    for (int kt=0;kt<16;kt++){
      int k0 = kt*8 + tig;
      unsigned a0 = f2tf(sH[g*128     + k0]);
      unsigned a1 = f2tf(sH[(g+8)*128 + k0]);
      unsigned a2 = f2tf(sH[g*128     + k0+4]);
      unsigned a3 = f2tf(sH[(g+8)*128 + k0+4]);
#pragma unroll
      for (int gate=0;gate<3;gate++){
        int pr = gate*8 + warp;
        float4 bv = swv4[(kt*24 + pr)*32 + lane];
        mma8(acc[gate][0], a0,a1,a2,a3, __float_as_uint(bv.x), __float_as_uint(bv.y));
        mma8(acc[gate][1], a0,a1,a2,a3, __float_as_uint(bv.z), __float_as_uint(bv.w));
      }
    }
    __syncthreads();
    const float* ig0 = g_IG + (((long)(b0+g))*5   + t)*384;
    const float* ig1 = g_IG + (((long)(b0+g+8))*5 + t)*384;
#pragma unroll
    for (int s=0;s<2;s++){
#pragma unroll
      for (int cc=0;cc<2;cc++){
        int j = warp*16 + s*8 + tig*2 + cc;
        {
          float r = sigf(ig0[j]       + acc[0][s][cc] + sB[j]);
          float z = sigf(ig0[128+j]   + acc[1][s][cc] + sB[128+j]);
          float n = tanhf_fast(ig0[256+j] + r*(acc[2][s][cc] + sB[256+j]));
          float hp = sH[g*128 + j];
          sH[g*128 + j] = (1.f-z)*n + z*hp;
        }
        {
          float r = sigf(ig1[j]       + acc[0][s][cc+2] + sB[j]);
          float z = sigf(ig1[128+j]   + acc[1][s][cc+2] + sB[128+j]);
          float n = tanhf_fast(ig1[256+j] + r*(acc[2][s][cc+2] + sB[256+j]));
          float hp = sH[(g+8)*128 + j];
          sH[(g+8)*128 + j] = (1.f-z)*n + z*hp;
        }
      }
    }
    __syncthreads();
  }

  // ================= fused per-batch prep =================
  const int L0 = lens[b0+g], L1 = lens[b0+8+g];
  const float* lt0 = txe + ((long)(b0+g)*L_   + L0-1)*128;
  const float* lt1 = txe + ((long)(b0+8+g)*L_ + L1-1)*128;
  const float* li0 = ide + ((long)(b0+g)*L_   + L0-1)*64;
  const float* li1 = ide + ((long)(b0+8+g)*L_ + L1-1)*64;
  const float* h0  = sH + g*128;
  const float* h1  = sH + (g+8)*128;

  // CT: M=16, N=128 (warp w owns n2=w), K=256 = [lt | h]
  {
    float acc[2][4];
    acc[0][0]=0.f;acc[0][1]=0.f;acc[0][2]=0.f;acc[0][3]=0.f;
    acc[1][0]=0.f;acc[1][1]=0.f;acc[1][2]=0.f;acc[1][3]=0.f;
    const float4* bp = (const float4*)g_WCT;
#pragma unroll
    for (int kt=0;kt<32;kt++){
      int k0 = kt*8 + tig, k4 = k0+4;
      unsigned a0 = f2tf(k0<128 ? lt0[k0] : h0[k0-128]);
      unsigned a2 = f2tf(k4<128 ? lt0[k4] : h0[k4-128]);
      unsigned a1 = f2tf(k0<128 ? lt1[k0] : h1[k0-128]);
      unsigned a3 = f2tf(k4<128 ? lt1[k4] : h1[k4-128]);
      float4 bv = bp[(kt*8 + warp)*32 + lane];
      mma8(acc[0], a0,a1,a2,a3, __float_as_uint(bv.x), __float_as_uint(bv.y));
      mma8(acc[1], a0,a1,a2,a3, __float_as_uint(bv.z), __float_as_uint(bv.w));
    }
#pragma unroll
    for (int s=0;s<2;s++){
      int j = (2*warp+s)*8 + 2*tig;
      float* o0 = g_CT + (long)(b0+g)*128 + j;
      float* o1 = g_CT + (long)(b0+8+g)*128 + j;
      o0[0] = acc[s][0]+sbt[j]; o0[1] = acc[s][1]+sbt[j+1];
      o1[0] = acc[s][2]+sbt[j]; o1[1] = acc[s][3]+sbt[j+1];
    }
  }
  // CI: K=192 = [lid | h]
  {
    float acc[2][4];
    acc[0][0]=0.f;acc[0][1]=0.f;acc[0][2]=0.f;acc[0][3]=0.f;
    acc[1][0]=0.f;acc[1][1]=0.f;acc[1][2]=0.f;acc[1][3]=0.f;
    const float4* bp = (const float4*)g_WCI;
#pragma unroll
    for (int kt=0;kt<24;kt++){
      int k0 = kt*8 + tig, k4 = k0+4;
      unsigned a0 = f2tf(k0<64 ? li0[k0] : h0[k0-64]);
      unsigned a2 = f2tf(k4<64 ? li0[k4] : h0[k4-64]);
      unsigned a1 = f2tf(k0<64 ? li1[k0] : h1[k0-64]);
      unsigned a3 = f2tf(k4<64 ? li1[k4] : h1[k4-64]);
      float4 bv = bp[(kt*8 + warp)*32 + lane];
      mma8(acc[0], a0,a1,a2,a3, __float_as_uint(bv.x), __float_as_uint(bv.y));
      mma8(acc[1], a0,a1,a2,a3, __float_as_uint(bv.z), __float_as_uint(bv.w));
    }
#pragma unroll
    for (int s=0;s<2;s++){
      int j = (2*warp+s)*8 + 2*tig;
      float* o0 = g_CI + (long)(b0+g)*128 + j;
      float* o1 = g_CI + (long)(b0+8+g)*128 + j;
      o0[0] = acc[s][0]+sbi[j]; o0[1] = acc[s][1]+sbi[j+1];
      o1[0] = acc[s][2]+sbi[j]; o1[1] = acc[s][3]+sbi[j+1];
    }
  }
  // alpha: N=64 (warps 0-3, n2=warp), K=128 = h ; a1s reuses sW space
  float (*a1s)[64] = (float(*)[64])sW;
  float (*lg)[3]   = (float(*)[3])(sW + 16*64);
  {
    if (warp < 4){
      float acc[2][4];
      acc[0][0]=0.f;acc[0][1]=0.f;acc[0][2]=0.f;acc[0][3]=0.f;
      acc[1][0]=0.f;acc[1][1]=0.f;acc[1][2]=0.f;acc[1][3]=0.f;
      const float4* bp = (const float4*)g_WA;
#pragma unroll
      for (int kt=0;kt<16;kt++){
        int k0 = kt*8 + tig;
        unsigned a0 = f2tf(h0[k0]), a2 = f2tf(h0[k0+4]);
        unsigned a1 = f2tf(h1[k0]), a3 = f2tf(h1[k0+4]);
        float4 bv = bp[(kt*4 + warp)*32 + lane];
        mma8(acc[0], a0,a1,a2,a3, __float_as_uint(bv.x), __float_as_uint(bv.y));
        mma8(acc[1], a0,a1,a2,a3, __float_as_uint(bv.z), __float_as_uint(bv.w));
      }
#pragma unroll
      for (int s=0;s<2;s++){
        int u = (2*warp+s)*8 + 2*tig;
        a1s[g][u]     = fmaxf(acc[s][0]+sba[u],0.f);
        a1s[g][u+1]   = fmaxf(acc[s][1]+sba[u+1],0.f);
        a1s[g+8][u]   = fmaxf(acc[s][2]+sba[u],0.f);
        a1s[g+8][u+1] = fmaxf(acc[s][3]+sba[u+1],0.f);
      }
    }
    __syncthreads();
    if (tid < 48){
      int bb = tid/3, gg = tid%3;
      float s = sba2[gg];
      const float* w = swa2 + gg*64;
      for (int u=0;u<64;u++) s += w[u]*a1s[bb][u];
      lg[bb][gg] = s;
    }
    __syncthreads();
    if (tid < 16){
      float l0=lg[tid][0], l1=lg[tid][1], l2=lg[tid][2];
      float m = fmaxf(l0, fmaxf(l1,l2));
      float e0=__expf(l0-m), e1=__expf(l1-m), e2=__expf(l2-m);
      float inv = 1.f/(e0+e1+e2);
      g_AL[(b0+tid)*3+0]=e0*inv; g_AL[(b0+tid)*3+1]=e1*inv; g_AL[(b0+tid)*3+2]=e2*inv;
    }
  }
}

// ---- fused scorer (tf32) + softmaxes + mix: one block per batch ----
__global__ __launch_bounds__(256) void k_score(
    const float* __restrict__ ctxe, const float* __restrict__ cide,
    const int* __restrict__ cids, const float* __restrict__ co,
    const float* __restrict__ Wt2, const float* __restrict__ bt2,
    const float* __restrict__ Wi2, const float* __restrict__ bi2,
    const float* __restrict__ betac, const float* __restrict__ lTc,
    const float* __restrict__ lTt, const float* __restrict__ lTi,
    float* __restrict__ out)
{
  __shared__ float ctv[128], civ[128], w2t[128], w2i[128];
  __shared__ float sco[3][128];
  __shared__ float mx3[3], inv3[3], sS;
  __shared__ float mixv[128];
  const int b = blockIdx.x, tid = threadIdx.x;
  const int warp = tid>>5, lane = tid&31;
  const int g = lane>>2, tig = lane&3;
  const int r0 = warp*16 + g, r1 = r0 + 8;

  if (tid < 128){
    ctv[tid]=g_CT[b*128+tid]; civ[tid]=g_CI[b*128+tid];
    w2t[tid]=Wt2[tid];        w2i[tid]=Wi2[tid];
  }
  if (tid < 100){
    long li = g_LI[b];
    sco[0][tid] = co[li*V_ + cids[(long)b*C_+tid]] * betac[0] / expf(lTc[0]);
  }
  const float Tt = expf(lTt[0]), Ti = expf(lTi[0]);
  __syncthreads();

  // text pass: M=128(pad 100) x N=128 x K=128
  {
    float acc[16][4];
#pragma unroll
    for (int nt=0;nt<16;nt++){ acc[nt][0]=0.f;acc[nt][1]=0.f;acc[nt][2]=0.f;acc[nt][3]=0.f; }
    const float* Eb = ctxe + (long)b*C_*128;
    const float4* bp = (const float4*)g_WT;
#pragma unroll
    for (int kt=0;kt<16;kt++){
      const int k0 = kt*8 + tig;
      unsigned a0=0u,a1=0u,a2=0u,a3=0u;
      if (r0 < C_){ a0 = f2tf(Eb[(long)r0*128 + k0]); a2 = f2tf(Eb[(long)r0*128 + k0 + 4]); }
      if (r1 < C_){ a1 = f2tf(Eb[(long)r1*128 + k0]); a3 = f2tf(Eb[(long)r1*128 + k0 + 4]); }
#pragma unroll
      for (int n2=0;n2<8;n2++){
        float4 bv = bp[(kt*8 + n2)*32 + lane];
        mma8(acc[2*n2],   a0,a1,a2,a3, __float_as_uint(bv.x), __float_as_uint(bv.y));
        mma8(acc[2*n2+1], a0,a1,a2,a3, __float_as_uint(bv.z), __float_as_uint(bv.w));
      }
    }
    float p0=0.f, p1=0.f;
#pragma unroll
    for (int nt=0;nt<16;nt++){
      int j0 = nt*8 + 2*tig;
      float w0=w2t[j0], w1=w2t[j0+1], c0=ctv[j0], c1=ctv[j0+1];
      p0 += w0*fmaxf(c0+acc[nt][0],0.f) + w1*fmaxf(c1+acc[nt][1],0.f);
      p1 += w0*fmaxf(c0+acc[nt][2],0.f) + w1*fmaxf(c1+acc[nt][3],0.f);
    }
    p0 += __shfl_xor_sync(0xffffffffu,p0,1); p0 += __shfl_xor_sync(0xffffffffu,p0,2);
    p1 += __shfl_xor_sync(0xffffffffu,p1,1); p1 += __shfl_xor_sync(0xffffffffu,p1,2);
    if (tig==0){
      if (r0 < C_) sco[1][r0] = (p0 + bt2[0]) / Tt;
      if (r1 < C_) sco[1][r1] = (p1 + bt2[0]) / Tt;
    }
  }
  // id pass: K=64
  {
    float acc[16][4];
#pragma unroll
    for (int nt=0;nt<16;nt++){ acc[nt][0]=0.f;acc[nt][1]=0.f;acc[nt][2]=0.f;acc[nt][3]=0.f; }
    const float* Eb = cide + (long)b*C_*64;
    const float4* bp = (const float4*)g_WI;
#pragma unroll
    for (int kt=0;kt<8;kt++){
      const int k0 = kt*8 + tig;
      unsigned a0=0u,a1=0u,a2=0u,a3=0u;
      if (r0 < C_){ a0 = f2tf(Eb[(long)r0*64 + k0]); a2 = f2tf(Eb[(long)r0*64 + k0 + 4]); }
      if (r1 < C_){ a1 = f2tf(Eb[(long)r1*64 + k0]); a3 = f2tf(Eb[(long)r1*64 + k0 + 4]); }
#pragma unroll
      for (int n2=0;n2<8;n2++){
        float4 bv = bp[(kt*8 + n2)*32 + lane];
        mma8(acc[2*n2],   a0,a1,a2,a3, __float_as_uint(bv.x), __float_as_uint(bv.y));
        mma8(acc[2*n2+1], a0,a1,a2,a3, __float_as_uint(bv.z), __float_as_uint(bv.w));
      }
    }
    float p0=0.f, p1=0.f;
#pragma unroll
    for (int nt=0;nt<16;nt++){
      int j0 = nt*8 + 2*tig;
      float w0=w2i[j0], w1=w2i[j0+1], c0=civ[j0], c1=civ[j0+1];
      p0 += w0*fmaxf(c0+acc[nt][0],0.f) + w1*fmaxf(c1+acc[nt][1],0.f);
      p1 += w0*fmaxf(c0+acc[nt][2],0.f) + w1*fmaxf(c1+acc[nt][3],0.f);
    }
    p0 += __shfl_xor_sync(0xffffffffu,p0,1); p0 += __shfl_xor_sync(0xffffffffu,p0,2);
    p1 += __shfl_xor_sync(0xffffffffu,p1,1); p1 += __shfl_xor_sync(0xffffffffu,p1,2);
    if (tig==0){
      if (r0 < C_) sco[2][r0] = (p0 + bi2[0]) / Ti;
      if (r1 < C_) sco[2][r1] = (p1 + bi2[0]) / Ti;
    }
  }
  __syncthreads();

  if (warp == 0){
#pragma unroll
    for (int chn=0;chn<3;chn++){
      float m = -1e30f;
      for (int q=lane;q<C_;q+=32) m = fmaxf(m, sco[chn][q]);
      m = wmax(m);
      float s = 0.f;
      for (int q=lane;q<C_;q+=32) s += __expf(sco[chn][q]-m);
      s = wsum(s);
      if (lane==0){ mx3[chn]=m; inv3[chn]=1.f/s; }
    }
  }
  __syncthreads();
  const float a0=g_AL[b*3], a1=g_AL[b*3+1], a2=g_AL[b*3+2];
  if (tid < C_){
    float p = 0.01f
      + a0*__expf(sco[0][tid]-mx3[0])*inv3[0]
      + a1*__expf(sco[1][tid]-mx3[1])*inv3[1]
      + a2*__expf(sco[2][tid]-mx3[2])*inv3[2];
    mixv[tid] = p;
  }
  __syncthreads();
  if (warp == 0){
    float s = 0.f;
    for (int q=lane;q<C_;q+=32) s += mixv[q];
    s = wsum(s);
    if (lane==0) sS = 1.f/s;
  }
  __syncthreads();
  if (tid < C_) out[(long)b*C_ + tid] = mixv[tid]*sS;
}

extern "C" void kernel_launch(void* const* d_in, const int* in_sizes, int n_in,
                              void* d_out, int out_size) {
  const int*   sitems = (const int*)  d_in[0];
  const float* ide    = (const float*)d_in[1];
  const float* txe    = (const float*)d_in[2];
  const int*   lens   = (const int*)  d_in[3];
  const int*   cids   = (const int*)  d_in[4];
  const float* cide   = (const float*)d_in[5];
  const float* ctxe   = (const float*)d_in[6];
  const float* co     = (const float*)d_in[7];
  const float* Wih    = (const float*)d_in[8];
  const float* Whh    = (const float*)d_in[9];
  const float* bih    = (const float*)d_in[10];
  const float* bhh    = (const float*)d_in[11];
  const float* Wt1    = (const float*)d_in[12];
  const float* bt1    = (const float*)d_in[13];
  const float* Wt2    = (const float*)d_in[14];
  const float* bt2    = (const float*)d_in[15];
  const float* Wi1    = (const float*)d_in[16];
  const float* bi1    = (const float*)d_in[17];
  const float* Wi2    = (const float*)d_in[18];
  const float* bi2    = (const float*)d_in[19];
  const float* Wa1    = (const float*)d_in[20];
  const float* ba1    = (const float*)d_in[21];
  const float* Wa2    = (const float*)d_in[22];
  const float* ba2    = (const float*)d_in[23];
  // d_in[24] = Wstab: unused (P_stable is uniform = 1/C exactly)
  const float* betac  = (const float*)d_in[25];
  const float* lTc    = (const float*)d_in[26];
  const float* lTt    = (const float*)d_in[27];
  const float* lTi    = (const float*)d_in[28];
  float* out = (float*)d_out;

  const int GRU_SMEM = (49152 + 2048 + 384 + 128 + 128 + 64 + 192 + 4) * 4;
  cudaFuncSetAttribute(k_gruall, cudaFuncAttributeMaxDynamicSharedMemorySize, GRU_SMEM);

  const int WPREP_N = 73728+49152+16384+8192+32768+24576+8192;
  k_wprep<<<(WPREP_N+255)/256, 256>>>(Wih, Whh, Wt1, Wi1, Wa1);
  k_ig<<<80, 256>>>(ide, txe, lens, bih);
  k_gruall<<<128, 256, GRU_SMEM>>>(bhh, ide, txe, lens, sitems,
                                   bt1, bi1, ba1, Wa2, ba2);
  k_score<<<B_, 256>>>(ctxe, cide, cids, co, Wt2, bt2, Wi2, bi2,
                       betac, lTc, lTt, lTi, out);
}

// round 9
// speedup vs baseline: 3.6009x; 1.1926x over previous
#include <cuda_runtime.h>
#include <cuda_bf16.h>
#include <math.h>

#define B_  2048
#define L_  200
#define C_  100
#define V_  2000

// ---------------- scratch ----------------
__device__ float g_IG  [B_*5*384];
__device__ float g_CT  [B_*128];
__device__ float g_CI  [B_*128];
__device__ float g_AL  [B_*3];
__device__ float g_WIHf[73728];        // W_ih (N=384,K=192) tf32 frag order
__device__ float g_WHHf[49152];        // W_hh (N=384,K=128) tf32 frag order
__device__ float g_WCT [32768];        // [Wt1 src | Wt1 h]  (N=128,K=256) tf32 frag
__device__ float g_WCI [24576];        // [Wi1 src | Wi1 h]  (N=128,K=192) tf32 frag
__device__ float g_WA  [8192];         // Wa1 (N=64,K=128) tf32 frag
__device__ unsigned g_WT16[8192];      // Wt1 mid slab bf16 m16n8k16 frag (32KB)
__device__ unsigned g_WI16[4096];      // Wi1 mid slab bf16 m16n8k16 frag (16KB)
__device__ int   g_LI  [B_];

__device__ __forceinline__ float sigf(float x){ return 1.0f/(1.0f+__expf(-x)); }
__device__ __forceinline__ float tanhf_fast(float x){
  x = fminf(fmaxf(x,-15.f),15.f);
  float e = __expf(2.f*x);
  return (e-1.f)/(e+1.f);
}
__device__ __forceinline__ float wsum(float v){
#pragma unroll
  for (int o=16;o;o>>=1) v += __shfl_xor_sync(0xffffffffu, v, o);
  return v;
}
__device__ __forceinline__ float wmax(float v){
#pragma unroll
  for (int o=16;o;o>>=1) v = fmaxf(v, __shfl_xor_sync(0xffffffffu, v, o));
  return v;
}
__device__ __forceinline__ unsigned f2tf(float x){
  unsigned r; asm("cvt.rna.tf32.f32 %0, %1;" : "=r"(r) : "f"(x)); return r;
}
__device__ __forceinline__ unsigned pkbf(float lo, float hi){
  __nv_bfloat162 h = __floats2bfloat162_rn(lo, hi);
  return *(unsigned*)&h;
}
__device__ __forceinline__ void mma8(float* d,
    unsigned a0, unsigned a1, unsigned a2, unsigned a3,
    unsigned b0, unsigned b1){
  asm volatile(
    "mma.sync.aligned.m16n8k8.row.col.f32.tf32.tf32.f32 "
    "{%0,%1,%2,%3},{%4,%5,%6,%7},{%8,%9},{%0,%1,%2,%3};\n"
    : "+f"(d[0]),"+f"(d[1]),"+f"(d[2]),"+f"(d[3])
    : "r"(a0),"r"(a1),"r"(a2),"r"(a3),"r"(b0),"r"(b1));
}
__device__ __forceinline__ void mma16(float* d,
    unsigned a0, unsigned a1, unsigned a2, unsigned a3,
    unsigned b0, unsigned b1){
  asm volatile(
    "mma.sync.aligned.m16n8k16.row.col.f32.bf16.bf16.f32 "
    "{%0,%1,%2,%3},{%4,%5,%6,%7},{%8,%9},{%0,%1,%2,%3};\n"
    : "+f"(d[0]),"+f"(d[1]),"+f"(d[2]),"+f"(d[3])
    : "r"(a0),"r"(a1),"r"(a2),"r"(a3),"r"(b0),"r"(b1));
}

// decode tf32 fragment-order flat index -> (j,k) for weight W[N][K]
__device__ __forceinline__ void frag_jk(int idx, int N, int* jj, int* kk){
  int c = idx & 3, lane = (idx>>2)&31;
  int P = N >> 4;
  int pr = (idx>>7) % P;
  int kt = idx / (128*P);
  int nt = 2*pr + (c>>1), p = c&1;
  *jj = nt*8 + (lane>>2);
  *kk = kt*8 + (lane&3) + 4*p;
}
// decode bf16 m16n8k16 frag (uint4-of-n-pairs) flat uint index -> (j, k0)
__device__ __forceinline__ void frag16_jk(int idx, int* jj, int* kk){
  int w = idx & 3, lane = (idx>>2)&31, n2 = (idx>>7)&7, kt = idx>>10;
  int n = 2*n2 + (w>>1);
  *jj = n*8 + (lane>>2);
  *kk = kt*16 + (lane&3)*2 + (w&1)*8;
}

// ---- prepare all fragment-ordered weights ----
__global__ void k_wprep(const float* __restrict__ Wih, const float* __restrict__ Whh,
                        const float* __restrict__ Wt1, const float* __restrict__ Wi1,
                        const float* __restrict__ Wa1){
  int idx = blockIdx.x*blockDim.x + threadIdx.x;
  int j, k;
  int off = 0;
  if (idx < (off += 73728)){                       // Wih: N=384,K=192
    frag_jk(idx, 384, &j, &k);
    g_WIHf[idx] = __uint_as_float(f2tf(Wih[(long)j*192 + k]));
    return;
  }
  if (idx < (off + 49152)){                        // Whh: N=384,K=128
    int i2 = idx - off;
    frag_jk(i2, 384, &j, &k);
    g_WHHf[i2] = __uint_as_float(f2tf(Whh[(long)j*128 + k]));
    return;
  }
  off += 49152;
  if (idx < (off + 32768)){                        // WCT: N=128,K=256
    int i2 = idx - off;
    frag_jk(i2, 128, &j, &k);
    float v = (k < 128) ? Wt1[(long)j*384 + k] : Wt1[(long)j*384 + 256 + (k-128)];
    g_WCT[i2] = __uint_as_float(f2tf(v));
    return;
  }
  off += 32768;
  if (idx < (off + 24576)){                        // WCI: N=128,K=192
    int i2 = idx - off;
    frag_jk(i2, 128, &j, &k);
    float v = (k < 64) ? Wi1[(long)j*256 + k] : Wi1[(long)j*256 + 128 + (k-64)];
    g_WCI[i2] = __uint_as_float(f2tf(v));
    return;
  }
  off += 24576;
  if (idx < (off + 8192)){                         // WA: N=64,K=128
    int i2 = idx - off;
    frag_jk(i2, 64, &j, &k);
    g_WA[i2] = __uint_as_float(f2tf(Wa1[(long)j*128 + k]));
    return;
  }
  off += 8192;
  if (idx < (off + 8192)){                         // WT16 bf16: N=128,K=128
    int i2 = idx - off;
    frag16_jk(i2, &j, &k);
    g_WT16[i2] = pkbf(Wt1[(long)j*384 + 128 + k], Wt1[(long)j*384 + 128 + k + 1]);
    return;
  }
  off += 8192;
  if (idx < (off + 4096)){                         // WI16 bf16: N=128,K=64
    int i2 = idx - off;
    frag16_jk(i2, &j, &k);
    g_WI16[i2] = pkbf(Wi1[(long)j*256 + 64 + k], Wi1[(long)j*256 + 64 + k + 1]);
    return;
  }
}

// ---- input-gate GEMM (tf32): IG[m][n] = x_m · Wih[n] + bih[n] ----
__global__ __launch_bounds__(256) void k_ig(
    const float* __restrict__ ide, const float* __restrict__ txe,
    const int* __restrict__ lens, const float* __restrict__ bih)
{
  __shared__ float sB[384];
  const int tid = threadIdx.x, warp = tid>>5, lane = tid&31;
  const int g = lane>>2, tig = lane&3;
  for (int i=tid; i<384; i+=256) sB[i] = bih[i];
  const int r0 = blockIdx.x*128 + warp*16 + g;
  const int r1 = r0 + 8;
  int b0 = r0/5, t0 = r0 - 5*b0;  int p0 = lens[b0] - 5 + t0;
  int b1 = r1/5, t1 = r1 - 5*b1;  int p1 = lens[b1] - 5 + t1;
  const float* id0 = ide + ((long)b0*L_ + p0)*64;
  const float* tx0 = txe + ((long)b0*L_ + p0)*128;
  const float* id1 = ide + ((long)b1*L_ + p1)*64;
  const float* tx1 = txe + ((long)b1*L_ + p1)*128;
  __syncthreads();

  const float4* bp = (const float4*)g_WIHf;
  for (int ch=0; ch<3; ch++){
    float acc[16][4];
#pragma unroll
    for (int nt=0;nt<16;nt++){ acc[nt][0]=0.f;acc[nt][1]=0.f;acc[nt][2]=0.f;acc[nt][3]=0.f; }
#pragma unroll
    for (int kt=0;kt<24;kt++){
      int k0 = kt*8 + tig, k4 = k0+4;
      unsigned a0 = f2tf(k0<64 ? id0[k0] : tx0[k0-64]);
      unsigned a2 = f2tf(k4<64 ? id0[k4] : tx0[k4-64]);
      unsigned a1 = f2tf(k0<64 ? id1[k0] : tx1[k0-64]);
      unsigned a3 = f2tf(k4<64 ? id1[k4] : tx1[k4-64]);
#pragma unroll
      for (int n2=0;n2<8;n2++){
        float4 bv = bp[(kt*24 + ch*8 + n2)*32 + lane];
        mma8(acc[2*n2],   a0,a1,a2,a3, __float_as_uint(bv.x), __float_as_uint(bv.y));
        mma8(acc[2*n2+1], a0,a1,a2,a3, __float_as_uint(bv.z), __float_as_uint(bv.w));
      }
    }
#pragma unroll
    for (int nt=0;nt<16;nt++){
      int j = ch*128 + nt*8 + 2*tig;
      float* o0 = g_IG + (long)r0*384 + j;
      float* o1 = g_IG + (long)r1*384 + j;
      o0[0] = acc[nt][0]+sB[j]; o0[1] = acc[nt][1]+sB[j+1];
      o1[0] = acc[nt][2]+sB[j]; o1[1] = acc[nt][3]+sB[j+1];
    }
  }
}

// ---- persistent fused GRU (5 steps) + per-batch prep (ct/ci/alpha) ----
__global__ __launch_bounds__(256) void k_gruall(
    const float* __restrict__ bhh,
    const float* __restrict__ ide, const float* __restrict__ txe,
    const int* __restrict__ lens, const int* __restrict__ sitems,
    const float* __restrict__ bt1, const float* __restrict__ bi1,
    const float* __restrict__ ba1, const float* __restrict__ Wa2,
    const float* __restrict__ ba2)
{
  extern __shared__ float sm[];
  float* sW  = sm;                  // 49152 (W_hh frags; reused after GRU)
  float* sH  = sm + 49152;          // 2048
  float* sB  = sm + 49152+2048;     // 384
  float* sbt = sB + 384;            // 128
  float* sbi = sbt + 128;           // 128
  float* sba = sbi + 128;           // 64
  float* swa2= sba + 64;            // 192
  float* sba2= swa2 + 192;          // 4 (3 used)
  const int tid = threadIdx.x, warp = tid>>5, lane = tid&31;
  const int g = lane>>2, tig = lane&3;
  const int b0 = blockIdx.x*16;

  {
    const float4* gw = (const float4*)g_WHHf;
    float4* swv = (float4*)sW;
    for (int i=tid;i<12288;i+=256) swv[i] = gw[i];
  }
  for (int i=tid;i<384;i+=256) sB[i] = bhh[i];
  if (tid < 128){ sbt[tid] = bt1[tid]; sbi[tid] = bi1[tid]; }
  else if (tid < 192) sba[tid-128] = ba1[tid-128];
  else if (tid < 195) sba2[tid-192] = ba2[tid-192];
  for (int i=tid;i<192;i+=256) swa2[i] = Wa2[i];
  if (tid < 16) g_LI[b0+tid] = sitems[(long)(b0+tid)*L_ + lens[b0+tid]-1];
  __syncthreads();

  // step 0
  for (int i=tid;i<2048;i+=256){
    int bb = i>>7, j = i&127;
    const float* ig = g_IG + ((long)(b0+bb)*5)*384;
    float r = sigf(ig[j]       + sB[j]);
    float z = sigf(ig[128+j]   + sB[128+j]);
    float n = tanhf_fast(ig[256+j] + r*sB[256+j]);
    sH[i] = (1.f - z)*n;
  }
  __syncthreads();

  const float4* swv4 = (const float4*)sW;
  for (int t=1;t<5;t++){
    float acc[3][2][4];
#pragma unroll
    for (int gate=0;gate<3;gate++)
#pragma unroll
      for (int s=0;s<2;s++){ acc[gate][s][0]=0.f;acc[gate][s][1]=0.f;acc[gate][s][2]=0.f;acc[gate][s][3]=0.f; }
#pragma unroll
    for (int kt=0;kt<16;kt++){
      int k0 = kt*8 + tig;
      unsigned a0 = f2tf(sH[g*128     + k0]);
      unsigned a1 = f2tf(sH[(g+8)*128 + k0]);
      unsigned a2 = f2tf(sH[g*128     + k0+4]);
      unsigned a3 = f2tf(sH[(g+8)*128 + k0+4]);
#pragma unroll
      for (int gate=0;gate<3;gate++){
        int pr = gate*8 + warp;
        float4 bv = swv4[(kt*24 + pr)*32 + lane];
        mma8(acc[gate][0], a0,a1,a2,a3, __float_as_uint(bv.x), __float_as_uint(bv.y));
        mma8(acc[gate][1], a0,a1,a2,a3, __float_as_uint(bv.z), __float_as_uint(bv.w));
      }
    }
    __syncthreads();
    const float* ig0 = g_IG + (((long)(b0+g))*5   + t)*384;
    const float* ig1 = g_IG + (((long)(b0+g+8))*5 + t)*384;
#pragma unroll
    for (int s=0;s<2;s++){
#pragma unroll
      for (int cc=0;cc<2;cc++){
        int j = warp*16 + s*8 + tig*2 + cc;
        {
          float r = sigf(ig0[j]       + acc[0][s][cc] + sB[j]);
          float z = sigf(ig0[128+j]   + acc[1][s][cc] + sB[128+j]);
          float n = tanhf_fast(ig0[256+j] + r*(acc[2][s][cc] + sB[256+j]));
          float hp = sH[g*128 + j];
          sH[g*128 + j] = (1.f-z)*n + z*hp;
        }
        {
          float r = sigf(ig1[j]       + acc[0][s][cc+2] + sB[j]);
          float z = sigf(ig1[128+j]   + acc[1][s][cc+2] + sB[128+j]);
          float n = tanhf_fast(ig1[256+j] + r*(acc[2][s][cc+2] + sB[256+j]));
          float hp = sH[(g+8)*128 + j];
          sH[(g+8)*128 + j] = (1.f-z)*n + z*hp;
        }
      }
    }
    __syncthreads();
  }

  // ================= fused per-batch prep =================
  const int L0 = lens[b0+g], L1 = lens[b0+8+g];
  const float* lt0 = txe + ((long)(b0+g)*L_   + L0-1)*128;
  const float* lt1 = txe + ((long)(b0+8+g)*L_ + L1-1)*128;
  const float* li0 = ide + ((long)(b0+g)*L_   + L0-1)*64;
  const float* li1 = ide + ((long)(b0+8+g)*L_ + L1-1)*64;
  const float* h0  = sH + g*128;
  const float* h1  = sH + (g+8)*128;

  // CT: M=16, N=128 (warp w owns n2=w), K=256 = [lt | h]
  {
    float acc[2][4];
    acc[0][0]=0.f;acc[0][1]=0.f;acc[0][2]=0.f;acc[0][3]=0.f;
    acc[1][0]=0.f;acc[1][1]=0.f;acc[1][2]=0.f;acc[1][3]=0.f;
    const float4* bp = (const float4*)g_WCT;
#pragma unroll
    for (int kt=0;kt<32;kt++){
      int k0 = kt*8 + tig, k4 = k0+4;
      unsigned a0 = f2tf(k0<128 ? lt0[k0] : h0[k0-128]);
      unsigned a2 = f2tf(k4<128 ? lt0[k4] : h0[k4-128]);
      unsigned a1 = f2tf(k0<128 ? lt1[k0] : h1[k0-128]);
      unsigned a3 = f2tf(k4<128 ? lt1[k4] : h1[k4-128]);
      float4 bv = bp[(kt*8 + warp)*32 + lane];
      mma8(acc[0], a0,a1,a2,a3, __float_as_uint(bv.x), __float_as_uint(bv.y));
      mma8(acc[1], a0,a1,a2,a3, __float_as_uint(bv.z), __float_as_uint(bv.w));
    }
#pragma unroll
    for (int s=0;s<2;s++){
      int j = (2*warp+s)*8 + 2*tig;
      float* o0 = g_CT + (long)(b0+g)*128 + j;
      float* o1 = g_CT + (long)(b0+8+g)*128 + j;
      o0[0] = acc[s][0]+sbt[j]; o0[1] = acc[s][1]+sbt[j+1];
      o1[0] = acc[s][2]+sbt[j]; o1[1] = acc[s][3]+sbt[j+1];
    }
  }
  // CI: K=192 = [lid | h]
  {
    float acc[2][4];
    acc[0][0]=0.f;acc[0][1]=0.f;acc[0][2]=0.f;acc[0][3]=0.f;
    acc[1][0]=0.f;acc[1][1]=0.f;acc[1][2]=0.f;acc[1][3]=0.f;
    const float4* bp = (const float4*)g_WCI;
#pragma unroll
    for (int kt=0;kt<24;kt++){
      int k0 = kt*8 + tig, k4 = k0+4;
      unsigned a0 = f2tf(k0<64 ? li0[k0] : h0[k0-64]);
      unsigned a2 = f2tf(k4<64 ? li0[k4] : h0[k4-64]);
      unsigned a1 = f2tf(k0<64 ? li1[k0] : h1[k0-64]);
      unsigned a3 = f2tf(k4<64 ? li1[k4] : h1[k4-64]);
      float4 bv = bp[(kt*8 + warp)*32 + lane];
      mma8(acc[0], a0,a1,a2,a3, __float_as_uint(bv.x), __float_as_uint(bv.y));
      mma8(acc[1], a0,a1,a2,a3, __float_as_uint(bv.z), __float_as_uint(bv.w));
    }
#pragma unroll
    for (int s=0;s<2;s++){
      int j = (2*warp+s)*8 + 2*tig;
      float* o0 = g_CI + (long)(b0+g)*128 + j;
      float* o1 = g_CI + (long)(b0+8+g)*128 + j;
      o0[0] = acc[s][0]+sbi[j]; o0[1] = acc[s][1]+sbi[j+1];
      o1[0] = acc[s][2]+sbi[j]; o1[1] = acc[s][3]+sbi[j+1];
    }
  }
  // alpha: N=64 (warps 0-3, n2=warp), K=128 = h ; a1s reuses sW space
  float (*a1s)[64] = (float(*)[64])sW;
  float (*lg)[3]   = (float(*)[3])(sW + 16*64);
  {
    if (warp < 4){
      float acc[2][4];
      acc[0][0]=0.f;acc[0][1]=0.f;acc[0][2]=0.f;acc[0][3]=0.f;
      acc[1][0]=0.f;acc[1][1]=0.f;acc[1][2]=0.f;acc[1][3]=0.f;
      const float4* bp = (const float4*)g_WA;
#pragma unroll
      for (int kt=0;kt<16;kt++){
        int k0 = kt*8 + tig;
        unsigned a0 = f2tf(h0[k0]), a2 = f2tf(h0[k0+4]);
        unsigned a1 = f2tf(h1[k0]), a3 = f2tf(h1[k0+4]);
        float4 bv = bp[(kt*4 + warp)*32 + lane];
        mma8(acc[0], a0,a1,a2,a3, __float_as_uint(bv.x), __float_as_uint(bv.y));
        mma8(acc[1], a0,a1,a2,a3, __float_as_uint(bv.z), __float_as_uint(bv.w));
      }
#pragma unroll
      for (int s=0;s<2;s++){
        int u = (2*warp+s)*8 + 2*tig;
        a1s[g][u]     = fmaxf(acc[s][0]+sba[u],0.f);
        a1s[g][u+1]   = fmaxf(acc[s][1]+sba[u+1],0.f);
        a1s[g+8][u]   = fmaxf(acc[s][2]+sba[u],0.f);
        a1s[g+8][u+1] = fmaxf(acc[s][3]+sba[u+1],0.f);
      }
    }
    __syncthreads();
    if (tid < 48){
      int bb = tid/3, gg = tid%3;
      float s = sba2[gg];
      const float* w = swa2 + gg*64;
      for (int u=0;u<64;u++) s += w[u]*a1s[bb][u];
      lg[bb][gg] = s;
    }
    __syncthreads();
    if (tid < 16){
      float l0=lg[tid][0], l1=lg[tid][1], l2=lg[tid][2];
      float m = fmaxf(l0, fmaxf(l1,l2));
      float e0=__expf(l0-m), e1=__expf(l1-m), e2=__expf(l2-m);
      float inv = 1.f/(e0+e1+e2);
      g_AL[(b0+tid)*3+0]=e0*inv; g_AL[(b0+tid)*3+1]=e1*inv; g_AL[(b0+tid)*3+2]=e2*inv;
    }
  }
}

// ---- fused scorer (bf16 m16n8k16) + softmaxes + mix: one block per batch ----
__global__ __launch_bounds__(256) void k_score(
    const float* __restrict__ ctxe, const float* __restrict__ cide,
    const int* __restrict__ cids, const float* __restrict__ co,
    const float* __restrict__ Wt2, const float* __restrict__ bt2,
    const float* __restrict__ Wi2, const float* __restrict__ bi2,
    const float* __restrict__ betac, const float* __restrict__ lTc,
    const float* __restrict__ lTt, const float* __restrict__ lTi,
    float* __restrict__ out)
{
  __shared__ float ctv[128], civ[128], w2t[128], w2i[128];
  __shared__ float sco[3][128];
  __shared__ float mx3[3], inv3[3], sS;
  __shared__ float mixv[128];
  const int b = blockIdx.x, tid = threadIdx.x;
  const int warp = tid>>5, lane = tid&31;
  const int g = lane>>2, tig = lane&3;
  const int r0 = warp*16 + g, r1 = r0 + 8;

  if (tid < 128){
    ctv[tid]=g_CT[b*128+tid]; civ[tid]=g_CI[b*128+tid];
    w2t[tid]=Wt2[tid];        w2i[tid]=Wi2[tid];
  }
  if (tid < 100){
    long li = g_LI[b];
    sco[0][tid] = co[li*V_ + cids[(long)b*C_+tid]] * betac[0] / expf(lTc[0]);
  }
  const float Tt = expf(lTt[0]), Ti = expf(lTi[0]);
  __syncthreads();

  // text pass: M=128(pad 100) x N=128 x K=128, bf16 k16
  {
    float acc[16][4];
#pragma unroll
    for (int nt=0;nt<16;nt++){ acc[nt][0]=0.f;acc[nt][1]=0.f;acc[nt][2]=0.f;acc[nt][3]=0.f; }
    const float* Eb = ctxe + (long)b*C_*128;
    const uint4* bp = (const uint4*)g_WT16;
#pragma unroll
    for (int kt=0;kt<8;kt++){
      const int k0 = kt*16 + tig*2;
      unsigned a0=0u,a1=0u,a2=0u,a3=0u;
      if (r0 < C_){
        float2 x = *(const float2*)(Eb + (long)r0*128 + k0);
        float2 y = *(const float2*)(Eb + (long)r0*128 + k0 + 8);
        a0 = pkbf(x.x,x.y); a2 = pkbf(y.x,y.y);
      }
      if (r1 < C_){
        float2 x = *(const float2*)(Eb + (long)r1*128 + k0);
        float2 y = *(const float2*)(Eb + (long)r1*128 + k0 + 8);
        a1 = pkbf(x.x,x.y); a3 = pkbf(y.x,y.y);
      }
#pragma unroll
      for (int n2=0;n2<8;n2++){
        uint4 bv = bp[(kt*8 + n2)*32 + lane];
        mma16(acc[2*n2],   a0,a1,a2,a3, bv.x, bv.y);
        mma16(acc[2*n2+1], a0,a1,a2,a3, bv.z, bv.w);
      }
    }
    float p0=0.f, p1=0.f;
#pragma unroll
    for (int nt=0;nt<16;nt++){
      int j0 = nt*8 + 2*tig;
      float w0=w2t[j0], w1=w2t[j0+1], c0=ctv[j0], c1=ctv[j0+1];
      p0 += w0*fmaxf(c0+acc[nt][0],0.f) + w1*fmaxf(c1+acc[nt][1],0.f);
      p1 += w0*fmaxf(c0+acc[nt][2],0.f) + w1*fmaxf(c1+acc[nt][3],0.f);
    }
    p0 += __shfl_xor_sync(0xffffffffu,p0,1); p0 += __shfl_xor_sync(0xffffffffu,p0,2);
    p1 += __shfl_xor_sync(0xffffffffu,p1,1); p1 += __shfl_xor_sync(0xffffffffu,p1,2);
    if (tig==0){
      if (r0 < C_) sco[1][r0] = (p0 + bt2[0]) / Tt;
      if (r1 < C_) sco[1][r1] = (p1 + bt2[0]) / Tt;
    }
  }
  // id pass: K=64, bf16 k16
  {
    float acc[16][4];
#pragma unroll
    for (int nt=0;nt<16;nt++){ acc[nt][0]=0.f;acc[nt][1]=0.f;acc[nt][2]=0.f;acc[nt][3]=0.f; }
    const float* Eb = cide + (long)b*C_*64;
    const uint4* bp = (const uint4*)g_WI16;
#pragma unroll
    for (int kt=0;kt<4;kt++){
      const int k0 = kt*16 + tig*2;
      unsigned a0=0u,a1=0u,a2=0u,a3=0u;
      if (r0 < C_){
        float2 x = *(const float2*)(Eb + (long)r0*64 + k0);
        float2 y = *(const float2*)(Eb + (long)r0*64 + k0 + 8);
        a0 = pkbf(x.x,x.y); a2 = pkbf(y.x,y.y);
      }
      if (r1 < C_){
        float2 x = *(const float2*)(Eb + (long)r1*64 + k0);
        float2 y = *(const float2*)(Eb + (long)r1*64 + k0 + 8);
        a1 = pkbf(x.x,x.y); a3 = pkbf(y.x,y.y);
      }
#pragma unroll
      for (int n2=0;n2<8;n2++){
        uint4 bv = bp[(kt*8 + n2)*32 + lane];
        mma16(acc[2*n2],   a0,a1,a2,a3, bv.x, bv.y);
        mma16(acc[2*n2+1], a0,a1,a2,a3, bv.z, bv.w);
      }
    }
    float p0=0.f, p1=0.f;
#pragma unroll
    for (int nt=0;nt<16;nt++){
      int j0 = nt*8 + 2*tig;
      float w0=w2i[j0], w1=w2i[j0+1], c0=civ[j0], c1=civ[j0+1];
      p0 += w0*fmaxf(c0+acc[nt][0],0.f) + w1*fmaxf(c1+acc[nt][1],0.f);
      p1 += w0*fmaxf(c0+acc[nt][2],0.f) + w1*fmaxf(c1+acc[nt][3],0.f);
    }
    p0 += __shfl_xor_sync(0xffffffffu,p0,1); p0 += __shfl_xor_sync(0xffffffffu,p0,2);
    p1 += __shfl_xor_sync(0xffffffffu,p1,1); p1 += __shfl_xor_sync(0xffffffffu,p1,2);
    if (tig==0){
      if (r0 < C_) sco[2][r0] = (p0 + bi2[0]) / Ti;
      if (r1 < C_) sco[2][r1] = (p1 + bi2[0]) / Ti;
    }
  }
  __syncthreads();

  if (warp == 0){
#pragma unroll
    for (int chn=0;chn<3;chn++){
      float m = -1e30f;
      for (int q=lane;q<C_;q+=32) m = fmaxf(m, sco[chn][q]);
      m = wmax(m);
      float s = 0.f;
      for (int q=lane;q<C_;q+=32) s += __expf(sco[chn][q]-m);
      s = wsum(s);
      if (lane==0){ mx3[chn]=m; inv3[chn]=1.f/s; }
    }
  }
  __syncthreads();
  const float a0=g_AL[b*3], a1=g_AL[b*3+1], a2=g_AL[b*3+2];
  if (tid < C_){
    float p = 0.01f
      + a0*__expf(sco[0][tid]-mx3[0])*inv3[0]
      + a1*__expf(sco[1][tid]-mx3[1])*inv3[1]
      + a2*__expf(sco[2][tid]-mx3[2])*inv3[2];
    mixv[tid] = p;
  }
  __syncthreads();
  if (warp == 0){
    float s = 0.f;
    for (int q=lane;q<C_;q+=32) s += mixv[q];
    s = wsum(s);
    if (lane==0) sS = 1.f/s;
  }
  __syncthreads();
  if (tid < C_) out[(long)b*C_ + tid] = mixv[tid]*sS;
}

extern "C" void kernel_launch(void* const* d_in, const int* in_sizes, int n_in,
                              void* d_out, int out_size) {
  const int*   sitems = (const int*)  d_in[0];
  const float* ide    = (const float*)d_in[1];
  const float* txe    = (const float*)d_in[2];
  const int*   lens   = (const int*)  d_in[3];
  const int*   cids   = (const int*)  d_in[4];
  const float* cide   = (const float*)d_in[5];
  const float* ctxe   = (const float*)d_in[6];
  const float* co     = (const float*)d_in[7];
  const float* Wih    = (const float*)d_in[8];
  const float* Whh    = (const float*)d_in[9];
  const float* bih    = (const float*)d_in[10];
  const float* bhh    = (const float*)d_in[11];
  const float* Wt1    = (const float*)d_in[12];
  const float* bt1    = (const float*)d_in[13];
  const float* Wt2    = (const float*)d_in[14];
  const float* bt2    = (const float*)d_in[15];
  const float* Wi1    = (const float*)d_in[16];
  const float* bi1    = (const float*)d_in[17];
  const float* Wi2    = (const float*)d_in[18];
  const float* bi2    = (const float*)d_in[19];
  const float* Wa1    = (const float*)d_in[20];
  const float* ba1    = (const float*)d_in[21];
  const float* Wa2    = (const float*)d_in[22];
  const float* ba2    = (const float*)d_in[23];
  // d_in[24] = Wstab: unused (P_stable is uniform = 1/C exactly)
  const float* betac  = (const float*)d_in[25];
  const float* lTc    = (const float*)d_in[26];
  const float* lTt    = (const float*)d_in[27];
  const float* lTi    = (const float*)d_in[28];
  float* out = (float*)d_out;

  const int GRU_SMEM = (49152 + 2048 + 384 + 128 + 128 + 64 + 192 + 4) * 4;
  cudaFuncSetAttribute(k_gruall, cudaFuncAttributeMaxDynamicSharedMemorySize, GRU_SMEM);

  const int WPREP_N = 73728+49152+32768+24576+8192+8192+4096;
  k_wprep<<<(WPREP_N+255)/256, 256>>>(Wih, Whh, Wt1, Wi1, Wa1);
  k_ig<<<80, 256>>>(ide, txe, lens, bih);
  k_gruall<<<128, 256, GRU_SMEM>>>(bhh, ide, txe, lens, sitems,
                                   bt1, bi1, ba1, Wa2, ba2);
  k_score<<<B_, 256>>>(ctxe, cide, cids, co, Wt2, bt2, Wi2, bi2,
                       betac, lTc, lTt, lTi, out);
}

// round 10
// speedup vs baseline: 3.6341x; 1.0092x over previous
#include <cuda_runtime.h>
#include <cuda_bf16.h>
#include <math.h>

#define B_  2048
#define L_  200
#define C_  100
#define V_  2000

// ---------------- scratch ----------------
__device__ float g_IG  [B_*5*384];
__device__ float g_CT  [B_*128];
__device__ float g_CI  [B_*128];
__device__ float g_AL  [B_*3];
__device__ float g_WIHf[73728];        // W_ih (N=384,K=192) tf32 frag order
__device__ float g_WHHf[49152];        // W_hh (N=384,K=128) tf32 frag order
__device__ float g_WCT [32768];        // [Wt1 src | Wt1 h]  (N=128,K=256) tf32 frag
__device__ float g_WCI [24576];        // [Wi1 src | Wi1 h]  (N=128,K=192) tf32 frag
__device__ float g_WA  [8192];         // Wa1 (N=64,K=128) tf32 frag
__device__ unsigned g_WT16[8192];      // Wt1 mid slab bf16 m16n8k16 frag (32KB)
__device__ unsigned g_WI16[4096];      // Wi1 mid slab bf16 m16n8k16 frag (16KB)
__device__ int   g_LI  [B_];

__device__ __forceinline__ float sigf(float x){ return 1.0f/(1.0f+__expf(-x)); }
__device__ __forceinline__ float tanhf_fast(float x){
  x = fminf(fmaxf(x,-15.f),15.f);
  float e = __expf(2.f*x);
  return (e-1.f)/(e+1.f);
}
__device__ __forceinline__ float wsum(float v){
#pragma unroll
  for (int o=16;o;o>>=1) v += __shfl_xor_sync(0xffffffffu, v, o);
  return v;
}
__device__ __forceinline__ float wmax(float v){
#pragma unroll
  for (int o=16;o;o>>=1) v = fmaxf(v, __shfl_xor_sync(0xffffffffu, v, o));
  return v;
}
__device__ __forceinline__ unsigned f2tf(float x){
  unsigned r; asm("cvt.rna.tf32.f32 %0, %1;" : "=r"(r) : "f"(x)); return r;
}
__device__ __forceinline__ unsigned pkbf(float lo, float hi){
  __nv_bfloat162 h = __floats2bfloat162_rn(lo, hi);
  return *(unsigned*)&h;
}
__device__ __forceinline__ void mma8(float* d,
    unsigned a0, unsigned a1, unsigned a2, unsigned a3,
    unsigned b0, unsigned b1){
  asm volatile(
    "mma.sync.aligned.m16n8k8.row.col.f32.tf32.tf32.f32 "
    "{%0,%1,%2,%3},{%4,%5,%6,%7},{%8,%9},{%0,%1,%2,%3};\n"
    : "+f"(d[0]),"+f"(d[1]),"+f"(d[2]),"+f"(d[3])
    : "r"(a0),"r"(a1),"r"(a2),"r"(a3),"r"(b0),"r"(b1));
}
__device__ __forceinline__ void mma16(float* d,
    unsigned a0, unsigned a1, unsigned a2, unsigned a3,
    unsigned b0, unsigned b1){
  asm volatile(
    "mma.sync.aligned.m16n8k16.row.col.f32.bf16.bf16.f32 "
    "{%0,%1,%2,%3},{%4,%5,%6,%7},{%8,%9},{%0,%1,%2,%3};\n"
    : "+f"(d[0]),"+f"(d[1]),"+f"(d[2]),"+f"(d[3])
    : "r"(a0),"r"(a1),"r"(a2),"r"(a3),"r"(b0),"r"(b1));
}

// decode tf32 fragment-order flat index -> (j,k) for weight W[N][K]
__device__ __forceinline__ void frag_jk(int idx, int N, int* jj, int* kk){
  int c = idx & 3, lane = (idx>>2)&31;
  int P = N >> 4;
  int pr = (idx>>7) % P;
  int kt = idx / (128*P);
  int nt = 2*pr + (c>>1), p = c&1;
  *jj = nt*8 + (lane>>2);
  *kk = kt*8 + (lane&3) + 4*p;
}
// decode bf16 m16n8k16 frag (uint4-of-n-pairs) flat uint index -> (j, k0)
__device__ __forceinline__ void frag16_jk(int idx, int* jj, int* kk){
  int w = idx & 3, lane = (idx>>2)&31, n2 = (idx>>7)&7, kt = idx>>10;
  int n = 2*n2 + (w>>1);
  *jj = n*8 + (lane>>2);
  *kk = kt*16 + (lane&3)*2 + (w&1)*8;
}

// ---- prepare all fragment-ordered weights ----
__global__ void k_wprep(const float* __restrict__ Wih, const float* __restrict__ Whh,
                        const float* __restrict__ Wt1, const float* __restrict__ Wi1,
                        const float* __restrict__ Wa1){
  int idx = blockIdx.x*blockDim.x + threadIdx.x;
  int j, k;
  int off = 0;
  if (idx < (off += 73728)){                       // Wih: N=384,K=192
    frag_jk(idx, 384, &j, &k);
    g_WIHf[idx] = __uint_as_float(f2tf(Wih[(long)j*192 + k]));
    return;
  }
  if (idx < (off + 49152)){                        // Whh: N=384,K=128
    int i2 = idx - off;
    frag_jk(i2, 384, &j, &k);
    g_WHHf[i2] = __uint_as_float(f2tf(Whh[(long)j*128 + k]));
    return;
  }
  off += 49152;
  if (idx < (off + 32768)){                        // WCT: N=128,K=256
    int i2 = idx - off;
    frag_jk(i2, 128, &j, &k);
    float v = (k < 128) ? Wt1[(long)j*384 + k] : Wt1[(long)j*384 + 256 + (k-128)];
    g_WCT[i2] = __uint_as_float(f2tf(v));
    return;
  }
  off += 32768;
  if (idx < (off + 24576)){                        // WCI: N=128,K=192
    int i2 = idx - off;
    frag_jk(i2, 128, &j, &k);
    float v = (k < 64) ? Wi1[(long)j*256 + k] : Wi1[(long)j*256 + 128 + (k-64)];
    g_WCI[i2] = __uint_as_float(f2tf(v));
    return;
  }
  off += 24576;
  if (idx < (off + 8192)){                         // WA: N=64,K=128
    int i2 = idx - off;
    frag_jk(i2, 64, &j, &k);
    g_WA[i2] = __uint_as_float(f2tf(Wa1[(long)j*128 + k]));
    return;
  }
  off += 8192;
  if (idx < (off + 8192)){                         // WT16 bf16: N=128,K=128
    int i2 = idx - off;
    frag16_jk(i2, &j, &k);
    g_WT16[i2] = pkbf(Wt1[(long)j*384 + 128 + k], Wt1[(long)j*384 + 128 + k + 1]);
    return;
  }
  off += 8192;
  if (idx < (off + 4096)){                         // WI16 bf16: N=128,K=64
    int i2 = idx - off;
    frag16_jk(i2, &j, &k);
    g_WI16[i2] = pkbf(Wi1[(long)j*256 + 64 + k], Wi1[(long)j*256 + 64 + k + 1]);
    return;
  }
}

// ---- input-gate GEMM (tf32): IG[m][n] = x_m · Wih[n] + bih[n] ----
// grid = (80, 3): blockIdx.y selects the 128-wide gate chunk
__global__ __launch_bounds__(256) void k_ig(
    const float* __restrict__ ide, const float* __restrict__ txe,
    const int* __restrict__ lens, const float* __restrict__ bih)
{
  __shared__ float sB[384];
  const int tid = threadIdx.x, warp = tid>>5, lane = tid&31;
  const int g = lane>>2, tig = lane&3;
  const int ch = blockIdx.y;
  for (int i=tid; i<384; i+=256) sB[i] = bih[i];
  const int r0 = blockIdx.x*128 + warp*16 + g;
  const int r1 = r0 + 8;
  int b0 = r0/5, t0 = r0 - 5*b0;  int p0 = lens[b0] - 5 + t0;
  int b1 = r1/5, t1 = r1 - 5*b1;  int p1 = lens[b1] - 5 + t1;
  const float* id0 = ide + ((long)b0*L_ + p0)*64;
  const float* tx0 = txe + ((long)b0*L_ + p0)*128;
  const float* id1 = ide + ((long)b1*L_ + p1)*64;
  const float* tx1 = txe + ((long)b1*L_ + p1)*128;
  __syncthreads();

  const float4* bp = (const float4*)g_WIHf;
  float acc[16][4];
#pragma unroll
  for (int nt=0;nt<16;nt++){ acc[nt][0]=0.f;acc[nt][1]=0.f;acc[nt][2]=0.f;acc[nt][3]=0.f; }
#pragma unroll
  for (int kt=0;kt<24;kt++){
    int k0 = kt*8 + tig, k4 = k0+4;
    unsigned a0 = f2tf(k0<64 ? id0[k0] : tx0[k0-64]);
    unsigned a2 = f2tf(k4<64 ? id0[k4] : tx0[k4-64]);
    unsigned a1 = f2tf(k0<64 ? id1[k0] : tx1[k0-64]);
    unsigned a3 = f2tf(k4<64 ? id1[k4] : tx1[k4-64]);
#pragma unroll
    for (int n2=0;n2<8;n2++){
      float4 bv = bp[(kt*24 + ch*8 + n2)*32 + lane];
      mma8(acc[2*n2],   a0,a1,a2,a3, __float_as_uint(bv.x), __float_as_uint(bv.y));
      mma8(acc[2*n2+1], a0,a1,a2,a3, __float_as_uint(bv.z), __float_as_uint(bv.w));
    }
  }
#pragma unroll
  for (int nt=0;nt<16;nt++){
    int j = ch*128 + nt*8 + 2*tig;
    float* o0 = g_IG + (long)r0*384 + j;
    float* o1 = g_IG + (long)r1*384 + j;
    o0[0] = acc[nt][0]+sB[j]; o0[1] = acc[nt][1]+sB[j+1];
    o1[0] = acc[nt][2]+sB[j]; o1[1] = acc[nt][3]+sB[j+1];
  }
}

// ---- persistent fused GRU (5 steps) + per-batch prep (ct/ci/alpha) ----
__global__ __launch_bounds__(256) void k_gruall(
    const float* __restrict__ bhh,
    const float* __restrict__ ide, const float* __restrict__ txe,
    const int* __restrict__ lens, const int* __restrict__ sitems,
    const float* __restrict__ bt1, const float* __restrict__ bi1,
    const float* __restrict__ ba1, const float* __restrict__ Wa2,
    const float* __restrict__ ba2)
{
  extern __shared__ float sm[];
  float* sW  = sm;                  // 49152 (W_hh frags; reused after GRU)
  float* sH  = sm + 49152;          // 2048
  float* sB  = sm + 49152+2048;     // 384
  float* sbt = sB + 384;            // 128
  float* sbi = sbt + 128;           // 128
  float* sba = sbi + 128;           // 64
  float* swa2= sba + 64;            // 192
  float* sba2= swa2 + 192;          // 4 (3 used)
  const int tid = threadIdx.x, warp = tid>>5, lane = tid&31;
  const int g = lane>>2, tig = lane&3;
  const int b0 = blockIdx.x*16;

  {
    const float4* gw = (const float4*)g_WHHf;
    float4* swv = (float4*)sW;
    for (int i=tid;i<12288;i+=256) swv[i] = gw[i];
  }
  for (int i=tid;i<384;i+=256) sB[i] = bhh[i];
  if (tid < 128){ sbt[tid] = bt1[tid]; sbi[tid] = bi1[tid]; }
  else if (tid < 192) sba[tid-128] = ba1[tid-128];
  else if (tid < 195) sba2[tid-192] = ba2[tid-192];
  for (int i=tid;i<192;i+=256) swa2[i] = Wa2[i];
  if (tid < 16) g_LI[b0+tid] = sitems[(long)(b0+tid)*L_ + lens[b0+tid]-1];
  __syncthreads();

  // step 0
  for (int i=tid;i<2048;i+=256){
    int bb = i>>7, j = i&127;
    const float* ig = g_IG + ((long)(b0+bb)*5)*384;
    float r = sigf(ig[j]       + sB[j]);
    float z = sigf(ig[128+j]   + sB[128+j]);
    float n = tanhf_fast(ig[256+j] + r*sB[256+j]);
    sH[i] = (1.f - z)*n;
  }
  __syncthreads();

  const float4* swv4 = (const float4*)sW;
  for (int t=1;t<5;t++){
    float acc[3][2][4];
#pragma unroll
    for (int gate=0;gate<3;gate++)
#pragma unroll
      for (int s=0;s<2;s++){ acc[gate][s][0]=0.f;acc[gate][s][1]=0.f;acc[gate][s][2]=0.f;acc[gate][s][3]=0.f; }
#pragma unroll
    for (int kt=0;kt<16;kt++){
      int k0 = kt*8 + tig;
      unsigned a0 = f2tf(sH[g*128     + k0]);
      unsigned a1 = f2tf(sH[(g+8)*128 + k0]);
      unsigned a2 = f2tf(sH[g*128     + k0+4]);
      unsigned a3 = f2tf(sH[(g+8)*128 + k0+4]);
#pragma unroll
      for (int gate=0;gate<3;gate++){
        int pr = gate*8 + warp;
        float4 bv = swv4[(kt*24 + pr)*32 + lane];
        mma8(acc[gate][0], a0,a1,a2,a3, __float_as_uint(bv.x), __float_as_uint(bv.y));
        mma8(acc[gate][1], a0,a1,a2,a3, __float_as_uint(bv.z), __float_as_uint(bv.w));
      }
    }
    __syncthreads();
    const float* ig0 = g_IG + (((long)(b0+g))*5   + t)*384;
    const float* ig1 = g_IG + (((long)(b0+g+8))*5 + t)*384;
#pragma unroll
    for (int s=0;s<2;s++){
#pragma unroll
      for (int cc=0;cc<2;cc++){
        int j = warp*16 + s*8 + tig*2 + cc;
        {
          float r = sigf(ig0[j]       + acc[0][s][cc] + sB[j]);
          float z = sigf(ig0[128+j]   + acc[1][s][cc] + sB[128+j]);
          float n = tanhf_fast(ig0[256+j] + r*(acc[2][s][cc] + sB[256+j]));
          float hp = sH[g*128 + j];
          sH[g*128 + j] = (1.f-z)*n + z*hp;
        }
        {
          float r = sigf(ig1[j]       + acc[0][s][cc+2] + sB[j]);
          float z = sigf(ig1[128+j]   + acc[1][s][cc+2] + sB[128+j]);
          float n = tanhf_fast(ig1[256+j] + r*(acc[2][s][cc+2] + sB[256+j]));
          float hp = sH[(g+8)*128 + j];
          sH[(g+8)*128 + j] = (1.f-z)*n + z*hp;
        }
      }
    }
    __syncthreads();
  }

  // ================= fused per-batch prep =================
  const int L0 = lens[b0+g], L1 = lens[b0+8+g];
  const float* lt0 = txe + ((long)(b0+g)*L_   + L0-1)*128;
  const float* lt1 = txe + ((long)(b0+8+g)*L_ + L1-1)*128;
  const float* li0 = ide + ((long)(b0+g)*L_   + L0-1)*64;
  const float* li1 = ide + ((long)(b0+8+g)*L_ + L1-1)*64;
  const float* h0  = sH + g*128;
  const float* h1  = sH + (g+8)*128;

  // CT: M=16, N=128 (warp w owns n2=w), K=256 = [lt | h]
  {
    float acc[2][4];
    acc[0][0]=0.f;acc[0][1]=0.f;acc[0][2]=0.f;acc[0][3]=0.f;
    acc[1][0]=0.f;acc[1][1]=0.f;acc[1][2]=0.f;acc[1][3]=0.f;
    const float4* bp = (const float4*)g_WCT;
#pragma unroll
    for (int kt=0;kt<32;kt++){
      int k0 = kt*8 + tig, k4 = k0+4;
      unsigned a0 = f2tf(k0<128 ? lt0[k0] : h0[k0-128]);
      unsigned a2 = f2tf(k4<128 ? lt0[k4] : h0[k4-128]);
      unsigned a1 = f2tf(k0<128 ? lt1[k0] : h1[k0-128]);
      unsigned a3 = f2tf(k4<128 ? lt1[k4] : h1[k4-128]);
      float4 bv = bp[(kt*8 + warp)*32 + lane];
      mma8(acc[0], a0,a1,a2,a3, __float_as_uint(bv.x), __float_as_uint(bv.y));
      mma8(acc[1], a0,a1,a2,a3, __float_as_uint(bv.z), __float_as_uint(bv.w));
    }
#pragma unroll
    for (int s=0;s<2;s++){
      int j = (2*warp+s)*8 + 2*tig;
      float* o0 = g_CT + (long)(b0+g)*128 + j;
      float* o1 = g_CT + (long)(b0+8+g)*128 + j;
      o0[0] = acc[s][0]+sbt[j]; o0[1] = acc[s][1]+sbt[j+1];
      o1[0] = acc[s][2]+sbt[j]; o1[1] = acc[s][3]+sbt[j+1];
    }
  }
  // CI: K=192 = [lid | h]
  {
    float acc[2][4];
    acc[0][0]=0.f;acc[0][1]=0.f;acc[0][2]=0.f;acc[0][3]=0.f;
    acc[1][0]=0.f;acc[1][1]=0.f;acc[1][2]=0.f;acc[1][3]=0.f;
    const float4* bp = (const float4*)g_WCI;
#pragma unroll
    for (int kt=0;kt<24;kt++){
      int k0 = kt*8 + tig, k4 = k0+4;
      unsigned a0 = f2tf(k0<64 ? li0[k0] : h0[k0-64]);
      unsigned a2 = f2tf(k4<64 ? li0[k4] : h0[k4-64]);
      unsigned a1 = f2tf(k0<64 ? li1[k0] : h1[k0-64]);
      unsigned a3 = f2tf(k4<64 ? li1[k4] : h1[k4-64]);
      float4 bv = bp[(kt*8 + warp)*32 + lane];
      mma8(acc[0], a0,a1,a2,a3, __float_as_uint(bv.x), __float_as_uint(bv.y));
      mma8(acc[1], a0,a1,a2,a3, __float_as_uint(bv.z), __float_as_uint(bv.w));
    }
#pragma unroll
    for (int s=0;s<2;s++){
      int j = (2*warp+s)*8 + 2*tig;
      float* o0 = g_CI + (long)(b0+g)*128 + j;
      float* o1 = g_CI + (long)(b0+8+g)*128 + j;
      o0[0] = acc[s][0]+sbi[j]; o0[1] = acc[s][1]+sbi[j+1];
      o1[0] = acc[s][2]+sbi[j]; o1[1] = acc[s][3]+sbi[j+1];
    }
  }
  // alpha: N=64 (warps 0-3, n2=warp), K=128 = h ; a1s reuses sW space
  float (*a1s)[64] = (float(*)[64])sW;
  float (*lg)[3]   = (float(*)[3])(sW + 16*64);
  {
    if (warp < 4){
      float acc[2][4];
      acc[0][0]=0.f;acc[0][1]=0.f;acc[0][2]=0.f;acc[0][3]=0.f;
      acc[1][0]=0.f;acc[1][1]=0.f;acc[1][2]=0.f;acc[1][3]=0.f;
      const float4* bp = (const float4*)g_WA;
#pragma unroll
      for (int kt=0;kt<16;kt++){
        int k0 = kt*8 + tig;
        unsigned a0 = f2tf(h0[k0]), a2 = f2tf(h0[k0+4]);
        unsigned a1 = f2tf(h1[k0]), a3 = f2tf(h1[k0+4]);
        float4 bv = bp[(kt*4 + warp)*32 + lane];
        mma8(acc[0], a0,a1,a2,a3, __float_as_uint(bv.x), __float_as_uint(bv.y));
        mma8(acc[1], a0,a1,a2,a3, __float_as_uint(bv.z), __float_as_uint(bv.w));
      }
#pragma unroll
      for (int s=0;s<2;s++){
        int u = (2*warp+s)*8 + 2*tig;
        a1s[g][u]     = fmaxf(acc[s][0]+sba[u],0.f);
        a1s[g][u+1]   = fmaxf(acc[s][1]+sba[u+1],0.f);
        a1s[g+8][u]   = fmaxf(acc[s][2]+sba[u],0.f);
        a1s[g+8][u+1] = fmaxf(acc[s][3]+sba[u+1],0.f);
      }
    }
    __syncthreads();
    if (tid < 48){
      int bb = tid/3, gg = tid%3;
      float s = sba2[gg];
      const float* w = swa2 + gg*64;
      for (int u=0;u<64;u++) s += w[u]*a1s[bb][u];
      lg[bb][gg] = s;
    }
    __syncthreads();
    if (tid < 16){
      float l0=lg[tid][0], l1=lg[tid][1], l2=lg[tid][2];
      float m = fmaxf(l0, fmaxf(l1,l2));
      float e0=__expf(l0-m), e1=__expf(l1-m), e2=__expf(l2-m);
      float inv = 1.f/(e0+e1+e2);
      g_AL[(b0+tid)*3+0]=e0*inv; g_AL[(b0+tid)*3+1]=e1*inv; g_AL[(b0+tid)*3+2]=e2*inv;
    }
  }
}

// ---- fused scorer (bf16 m16n8k16, A prefetched for MLP) ----
__global__ __launch_bounds__(256, 2) void k_score(
    const float* __restrict__ ctxe, const float* __restrict__ cide,
    const int* __restrict__ cids, const float* __restrict__ co,
    const float* __restrict__ Wt2, const float* __restrict__ bt2,
    const float* __restrict__ Wi2, const float* __restrict__ bi2,
    const float* __restrict__ betac, const float* __restrict__ lTc,
    const float* __restrict__ lTt, const float* __restrict__ lTi,
    float* __restrict__ out)
{
  __shared__ float ctv[128], civ[128], w2t[128], w2i[128];
  __shared__ float sco[3][128];
  __shared__ float mx3[3], inv3[3], sS;
  __shared__ float mixv[128];
  const int b = blockIdx.x, tid = threadIdx.x;
  const int warp = tid>>5, lane = tid&31;
  const int g = lane>>2, tig = lane&3;
  const int r0 = warp*16 + g, r1 = r0 + 8;

  if (tid < 128){
    ctv[tid]=g_CT[b*128+tid]; civ[tid]=g_CI[b*128+tid];
    w2t[tid]=Wt2[tid];        w2i[tid]=Wi2[tid];
  }
  if (tid < 100){
    long li = g_LI[b];
    sco[0][tid] = co[li*V_ + cids[(long)b*C_+tid]] * betac[0] / expf(lTc[0]);
  }
  const float Tt = expf(lTt[0]), Ti = expf(lTi[0]);
  __syncthreads();

  // text pass: M=128(pad 100) x N=128 x K=128, bf16 k16; A prefetched
  {
    float acc[16][4];
#pragma unroll
    for (int nt=0;nt<16;nt++){ acc[nt][0]=0.f;acc[nt][1]=0.f;acc[nt][2]=0.f;acc[nt][3]=0.f; }
    const float* Eb = ctxe + (long)b*C_*128;
    unsigned aT[8][4];
#pragma unroll
    for (int kt=0;kt<8;kt++){
      const int k0 = kt*16 + tig*2;
      aT[kt][0]=0u; aT[kt][1]=0u; aT[kt][2]=0u; aT[kt][3]=0u;
      if (r0 < C_){
        float2 x = *(const float2*)(Eb + (long)r0*128 + k0);
        float2 y = *(const float2*)(Eb + (long)r0*128 + k0 + 8);
        aT[kt][0] = pkbf(x.x,x.y); aT[kt][2] = pkbf(y.x,y.y);
      }
      if (r1 < C_){
        float2 x = *(const float2*)(Eb + (long)r1*128 + k0);
        float2 y = *(const float2*)(Eb + (long)r1*128 + k0 + 8);
        aT[kt][1] = pkbf(x.x,x.y); aT[kt][3] = pkbf(y.x,y.y);
      }
    }
    const uint4* bp = (const uint4*)g_WT16;
#pragma unroll
    for (int kt=0;kt<8;kt++){
#pragma unroll
      for (int n2=0;n2<8;n2++){
        uint4 bv = bp[(kt*8 + n2)*32 + lane];
        mma16(acc[2*n2],   aT[kt][0],aT[kt][1],aT[kt][2],aT[kt][3], bv.x, bv.y);
        mma16(acc[2*n2+1], aT[kt][0],aT[kt][1],aT[kt][2],aT[kt][3], bv.z, bv.w);
      }
    }
    float p0=0.f, p1=0.f;
#pragma unroll
    for (int nt=0;nt<16;nt++){
      int j0 = nt*8 + 2*tig;
      float w0=w2t[j0], w1=w2t[j0+1], c0=ctv[j0], c1=ctv[j0+1];
      p0 += w0*fmaxf(c0+acc[nt][0],0.f) + w1*fmaxf(c1+acc[nt][1],0.f);
      p1 += w0*fmaxf(c0+acc[nt][2],0.f) + w1*fmaxf(c1+acc[nt][3],0.f);
    }
    p0 += __shfl_xor_sync(0xffffffffu,p0,1); p0 += __shfl_xor_sync(0xffffffffu,p0,2);
    p1 += __shfl_xor_sync(0xffffffffu,p1,1); p1 += __shfl_xor_sync(0xffffffffu,p1,2);
    if (tig==0){
      if (r0 < C_) sco[1][r0] = (p0 + bt2[0]) / Tt;
      if (r1 < C_) sco[1][r1] = (p1 + bt2[0]) / Tt;
    }
  }
  // id pass: K=64, bf16 k16; A prefetched
  {
    float acc[16][4];
#pragma unroll
    for (int nt=0;nt<16;nt++){ acc[nt][0]=0.f;acc[nt][1]=0.f;acc[nt][2]=0.f;acc[nt][3]=0.f; }
    const float* Eb = cide + (long)b*C_*64;
    unsigned aI[4][4];
#pragma unroll
    for (int kt=0;kt<4;kt++){
      const int k0 = kt*16 + tig*2;
      aI[kt][0]=0u; aI[kt][1]=0u; aI[kt][2]=0u; aI[kt][3]=0u;
      if (r0 < C_){
        float2 x = *(const float2*)(Eb + (long)r0*64 + k0);
        float2 y = *(const float2*)(Eb + (long)r0*64 + k0 + 8);
        aI[kt][0] = pkbf(x.x,x.y); aI[kt][2] = pkbf(y.x,y.y);
      }
      if (r1 < C_){
        float2 x = *(const float2*)(Eb + (long)r1*64 + k0);
        float2 y = *(const float2*)(Eb + (long)r1*64 + k0 + 8);
        aI[kt][1] = pkbf(x.x,x.y); aI[kt][3] = pkbf(y.x,y.y);
      }
    }
    const uint4* bp = (const uint4*)g_WI16;
#pragma unroll
    for (int kt=0;kt<4;kt++){
#pragma unroll
      for (int n2=0;n2<8;n2++){
        uint4 bv = bp[(kt*8 + n2)*32 + lane];
        mma16(acc[2*n2],   aI[kt][0],aI[kt][1],aI[kt][2],aI[kt][3], bv.x, bv.y);
        mma16(acc[2*n2+1], aI[kt][0],aI[kt][1],aI[kt][2],aI[kt][3], bv.z, bv.w);
      }
    }
    float p0=0.f, p1=0.f;
#pragma unroll
    for (int nt=0;nt<16;nt++){
      int j0 = nt*8 + 2*tig;
      float w0=w2i[j0], w1=w2i[j0+1], c0=civ[j0], c1=civ[j0+1];
      p0 += w0*fmaxf(c0+acc[nt][0],0.f) + w1*fmaxf(c1+acc[nt][1],0.f);
      p1 += w0*fmaxf(c0+acc[nt][2],0.f) + w1*fmaxf(c1+acc[nt][3],0.f);
    }
    p0 += __shfl_xor_sync(0xffffffffu,p0,1); p0 += __shfl_xor_sync(0xffffffffu,p0,2);
    p1 += __shfl_xor_sync(0xffffffffu,p1,1); p1 += __shfl_xor_sync(0xffffffffu,p1,2);
    if (tig==0){
      if (r0 < C_) sco[2][r0] = (p0 + bi2[0]) / Ti;
      if (r1 < C_) sco[2][r1] = (p1 + bi2[0]) / Ti;
    }
  }
  __syncthreads();

  if (warp == 0){
#pragma unroll
    for (int chn=0;chn<3;chn++){
      float m = -1e30f;
      for (int q=lane;q<C_;q+=32) m = fmaxf(m, sco[chn][q]);
      m = wmax(m);
      float s = 0.f;
      for (int q=lane;q<C_;q+=32) s += __expf(sco[chn][q]-m);
      s = wsum(s);
      if (lane==0){ mx3[chn]=m; inv3[chn]=1.f/s; }
    }
  }
  __syncthreads();
  const float a0=g_AL[b*3], a1=g_AL[b*3+1], a2=g_AL[b*3+2];
  if (tid < C_){
    float p = 0.01f
      + a0*__expf(sco[0][tid]-mx3[0])*inv3[0]
      + a1*__expf(sco[1][tid]-mx3[1])*inv3[1]
      + a2*__expf(sco[2][tid]-mx3[2])*inv3[2];
    mixv[tid] = p;
  }
  __syncthreads();
  if (warp == 0){
    float s = 0.f;
    for (int q=lane;q<C_;q+=32) s += mixv[q];
    s = wsum(s);
    if (lane==0) sS = 1.f/s;
  }
  __syncthreads();
  if (tid < C_) out[(long)b*C_ + tid] = mixv[tid]*sS;
}

extern "C" void kernel_launch(void* const* d_in, const int* in_sizes, int n_in,
                              void* d_out, int out_size) {
  const int*   sitems = (const int*)  d_in[0];
  const float* ide    = (const float*)d_in[1];
  const float* txe    = (const float*)d_in[2];
  const int*   lens   = (const int*)  d_in[3];
  const int*   cids   = (const int*)  d_in[4];
  const float* cide   = (const float*)d_in[5];
  const float* ctxe   = (const float*)d_in[6];
  const float* co     = (const float*)d_in[7];
  const float* Wih    = (const float*)d_in[8];
  const float* Whh    = (const float*)d_in[9];
  const float* bih    = (const float*)d_in[10];
  const float* bhh    = (const float*)d_in[11];
  const float* Wt1    = (const float*)d_in[12];
  const float* bt1    = (const float*)d_in[13];
  const float* Wt2    = (const float*)d_in[14];
  const float* bt2    = (const float*)d_in[15];
  const float* Wi1    = (const float*)d_in[16];
  const float* bi1    = (const float*)d_in[17];
  const float* Wi2    = (const float*)d_in[18];
  const float* bi2    = (const float*)d_in[19];
  const float* Wa1    = (const float*)d_in[20];
  const float* ba1    = (const float*)d_in[21];
  const float* Wa2    = (const float*)d_in[22];
  const float* ba2    = (const float*)d_in[23];
  // d_in[24] = Wstab: unused (P_stable is uniform = 1/C exactly)
  const float* betac  = (const float*)d_in[25];
  const float* lTc    = (const float*)d_in[26];
  const float* lTt    = (const float*)d_in[27];
  const float* lTi    = (const float*)d_in[28];
  float* out = (float*)d_out;

  const int GRU_SMEM = (49152 + 2048 + 384 + 128 + 128 + 64 + 192 + 4) * 4;
  cudaFuncSetAttribute(k_gruall, cudaFuncAttributeMaxDynamicSharedMemorySize, GRU_SMEM);

  const int WPREP_N = 73728+49152+32768+24576+8192+8192+4096;
  k_wprep<<<(WPREP_N+255)/256, 256>>>(Wih, Whh, Wt1, Wi1, Wa1);
  k_ig<<<dim3(80,3), 256>>>(ide, txe, lens, bih);
  k_gruall<<<128, 256, GRU_SMEM>>>(bhh, ide, txe, lens, sitems,
                                   bt1, bi1, ba1, Wa2, ba2);
  k_score<<<B_, 256>>>(ctxe, cide, cids, co, Wt2, bt2, Wi2, bi2,
                       betac, lTc, lTt, lTi, out);
}